// round 8
// baseline (speedup 1.0000x reference)
#include <cuda_runtime.h>
#include <math.h>

// ---------------------------------------------------------------------------
// Wavelet scattering, T=16384, B=16, n1=64, n2=8, P=224, stride 256.
//
// R8: AoS float2 shared array with LDS.64/STS.64 (half the shared-op count),
// padding e + 4*(e>>5) proven conflict-free for all stride classes
// (2048/256/32/4); twiddle powers w1,w2,w4 from shared tables (no serial
// power chain, single apply-cmul per bin); |.| stores (mag,0) in one STS.64.
// Same radix-8 x4 + boundary radix-4 factorization and index maps as R7.
// ---------------------------------------------------------------------------

#define T_N    16384
#define B_N    16
#define N1     64
#define N2     8
#define P_N    224
#define M_OUT  64
#define W_PHI  512
#define NPAD2  18432                   // 16384 + 2048 pad (float2 elements)
#define TWN    (2048 + 256 + 32 + 4)   // 2340 per table
#define SMEM_BYTES ((NPAD2 + 3 * TWN) * 8 + (W_PHI + 4) * 4)

#define S1_BASE 1024
#define S2_BASE 66560

// ----------------------- device scratch ------------------------------------
static __device__ float2 g_xh[B_N * T_N];                     // permuted
static __device__ float2 g_u1h[(size_t)B_N * N1 * T_N];       // permuted
static __device__ float  g_psi1p[N1 * T_N];                   // permuted, /N
static __device__ float  g_psi2p[N2 * T_N];
static __device__ float2 g_tw[T_N];                           // e^{-2pi i k/N}
static __device__ float  g_phit[W_PHI + 1];

// ----------------------- helpers -------------------------------------------
__device__ __forceinline__ int adr2(int e) { return e + ((e >> 5) << 2); }

__device__ __forceinline__ float2 cmul(float2 a, float2 b) {
    return make_float2(fmaf(a.x, b.x, -a.y * b.y),
                       fmaf(a.x, b.y,  a.y * b.x));
}
// a * conj(b)
__device__ __forceinline__ float2 cmulc(float2 a, float2 b) {
    return make_float2(fmaf(a.x, b.x,  a.y * b.y),
                       fmaf(a.y, b.x, -a.x * b.y));
}

__device__ __forceinline__ void r4f(float2& A, float2& B, float2& C, float2& D) {
    float t0x = A.x + C.x, t0y = A.y + C.y, t1x = A.x - C.x, t1y = A.y - C.y;
    float t2x = B.x + D.x, t2y = B.y + D.y, t3x = B.x - D.x, t3y = B.y - D.y;
    A.x = t0x + t2x; A.y = t0y + t2y;  C.x = t0x - t2x; C.y = t0y - t2y;
    B.x = t1x + t3y; B.y = t1y - t3x;  D.x = t1x - t3y; D.y = t1y + t3x;
}
__device__ __forceinline__ void r4i(float2& A, float2& B, float2& C, float2& D) {
    float t0x = A.x + C.x, t0y = A.y + C.y, t1x = A.x - C.x, t1y = A.y - C.y;
    float t2x = B.x + D.x, t2y = B.y + D.y, t3x = B.x - D.x, t3y = B.y - D.y;
    A.x = t0x + t2x; A.y = t0y + t2y;  C.x = t0x - t2x; C.y = t0y - t2y;
    B.x = t1x - t3y; B.y = t1y + t3x;  D.x = t1x + t3y; D.y = t1y - t3x;
}

#define RSQ2 0.7071067811865476f

// Forward radix-8 stage (AoS). Loads a[m] at base+L*m, stores bin r * w^r.
__device__ __forceinline__ void bf8_fwd(float2* __restrict__ s, int base, int L,
                                        float2 w1, float2 w2, float2 w4) {
    float2 a[8];
#pragma unroll
    for (int m = 0; m < 8; m++) a[m] = s[adr2(base + L * m)];
    float2 s0, s1, s2, s3, d0, d1, d2, d3;
    s0 = make_float2(a[0].x + a[4].x, a[0].y + a[4].y);
    s1 = make_float2(a[1].x + a[5].x, a[1].y + a[5].y);
    s2 = make_float2(a[2].x + a[6].x, a[2].y + a[6].y);
    s3 = make_float2(a[3].x + a[7].x, a[3].y + a[7].y);
    d0 = make_float2(a[0].x - a[4].x, a[0].y - a[4].y);
    float2 e1 = make_float2(a[1].x - a[5].x, a[1].y - a[5].y);
    float2 e2 = make_float2(a[2].x - a[6].x, a[2].y - a[6].y);
    float2 e3 = make_float2(a[3].x - a[7].x, a[3].y - a[7].y);
    d1 = make_float2((e1.x + e1.y) * RSQ2, (e1.y - e1.x) * RSQ2);   // *(1-i)/s2
    d2 = make_float2(e2.y, -e2.x);                                  // *(-i)
    d3 = make_float2((e3.y - e3.x) * RSQ2, -(e3.x + e3.y) * RSQ2);  // *(-(1+i)/s2)
    r4f(s0, s1, s2, s3);   // bins 0,2,4,6
    r4f(d0, d1, d2, d3);   // bins 1,3,5,7
    float2 w3 = cmul(w2, w1), w5 = cmul(w4, w1);
    float2 w6 = cmul(w4, w2), w7 = cmul(w4, cmul(w2, w1));
    s[adr2(base)]         = s0;
    s[adr2(base + L)]     = cmul(d0, w1);
    s[adr2(base + 2 * L)] = cmul(s1, w2);
    s[adr2(base + 3 * L)] = cmul(d1, w3);
    s[adr2(base + 4 * L)] = cmul(s2, w4);
    s[adr2(base + 5 * L)] = cmul(d2, w5);
    s[adr2(base + 6 * L)] = cmul(s3, w6);
    s[adr2(base + 7 * L)] = cmul(d3, w7);
}

// Inverse radix-8 stage. ABS: store (|x|, 0).
template<bool ABS>
__device__ __forceinline__ void bf8_inv(float2* __restrict__ s, int base, int L,
                                        float2 w1, float2 w2, float2 w4) {
    float2 y[8];
#pragma unroll
    for (int r = 0; r < 8; r++) y[r] = s[adr2(base + L * r)];
    float2 w3 = cmul(w2, w1), w5 = cmul(w4, w1);
    float2 w6 = cmul(w4, w2), w7 = cmul(w4, cmul(w2, w1));
    y[1] = cmulc(y[1], w1);
    y[2] = cmulc(y[2], w2);
    y[3] = cmulc(y[3], w3);
    y[4] = cmulc(y[4], w4);
    y[5] = cmulc(y[5], w5);
    y[6] = cmulc(y[6], w6);
    y[7] = cmulc(y[7], w7);
    float2 E0 = y[0], E1 = y[2], E2 = y[4], E3 = y[6];
    float2 O0 = y[1], O1 = y[3], O2 = y[5], O3 = y[7];
    r4i(E0, E1, E2, E3);
    r4i(O0, O1, O2, O3);
    float2 u0 = O0;
    float2 u1 = make_float2((O1.x - O1.y) * RSQ2, (O1.x + O1.y) * RSQ2);   // *(1+i)/s2
    float2 u2 = make_float2(-O2.y, O2.x);                                  // *(+i)
    float2 u3 = make_float2(-(O3.x + O3.y) * RSQ2, (O3.x - O3.y) * RSQ2);  // *(-1+i)/s2
    float2 X[8];
    X[0] = make_float2(E0.x + u0.x, E0.y + u0.y);
    X[1] = make_float2(E1.x + u1.x, E1.y + u1.y);
    X[2] = make_float2(E2.x + u2.x, E2.y + u2.y);
    X[3] = make_float2(E3.x + u3.x, E3.y + u3.y);
    X[4] = make_float2(E0.x - u0.x, E0.y - u0.y);
    X[5] = make_float2(E1.x - u1.x, E1.y - u1.y);
    X[6] = make_float2(E2.x - u2.x, E2.y - u2.y);
    X[7] = make_float2(E3.x - u3.x, E3.y - u3.y);
#pragma unroll
    for (int m = 0; m < 8; m++) {
        int A_ = adr2(base + L * m);
        if (ABS) {
            s[A_] = make_float2(sqrtf(fmaf(X[m].x, X[m].x, X[m].y * X[m].y)), 0.f);
        } else {
            s[A_] = X[m];
        }
    }
}

// Final forward radix-4 stage: shared -> gmem (permuted order), no twiddles.
__device__ __forceinline__ void pass4_fwd(const float2* __restrict__ s,
                                          int t, float2* __restrict__ dst) {
#pragma unroll
    for (int h = 0; h < 4; h++) {
        int i0 = 4 * (t + 1024 * h);
        const float4* sp = (const float4*)(s + adr2(i0));   // adr2(i0) % 4 == 0
        float4 v1 = sp[0], v2 = sp[1];
        float2 A = make_float2(v1.x, v1.y), B = make_float2(v1.z, v1.w);
        float2 C = make_float2(v2.x, v2.y), D = make_float2(v2.z, v2.w);
        r4f(A, B, C, D);
        float4* dp = (float4*)(dst + i0);
        dp[0] = make_float4(A.x, A.y, B.x, B.y);
        dp[1] = make_float4(C.x, C.y, D.x, D.y);
    }
}

// Entry inverse radix-4 stage: gmem * psi -> shared, no twiddles.
__device__ __forceinline__ void pass4_inv(float2* __restrict__ s,
                                          int t, const float2* __restrict__ src,
                                          const float* __restrict__ psi) {
#pragma unroll
    for (int h = 0; h < 4; h++) {
        int i0 = 4 * (t + 1024 * h);
        const float4* sp = (const float4*)(src + i0);
        float4 v1 = sp[0], v2 = sp[1];
        float4 p4 = *(const float4*)(psi + i0);
        float2 A = make_float2(v1.x * p4.x, v1.y * p4.x);
        float2 B = make_float2(v1.z * p4.y, v1.w * p4.y);
        float2 C = make_float2(v2.x * p4.z, v2.y * p4.z);
        float2 D = make_float2(v2.z * p4.w, v2.w * p4.w);
        r4i(A, B, C, D);
        float4* dp = (float4*)(s + adr2(i0));
        dp[0] = make_float4(A.x, A.y, B.x, B.y);
        dp[1] = make_float4(C.x, C.y, D.x, D.y);
    }
}

// Twiddle tables: per stage, w1 / w1^2 / w1^4 at offsets {0,2048,2304,2336}.
__device__ __forceinline__ void load_tw(float2* twA, float2* twB, float2* twC, int t) {
    for (int j = t; j < 2048; j += 1024) {
        twA[j] = g_tw[j]; twB[j] = g_tw[2 * j]; twC[j] = g_tw[4 * j];
    }
    if (t < 256) {
        twA[2048 + t] = g_tw[8 * t];  twB[2048 + t] = g_tw[16 * t];  twC[2048 + t] = g_tw[32 * t];
    }
    if (t < 32) {
        twA[2304 + t] = g_tw[64 * t]; twB[2304 + t] = g_tw[128 * t]; twC[2304 + t] = g_tw[256 * t];
    }
    if (t < 4) {
        twA[2336 + t] = g_tw[512 * t]; twB[2336 + t] = g_tw[1024 * t]; twC[2336 + t] = g_tw[2048 * t];
    }
}

// 4 forward radix-8 passes (L = 2048, 256, 32, 4).
__device__ __forceinline__ void fwd4(float2* s, const float2* twA, const float2* twB,
                                     const float2* twC, int t) {
#pragma unroll
    for (int q = 0; q < 2; q++) {
        int i = t + 1024 * q;
        bf8_fwd(s, i, 2048, twA[i], twB[i], twC[i]);
    }
    __syncthreads();
#pragma unroll
    for (int q = 0; q < 2; q++) {
        int i = t + 1024 * q, j = i & 255;
        bf8_fwd(s, ((i >> 8) << 11) + j, 256, twA[2048 + j], twB[2048 + j], twC[2048 + j]);
    }
    __syncthreads();
#pragma unroll
    for (int q = 0; q < 2; q++) {
        int i = t + 1024 * q, j = i & 31;
        bf8_fwd(s, ((i >> 5) << 8) + j, 32, twA[2304 + j], twB[2304 + j], twC[2304 + j]);
    }
    __syncthreads();
#pragma unroll
    for (int q = 0; q < 2; q++) {
        int i = t + 1024 * q, j = i & 3;
        bf8_fwd(s, ((i >> 2) << 5) + j, 4, twA[2336 + j], twB[2336 + j], twC[2336 + j]);
    }
    __syncthreads();
}

// 4 inverse radix-8 passes (L = 4, 32, 256, 2048); last optionally |.|
template<bool ABS>
__device__ __forceinline__ void inv4(float2* s, const float2* twA, const float2* twB,
                                     const float2* twC, int t) {
#pragma unroll
    for (int q = 0; q < 2; q++) {
        int i = t + 1024 * q, j = i & 3;
        bf8_inv<false>(s, ((i >> 2) << 5) + j, 4, twA[2336 + j], twB[2336 + j], twC[2336 + j]);
    }
    __syncthreads();
#pragma unroll
    for (int q = 0; q < 2; q++) {
        int i = t + 1024 * q, j = i & 31;
        bf8_inv<false>(s, ((i >> 5) << 8) + j, 32, twA[2304 + j], twB[2304 + j], twC[2304 + j]);
    }
    __syncthreads();
#pragma unroll
    for (int q = 0; q < 2; q++) {
        int i = t + 1024 * q, j = i & 255;
        bf8_inv<false>(s, ((i >> 8) << 11) + j, 256, twA[2048 + j], twB[2048 + j], twC[2048 + j]);
    }
    __syncthreads();
#pragma unroll
    for (int q = 0; q < 2; q++) {
        int i = t + 1024 * q;
        bf8_inv<ABS>(s, i, 2048, twA[i], twB[i], twC[i]);
    }
    __syncthreads();
}

// Time-domain lowpass + downsample by 256 (reads .x of AoS array).
__device__ __forceinline__ void lowpass64(const float2* __restrict__ s,
                                          const float* __restrict__ ph,
                                          float* __restrict__ outp) {
    const int lane = threadIdx.x & 31;
    const int warp = threadIdx.x >> 5;
    for (int m = warp; m < M_OUT; m += 32) {
        const int t0 = m << 8;
        float acc = 0.f;
        for (int dd = lane; dd <= 2 * W_PHI; dd += 32) {
            const int d   = dd - W_PHI;
            const int ad  = d < 0 ? -d : d;
            const int idx = (t0 - d + T_N) & (T_N - 1);
            acc = fmaf(s[adr2(idx)].x, ph[ad], acc);
        }
#pragma unroll
        for (int off = 16; off; off >>= 1)
            acc += __shfl_down_sync(0xffffffffu, acc, off);
        if (lane == 0) outp[m] = acc;
    }
}

// ----------------------- init kernels ---------------------------------------
// frequency k -> stored position (8,8,8,8 digit reversal, top factor 4 last)
__device__ __forceinline__ int posrm8(int k) {
    return ((k & 7) << 11) | (((k >> 3) & 7) << 8) | (((k >> 6) & 7) << 5)
         | (((k >> 9) & 7) << 2) | (k >> 12);
}

__global__ void k_init(const float* __restrict__ psi1, const float* __restrict__ psi2) {
    const float invN = 1.0f / (float)T_N;
    const int total = N1 * T_N;
    for (int i = blockIdx.x * blockDim.x + threadIdx.x; i < total;
         i += gridDim.x * blockDim.x) {
        const int k = i & (T_N - 1);
        const int j = i >> 14;
        const int pos = posrm8(k);
        g_psi1p[(j << 14) + pos] = psi1[i] * invN;
        if (j < N2) g_psi2p[(j << 14) + pos] = psi2[i] * invN;
        if (j == 0) {
            float sn, cn;
            sincospif(-2.0f * (float)k / (float)T_N, &sn, &cn);
            g_tw[k] = make_float2(cn, sn);
        }
    }
}

__global__ void k_phit(const float* __restrict__ phi) {
    __shared__ float red[256];
    const int n = blockIdx.x;   // 0..W_PHI
    float acc = 0.f;
    for (int k = threadIdx.x; k < T_N; k += blockDim.x)
        acc = fmaf(phi[k], g_tw[(k * n) & (T_N - 1)].x, acc);
    red[threadIdx.x] = acc;
    __syncthreads();
    for (int off = 128; off; off >>= 1) {
        if (threadIdx.x < off) red[threadIdx.x] += red[threadIdx.x + off];
        __syncthreads();
    }
    if (threadIdx.x == 0) g_phit[n] = red[0] * (1.0f / (float)T_N);
}

// ----------------------- main kernels ---------------------------------------
__global__ void __launch_bounds__(1024, 1)
k_xfft(const float* __restrict__ x, float* __restrict__ out) {
    extern __shared__ float2 sm2[];
    float2* s   = sm2;
    float2* twA = sm2 + NPAD2;
    float2* twB = twA + TWN;
    float2* twC = twB + TWN;
    float*  ph  = (float*)(twC + TWN);
    const int b = blockIdx.x, t = threadIdx.x;
    load_tw(twA, twB, twC, t);
    for (int i = t; i <= W_PHI; i += 1024) ph[i] = g_phit[i];
    const float* xb = x + b * T_N;
    for (int i = t; i < T_N; i += 1024) s[adr2(i)] = make_float2(xb[i], 0.f);
    __syncthreads();
    lowpass64(s, ph, out + b * M_OUT);                 // S0
    __syncthreads();
    fwd4(s, twA, twB, twC, t);
    pass4_fwd(s, t, g_xh + b * T_N);
}

__global__ void __launch_bounds__(1024, 1)
k_order1(float* __restrict__ out) {
    extern __shared__ float2 sm2[];
    float2* s   = sm2;
    float2* twA = sm2 + NPAD2;
    float2* twB = twA + TWN;
    float2* twC = twB + TWN;
    float*  ph  = (float*)(twC + TWN);
    const int j1 = blockIdx.x, b = blockIdx.y, t = threadIdx.x;
    load_tw(twA, twB, twC, t);
    for (int i = t; i <= W_PHI; i += 1024) ph[i] = g_phit[i];
    pass4_inv(s, t, g_xh + b * T_N, g_psi1p + j1 * T_N);
    __syncthreads();
    inv4<true>(s, twA, twB, twC, t);                    // |ifft| -> (mag, 0)
    lowpass64(s, ph, out + S1_BASE + (b * N1 + j1) * M_OUT);   // S1
    __syncthreads();
    fwd4(s, twA, twB, twC, t);
    pass4_fwd(s, t, g_u1h + (size_t)(b * N1 + j1) * T_N);
}

__global__ void __launch_bounds__(1024, 1)
k_order2(const int* __restrict__ pj1, const int* __restrict__ pj2,
         float* __restrict__ out) {
    extern __shared__ float2 sm2[];
    float2* s   = sm2;
    float2* twA = sm2 + NPAD2;
    float2* twB = twA + TWN;
    float2* twC = twB + TWN;
    float*  ph  = (float*)(twC + TWN);
    const int idx = blockIdx.x, t = threadIdx.x;
    const int b = idx / P_N;
    const int p = idx - b * P_N;
    const int j1 = pj1[p], j2 = pj2[p];
    load_tw(twA, twB, twC, t);
    for (int i = t; i <= W_PHI; i += 1024) ph[i] = g_phit[i];
    pass4_inv(s, t, g_u1h + (size_t)(b * N1 + j1) * T_N, g_psi2p + j2 * T_N);
    __syncthreads();
    inv4<true>(s, twA, twB, twC, t);
    lowpass64(s, ph, out + S2_BASE + (b * P_N + p) * M_OUT);   // S2
}

// ----------------------- launch --------------------------------------------
extern "C" void kernel_launch(void* const* d_in, const int* in_sizes, int n_in,
                              void* d_out, int out_size) {
    (void)in_sizes; (void)n_in; (void)out_size;
    const float* x    = (const float*)d_in[0];
    const float* psi1 = (const float*)d_in[1];
    const float* psi2 = (const float*)d_in[2];
    const float* phi  = (const float*)d_in[3];
    const int*   pj1  = (const int*)d_in[4];
    const int*   pj2  = (const int*)d_in[5];
    float* out = (float*)d_out;

    cudaFuncSetAttribute(k_xfft,   cudaFuncAttributeMaxDynamicSharedMemorySize, SMEM_BYTES);
    cudaFuncSetAttribute(k_order1, cudaFuncAttributeMaxDynamicSharedMemorySize, SMEM_BYTES);
    cudaFuncSetAttribute(k_order2, cudaFuncAttributeMaxDynamicSharedMemorySize, SMEM_BYTES);

    k_init<<<256, 256>>>(psi1, psi2);
    k_phit<<<W_PHI + 1, 256>>>(phi);
    k_xfft<<<B_N, 1024, SMEM_BYTES>>>(x, out);
    dim3 g1(N1, B_N);
    k_order1<<<g1, 1024, SMEM_BYTES>>>(out);
    k_order2<<<B_N * P_N, 1024, SMEM_BYTES>>>(pj1, pj2, out);
}

// round 10
// speedup vs baseline: 1.0651x; 1.0651x over previous
#include <cuda_runtime.h>
#include <math.h>

// ---------------------------------------------------------------------------
// Wavelet scattering, T=16384, B=16, n1=64, n2=8, P=224, stride 256.
//
// R9: R7 skeleton (radix-8 x4 + boundary radix-4, SoA re/im shared arrays,
// pad e + 4*(e>>5), proven maps) but each thread's TWO butterflies per pass
// are executed in packed f32x2 registers (pair = butterflyA,butterflyB).
// All float math (DFT8 core, twiddle build, cmul applies) runs on
// add/mul/fma.rn.f32x2 -> float instruction count halved. LDS/STS stay
// scalar (conflict-free). Twiddle w1 from SoA shared tables; w2=w1^2,
// w4=w2^2 packed; single cmul apply per bin.
// ---------------------------------------------------------------------------

#define T_N    16384
#define B_N    16
#define N1     64
#define N2     8
#define P_N    224
#define M_OUT  64
#define W_PHI  512
#define NPAD   (T_N + 2048)            // i + ((i>>5)<<2) padding (floats)
#define SMEM_FLOATS (2 * NPAD + 2 * (2048 + 256 + 32 + 4) + W_PHI + 8)
#define SMEM_BYTES  (SMEM_FLOATS * (int)sizeof(float))

#define S1_BASE 1024
#define S2_BASE 66560

// ----------------------- device scratch ------------------------------------
static __device__ float2 g_xh[B_N * T_N];                     // permuted
static __device__ float2 g_u1h[(size_t)B_N * N1 * T_N];       // permuted
static __device__ float  g_psi1p[N1 * T_N];                   // permuted, /N
static __device__ float  g_psi2p[N2 * T_N];
static __device__ float2 g_tw[T_N];                           // e^{-2pi i k/N}
static __device__ float  g_phit[W_PHI + 1];

// ----------------------- f32x2 packed helpers --------------------------------
typedef unsigned long long f2x;

#define C_NEG1 0xBF800000BF800000ULL   // (-1.f, -1.f)
#define C_RS2  0x3F3504F33F3504F3ULL   // ( 0.70710678f,  0.70710678f)
#define C_NRS2 0xBF3504F3BF3504F3ULL   // (-0.70710678f, -0.70710678f)
#define C_TWO  0x4000000040000000ULL   // ( 2.f, 2.f)

__device__ __forceinline__ f2x pk2(float lo, float hi) {
    f2x r; asm("mov.b64 %0, {%1, %2};" : "=l"(r) : "f"(lo), "f"(hi)); return r;
}
__device__ __forceinline__ void upk2(f2x v, float& lo, float& hi) {
    asm("mov.b64 {%0, %1}, %2;" : "=f"(lo), "=f"(hi) : "l"(v));
}
__device__ __forceinline__ f2x fadd2(f2x a, f2x b) {
    f2x r; asm("add.rn.f32x2 %0, %1, %2;" : "=l"(r) : "l"(a), "l"(b)); return r;
}
__device__ __forceinline__ f2x fmul2(f2x a, f2x b) {
    f2x r; asm("mul.rn.f32x2 %0, %1, %2;" : "=l"(r) : "l"(a), "l"(b)); return r;
}
__device__ __forceinline__ f2x ffma2(f2x a, f2x b, f2x c) {
    f2x r; asm("fma.rn.f32x2 %0, %1, %2, %3;" : "=l"(r) : "l"(a), "l"(b), "l"(c)); return r;
}
__device__ __forceinline__ f2x fsub2(f2x a, f2x b) { return ffma2(b, (f2x)C_NEG1, a); }
__device__ __forceinline__ f2x fneg2(f2x a)        { return fmul2(a, (f2x)C_NEG1); }

struct TW { f2x x, y, ny; };

__device__ __forceinline__ TW twsq(TW w) {
    TW r;
    r.x  = ffma2(w.y, w.ny, fmul2(w.x, w.x));
    r.y  = fmul2(fmul2(w.x, w.y), (f2x)C_TWO);
    r.ny = fneg2(r.y);
    return r;
}
__device__ __forceinline__ TW twmul(TW a, TW b) {
    TW r;
    r.x  = ffma2(a.y, b.ny, fmul2(a.x, b.x));
    r.y  = ffma2(a.y, b.x,  fmul2(a.x, b.y));
    r.ny = fneg2(r.y);
    return r;
}
// v *= w
__device__ __forceinline__ void capp(f2x& vr, f2x& vi, TW w) {
    f2x r = ffma2(vi, w.ny, fmul2(vr, w.x));
    vi    = ffma2(vi, w.x,  fmul2(vr, w.y));
    vr = r;
}
// v *= conj(w)
__device__ __forceinline__ void cappc(f2x& vr, f2x& vi, TW w) {
    f2x r = ffma2(vi, w.y, fmul2(vr, w.x));
    vi    = ffma2(vi, w.x, fmul2(vr, w.ny));
    vr = r;
}

#define R4F(Ar,Ai,Br,Bi,Cr,Ci,Dr,Di) do{ \
    f2x t0r=fadd2(Ar,Cr), t0i=fadd2(Ai,Ci), t1r=fsub2(Ar,Cr), t1i=fsub2(Ai,Ci); \
    f2x t2r=fadd2(Br,Dr), t2i=fadd2(Bi,Di), t3r=fsub2(Br,Dr), t3i=fsub2(Bi,Di); \
    Ar=fadd2(t0r,t2r); Ai=fadd2(t0i,t2i); Cr=fsub2(t0r,t2r); Ci=fsub2(t0i,t2i); \
    Br=fadd2(t1r,t3i); Bi=fsub2(t1i,t3r); Dr=fsub2(t1r,t3i); Di=fadd2(t1i,t3r); }while(0)

#define R4I(Ar,Ai,Br,Bi,Cr,Ci,Dr,Di) do{ \
    f2x t0r=fadd2(Ar,Cr), t0i=fadd2(Ai,Ci), t1r=fsub2(Ar,Cr), t1i=fsub2(Ai,Ci); \
    f2x t2r=fadd2(Br,Dr), t2i=fadd2(Bi,Di), t3r=fsub2(Br,Dr), t3i=fsub2(Bi,Di); \
    Ar=fadd2(t0r,t2r); Ai=fadd2(t0i,t2i); Cr=fsub2(t0r,t2r); Ci=fsub2(t0i,t2i); \
    Br=fsub2(t1r,t3i); Bi=fadd2(t1i,t3r); Dr=fadd2(t1r,t3i); Di=fsub2(t1i,t3r); }while(0)

// ----------------------- scalar helpers (boundary passes) --------------------
__device__ __forceinline__ int adr(int i) { return i + ((i >> 5) << 2); }

__device__ __forceinline__ void r4f_s(float2& A, float2& B, float2& C, float2& D) {
    float t0x = A.x + C.x, t0y = A.y + C.y, t1x = A.x - C.x, t1y = A.y - C.y;
    float t2x = B.x + D.x, t2y = B.y + D.y, t3x = B.x - D.x, t3y = B.y - D.y;
    A.x = t0x + t2x; A.y = t0y + t2y;  C.x = t0x - t2x; C.y = t0y - t2y;
    B.x = t1x + t3y; B.y = t1y - t3x;  D.x = t1x - t3y; D.y = t1y + t3x;
}
__device__ __forceinline__ void r4i_s(float2& A, float2& B, float2& C, float2& D) {
    float t0x = A.x + C.x, t0y = A.y + C.y, t1x = A.x - C.x, t1y = A.y - C.y;
    float t2x = B.x + D.x, t2y = B.y + D.y, t3x = B.x - D.x, t3y = B.y - D.y;
    A.x = t0x + t2x; A.y = t0y + t2y;  C.x = t0x - t2x; C.y = t0y - t2y;
    B.x = t1x - t3y; B.y = t1y + t3x;  D.x = t1x + t3y; D.y = t1y - t3x;
}

// ----------------------- packed radix-8 butterfly pair -----------------------
// Processes butterflies at bases bA and bB (element indices) in one shot.
// L: compile-time stride.  INV: inverse direction.  ABS: store (|x|) to re only.
template<int L, bool INV, bool ABS>
__device__ __forceinline__ void bf8p(float* __restrict__ re, float* __restrict__ im,
                                     int bA, int bB, TW w1) {
    const int step = (L >= 32) ? (L + (L >> 3)) : L;   // padded stride
    const int pA = bA + ((bA >> 5) << 2);
    const int pB = bB + ((bB >> 5) << 2);
    f2x xr[8], xi[8];
#pragma unroll
    for (int m = 0; m < 8; m++) {
        int oA = pA + m * step, oB = pB + m * step;
        xr[m] = pk2(re[oA], re[oB]);
        xi[m] = pk2(im[oA], im[oB]);
    }
    if (!INV) {
        // ---- forward DFT8 (matches scalar R7 bf8_fwd) ----
        f2x s0r=fadd2(xr[0],xr[4]), s0i=fadd2(xi[0],xi[4]);
        f2x s1r=fadd2(xr[1],xr[5]), s1i=fadd2(xi[1],xi[5]);
        f2x s2r=fadd2(xr[2],xr[6]), s2i=fadd2(xi[2],xi[6]);
        f2x s3r=fadd2(xr[3],xr[7]), s3i=fadd2(xi[3],xi[7]);
        f2x d0r=fsub2(xr[0],xr[4]), d0i=fsub2(xi[0],xi[4]);
        f2x e1r=fsub2(xr[1],xr[5]), e1i=fsub2(xi[1],xi[5]);
        f2x e2r=fsub2(xr[2],xr[6]), e2i=fsub2(xi[2],xi[6]);
        f2x e3r=fsub2(xr[3],xr[7]), e3i=fsub2(xi[3],xi[7]);
        f2x d1r=fmul2(fadd2(e1r,e1i),(f2x)C_RS2),  d1i=fmul2(fsub2(e1i,e1r),(f2x)C_RS2);
        f2x d2r=e2i,                               d2i=fneg2(e2r);
        f2x d3r=fmul2(fsub2(e3i,e3r),(f2x)C_RS2),  d3i=fmul2(fadd2(e3r,e3i),(f2x)C_NRS2);
        R4F(s0r,s0i,s1r,s1i,s2r,s2i,s3r,s3i);      // bins 0,2,4,6
        R4F(d0r,d0i,d1r,d1i,d2r,d2i,d3r,d3i);      // bins 1,3,5,7
        // ---- twiddle + store (order: s0,d0,s1,d1,s2,d2,s3,d3) ----
        float a,b,c,d;
        upk2(s0r,a,b); upk2(s0i,c,d);
        re[pA]=a; re[pB]=b; im[pA]=c; im[pB]=d;
        TW w2 = twsq(w1), w4 = twsq(w2);
        capp(d0r,d0i,w1); upk2(d0r,a,b); upk2(d0i,c,d);
        re[pA+step]=a; re[pB+step]=b; im[pA+step]=c; im[pB+step]=d;
        capp(s1r,s1i,w2); upk2(s1r,a,b); upk2(s1i,c,d);
        re[pA+2*step]=a; re[pB+2*step]=b; im[pA+2*step]=c; im[pB+2*step]=d;
        TW w3 = twmul(w2,w1);
        capp(d1r,d1i,w3); upk2(d1r,a,b); upk2(d1i,c,d);
        re[pA+3*step]=a; re[pB+3*step]=b; im[pA+3*step]=c; im[pB+3*step]=d;
        capp(s2r,s2i,w4); upk2(s2r,a,b); upk2(s2i,c,d);
        re[pA+4*step]=a; re[pB+4*step]=b; im[pA+4*step]=c; im[pB+4*step]=d;
        TW w5 = twmul(w4,w1);
        capp(d2r,d2i,w5); upk2(d2r,a,b); upk2(d2i,c,d);
        re[pA+5*step]=a; re[pB+5*step]=b; im[pA+5*step]=c; im[pB+5*step]=d;
        TW w6 = twmul(w4,w2);
        capp(s3r,s3i,w6); upk2(s3r,a,b); upk2(s3i,c,d);
        re[pA+6*step]=a; re[pB+6*step]=b; im[pA+6*step]=c; im[pB+6*step]=d;
        TW w7 = twmul(w6,w1);
        capp(d3r,d3i,w7); upk2(d3r,a,b); upk2(d3i,c,d);
        re[pA+7*step]=a; re[pB+7*step]=b; im[pA+7*step]=c; im[pB+7*step]=d;
    } else {
        // ---- un-twiddle by conj(w^r) ----
        TW w2 = twsq(w1), w4 = twsq(w2);
        cappc(xr[1],xi[1],w1);
        cappc(xr[2],xi[2],w2);
        TW w3 = twmul(w2,w1); cappc(xr[3],xi[3],w3);
        cappc(xr[4],xi[4],w4);
        TW w5 = twmul(w4,w1); cappc(xr[5],xi[5],w5);
        TW w6 = twmul(w4,w2); cappc(xr[6],xi[6],w6);
        TW w7 = twmul(w6,w1); cappc(xr[7],xi[7],w7);
        // ---- inverse DFT8 (matches scalar R7 bf8_inv) ----
        R4I(xr[0],xi[0], xr[2],xi[2], xr[4],xi[4], xr[6],xi[6]);  // E0..E3
        R4I(xr[1],xi[1], xr[3],xi[3], xr[5],xi[5], xr[7],xi[7]);  // O0..O3
        f2x u1r=fmul2(fsub2(xr[3],xi[3]),(f2x)C_RS2), u1i=fmul2(fadd2(xr[3],xi[3]),(f2x)C_RS2);
        f2x u2r=fneg2(xi[5]),                         u2i=xr[5];
        f2x u3r=fmul2(fadd2(xr[7],xi[7]),(f2x)C_NRS2),u3i=fmul2(fsub2(xr[7],xi[7]),(f2x)C_RS2);
        f2x Xr[8], Xi[8];
        Xr[0]=fadd2(xr[0],xr[1]); Xi[0]=fadd2(xi[0],xi[1]);
        Xr[4]=fsub2(xr[0],xr[1]); Xi[4]=fsub2(xi[0],xi[1]);
        Xr[1]=fadd2(xr[2],u1r);   Xi[1]=fadd2(xi[2],u1i);
        Xr[5]=fsub2(xr[2],u1r);   Xi[5]=fsub2(xi[2],u1i);
        Xr[2]=fadd2(xr[4],u2r);   Xi[2]=fadd2(xi[4],u2i);
        Xr[6]=fsub2(xr[4],u2r);   Xi[6]=fsub2(xi[4],u2i);
        Xr[3]=fadd2(xr[6],u3r);   Xi[3]=fadd2(xi[6],u3i);
        Xr[7]=fsub2(xr[6],u3r);   Xi[7]=fsub2(xi[6],u3i);
#pragma unroll
        for (int m = 0; m < 8; m++) {
            float a,b,c,d;
            upk2(Xr[m],a,b); upk2(Xi[m],c,d);
            int oA = pA + m * step, oB = pB + m * step;
            if (ABS) {
                re[oA] = sqrtf(fmaf(a, a, c * c));
                re[oB] = sqrtf(fmaf(b, b, d * d));
            } else {
                re[oA]=a; re[oB]=b; im[oA]=c; im[oB]=d;
            }
        }
    }
}

// ----------------------- boundary passes (scalar, gmem) ----------------------
__device__ __forceinline__ void pass4_fwd(const float* __restrict__ re,
                                          const float* __restrict__ im,
                                          int t, float2* __restrict__ dst) {
#pragma unroll
    for (int h = 0; h < 4; h++) {
        int i0 = 4 * (t + 1024 * h);
        int A0 = adr(i0);
        float4 rr = *(const float4*)(re + A0);
        float4 ii = *(const float4*)(im + A0);
        float2 A = make_float2(rr.x, ii.x), B = make_float2(rr.y, ii.y);
        float2 C = make_float2(rr.z, ii.z), D = make_float2(rr.w, ii.w);
        r4f_s(A, B, C, D);
        float4* dp = (float4*)(dst + i0);
        dp[0] = make_float4(A.x, A.y, B.x, B.y);
        dp[1] = make_float4(C.x, C.y, D.x, D.y);
    }
}
__device__ __forceinline__ void pass4_inv(float* __restrict__ re, float* __restrict__ im,
                                          int t, const float2* __restrict__ src,
                                          const float* __restrict__ psi) {
#pragma unroll
    for (int h = 0; h < 4; h++) {
        int i0 = 4 * (t + 1024 * h);
        const float4* sp = (const float4*)(src + i0);
        float4 v1 = sp[0], v2 = sp[1];
        float4 p4 = *(const float4*)(psi + i0);
        float2 A = make_float2(v1.x * p4.x, v1.y * p4.x);
        float2 B = make_float2(v1.z * p4.y, v1.w * p4.y);
        float2 C = make_float2(v2.x * p4.z, v2.y * p4.z);
        float2 D = make_float2(v2.z * p4.w, v2.w * p4.w);
        r4i_s(A, B, C, D);
        int A0 = adr(i0);
        *(float4*)(re + A0) = make_float4(A.x, B.x, C.x, D.x);
        *(float4*)(im + A0) = make_float4(A.y, B.y, C.y, D.y);
    }
}

// ----------------------- twiddle tables + drivers ---------------------------
struct Tabs { float *t1x, *t1y, *t2x, *t2y, *t3x, *t3y, *t4x, *t4y, *ph; };

__device__ __forceinline__ Tabs layout(float* sm) {
    Tabs tb;
    float* p = sm + 2 * NPAD;
    tb.t1x = p;           tb.t1y = p + 2048;
    tb.t2x = p + 4096;    tb.t2y = p + 4352;
    tb.t3x = p + 4608;    tb.t3y = p + 4640;
    tb.t4x = p + 4672;    tb.t4y = p + 4676;
    tb.ph  = p + 4680;
    return tb;
}

__device__ __forceinline__ void load_tabs(Tabs tb, int t) {
    for (int j = t; j < 2048; j += 1024) {
        float2 v = g_tw[j]; tb.t1x[j] = v.x; tb.t1y[j] = v.y;
    }
    if (t < 256) { float2 v = g_tw[8 * t];   tb.t2x[t] = v.x; tb.t2y[t] = v.y; }
    if (t < 32)  { float2 v = g_tw[64 * t];  tb.t3x[t] = v.x; tb.t3y[t] = v.y; }
    if (t < 4)   { float2 v = g_tw[512 * t]; tb.t4x[t] = v.x; tb.t4y[t] = v.y; }
    for (int i = t; i <= W_PHI; i += 1024) tb.ph[i] = g_phit[i];
}

__device__ __forceinline__ TW ldw_pair(const float* tx, const float* ty, int jA, int jB) {
    TW w; w.x = pk2(tx[jA], tx[jB]); w.y = pk2(ty[jA], ty[jB]); w.ny = fneg2(w.y); return w;
}
__device__ __forceinline__ TW ldw_same(const float* tx, const float* ty, int j) {
    float c = tx[j], s = ty[j];
    TW w; w.x = pk2(c, c); w.y = pk2(s, s); w.ny = fneg2(w.y); return w;
}

// 4 forward radix-8 passes (L = 2048, 256, 32, 4); second butterfly = +8192/+1024.
__device__ __forceinline__ void fwd4p(float* re, float* im, Tabs tb, int t) {
    bf8p<2048,false,false>(re, im, t, t + 1024, ldw_pair(tb.t1x, tb.t1y, t, t + 1024));
    __syncthreads();
    { int j = t & 255, bA = ((t >> 8) << 11) + j;
      bf8p<256,false,false>(re, im, bA, bA + 8192, ldw_same(tb.t2x, tb.t2y, j)); }
    __syncthreads();
    { int j = t & 31, bA = ((t >> 5) << 8) + j;
      bf8p<32,false,false>(re, im, bA, bA + 8192, ldw_same(tb.t3x, tb.t3y, j)); }
    __syncthreads();
    { int j = t & 3, bA = ((t >> 2) << 5) + j;
      bf8p<4,false,false>(re, im, bA, bA + 8192, ldw_same(tb.t4x, tb.t4y, j)); }
    __syncthreads();
}

// 4 inverse radix-8 passes (L = 4, 32, 256, 2048); last optionally |.|
template<bool ABS>
__device__ __forceinline__ void inv4p(float* re, float* im, Tabs tb, int t) {
    { int j = t & 3, bA = ((t >> 2) << 5) + j;
      bf8p<4,true,false>(re, im, bA, bA + 8192, ldw_same(tb.t4x, tb.t4y, j)); }
    __syncthreads();
    { int j = t & 31, bA = ((t >> 5) << 8) + j;
      bf8p<32,true,false>(re, im, bA, bA + 8192, ldw_same(tb.t3x, tb.t3y, j)); }
    __syncthreads();
    { int j = t & 255, bA = ((t >> 8) << 11) + j;
      bf8p<256,true,false>(re, im, bA, bA + 8192, ldw_same(tb.t2x, tb.t2y, j)); }
    __syncthreads();
    bf8p<2048,true,ABS>(re, im, t, t + 1024, ldw_pair(tb.t1x, tb.t1y, t, t + 1024));
    __syncthreads();
}

// Time-domain lowpass + downsample by 256 (reads padded re array).
__device__ __forceinline__ void lowpass64(const float* __restrict__ re,
                                          const float* __restrict__ ph,
                                          float* __restrict__ outp) {
    const int lane = threadIdx.x & 31;
    const int warp = threadIdx.x >> 5;
    for (int m = warp; m < M_OUT; m += 32) {
        const int t0 = m << 8;
        float acc = 0.f;
        for (int dd = lane; dd <= 2 * W_PHI; dd += 32) {
            const int d   = dd - W_PHI;
            const int ad  = d < 0 ? -d : d;
            const int idx = (t0 - d + T_N) & (T_N - 1);
            acc = fmaf(re[adr(idx)], ph[ad], acc);
        }
#pragma unroll
        for (int off = 16; off; off >>= 1)
            acc += __shfl_down_sync(0xffffffffu, acc, off);
        if (lane == 0) outp[m] = acc;
    }
}

// ----------------------- init kernels ---------------------------------------
__device__ __forceinline__ int posrm8(int k) {
    return ((k & 7) << 11) | (((k >> 3) & 7) << 8) | (((k >> 6) & 7) << 5)
         | (((k >> 9) & 7) << 2) | (k >> 12);
}

__global__ void k_init(const float* __restrict__ psi1, const float* __restrict__ psi2) {
    const float invN = 1.0f / (float)T_N;
    const int total = N1 * T_N;
    for (int i = blockIdx.x * blockDim.x + threadIdx.x; i < total;
         i += gridDim.x * blockDim.x) {
        const int k = i & (T_N - 1);
        const int j = i >> 14;
        const int pos = posrm8(k);
        g_psi1p[(j << 14) + pos] = psi1[i] * invN;
        if (j < N2) g_psi2p[(j << 14) + pos] = psi2[i] * invN;
        if (j == 0) {
            float sn, cn;
            sincospif(-2.0f * (float)k / (float)T_N, &sn, &cn);
            g_tw[k] = make_float2(cn, sn);
        }
    }
}

__global__ void k_phit(const float* __restrict__ phi) {
    __shared__ float red[256];
    const int n = blockIdx.x;   // 0..W_PHI
    float acc = 0.f;
    for (int k = threadIdx.x; k < T_N; k += blockDim.x)
        acc = fmaf(phi[k], g_tw[(k * n) & (T_N - 1)].x, acc);
    red[threadIdx.x] = acc;
    __syncthreads();
    for (int off = 128; off; off >>= 1) {
        if (threadIdx.x < off) red[threadIdx.x] += red[threadIdx.x + off];
        __syncthreads();
    }
    if (threadIdx.x == 0) g_phit[n] = red[0] * (1.0f / (float)T_N);
}

// ----------------------- main kernels ---------------------------------------
__global__ void __launch_bounds__(1024, 1)
k_xfft(const float* __restrict__ x, float* __restrict__ out) {
    extern __shared__ float sm[];
    float* re = sm; float* im = sm + NPAD;
    Tabs tb = layout(sm);
    const int b = blockIdx.x, t = threadIdx.x;
    load_tabs(tb, t);
    const float* xb = x + b * T_N;
    for (int i = t; i < T_N; i += 1024) { int A_ = adr(i); re[A_] = xb[i]; im[A_] = 0.f; }
    __syncthreads();
    lowpass64(re, tb.ph, out + b * M_OUT);             // S0
    __syncthreads();
    fwd4p(re, im, tb, t);
    pass4_fwd(re, im, t, g_xh + b * T_N);
}

__global__ void __launch_bounds__(1024, 1)
k_order1(float* __restrict__ out) {
    extern __shared__ float sm[];
    float* re = sm; float* im = sm + NPAD;
    Tabs tb = layout(sm);
    const int j1 = blockIdx.x, b = blockIdx.y, t = threadIdx.x;
    load_tabs(tb, t);
    pass4_inv(re, im, t, g_xh + b * T_N, g_psi1p + j1 * T_N);
    __syncthreads();
    inv4p<true>(re, im, tb, t);                         // |ifft| -> re, im stale
    lowpass64(re, tb.ph, out + S1_BASE + (b * N1 + j1) * M_OUT);   // S1
    // rebuild im = 0 for the forward transform of the (real) modulus
    for (int i = t; i < T_N; i += 1024) im[adr(i)] = 0.f;
    __syncthreads();
    fwd4p(re, im, tb, t);
    pass4_fwd(re, im, t, g_u1h + (size_t)(b * N1 + j1) * T_N);
}

__global__ void __launch_bounds__(1024, 1)
k_order2(const int* __restrict__ pj1, const int* __restrict__ pj2,
         float* __restrict__ out) {
    extern __shared__ float sm[];
    float* re = sm; float* im = sm + NPAD;
    Tabs tb = layout(sm);
    const int idx = blockIdx.x, t = threadIdx.x;
    const int b = idx / P_N;
    const int p = idx - b * P_N;
    const int j1 = pj1[p], j2 = pj2[p];
    load_tabs(tb, t);
    pass4_inv(re, im, t, g_u1h + (size_t)(b * N1 + j1) * T_N, g_psi2p + j2 * T_N);
    __syncthreads();
    inv4p<true>(re, im, tb, t);
    lowpass64(re, tb.ph, out + S2_BASE + (b * P_N + p) * M_OUT);   // S2
}

// ----------------------- launch --------------------------------------------
extern "C" void kernel_launch(void* const* d_in, const int* in_sizes, int n_in,
                              void* d_out, int out_size) {
    (void)in_sizes; (void)n_in; (void)out_size;
    const float* x    = (const float*)d_in[0];
    const float* psi1 = (const float*)d_in[1];
    const float* psi2 = (const float*)d_in[2];
    const float* phi  = (const float*)d_in[3];
    const int*   pj1  = (const int*)d_in[4];
    const int*   pj2  = (const int*)d_in[5];
    float* out = (float*)d_out;

    cudaFuncSetAttribute(k_xfft,   cudaFuncAttributeMaxDynamicSharedMemorySize, SMEM_BYTES);
    cudaFuncSetAttribute(k_order1, cudaFuncAttributeMaxDynamicSharedMemorySize, SMEM_BYTES);
    cudaFuncSetAttribute(k_order2, cudaFuncAttributeMaxDynamicSharedMemorySize, SMEM_BYTES);

    k_init<<<256, 256>>>(psi1, psi2);
    k_phit<<<W_PHI + 1, 256>>>(phi);
    k_xfft<<<B_N, 1024, SMEM_BYTES>>>(x, out);
    dim3 g1(N1, B_N);
    k_order1<<<g1, 1024, SMEM_BYTES>>>(out);
    k_order2<<<B_N * P_N, 1024, SMEM_BYTES>>>(pj1, pj2, out);
}

// round 11
// speedup vs baseline: 1.7272x; 1.6216x over previous
#include <cuda_runtime.h>
#include <math.h>

// ---------------------------------------------------------------------------
// Wavelet scattering, T=16384, B=16, n1=64, n2=8, P=224, stride 256.
//
// R11 = R5 (best: radix-16 x3 + boundary radix-4, scalar SoA shared, pad
// i + 4*(i>>6), 1024 thr) with ONE change: the 14-deep serial twiddle power
// chain is replaced by per-stage shared tables of w1,w2,w4,w8 and a
// bit-decomposed application (<=4 independent cmuls per bin, depth<=4).
// ---------------------------------------------------------------------------

#define T_N    16384
#define B_N    16
#define N1     64
#define N2     8
#define P_N    224
#define M_OUT  64
#define W_PHI  512
#define NPAD   (T_N + 1024)           // padded float array length (i + 4*(i>>6))
#define TW_F2  (4 * (1024 + 64 + 4))  // 4368 float2 of twiddle tables
#define SMEM_BYTES ((2 * NPAD) * 4 + TW_F2 * 8 + (W_PHI + 4) * 4)

#define S1_BASE 1024
#define S2_BASE 66560

// ----------------------- device scratch ------------------------------------
static __device__ float2 g_xh[B_N * T_N];                     // permuted
static __device__ float2 g_u1h[(size_t)B_N * N1 * T_N];       // permuted
static __device__ float  g_psi1p[N1 * T_N];                   // permuted, /N
static __device__ float  g_psi2p[N2 * T_N];
static __device__ float2 g_tw[T_N];                           // e^{-2pi i k/N}
static __device__ float  g_phit[W_PHI + 1];

// ----------------------- helpers -------------------------------------------
__device__ __forceinline__ int adr(int i) { return i + ((i >> 6) << 2); }

__device__ __forceinline__ float2 cmul(float2 a, float2 b) {
    return make_float2(fmaf(a.x, b.x, -a.y * b.y),
                       fmaf(a.x, b.y,  a.y * b.x));
}
// a * conj(b)
__device__ __forceinline__ float2 cmulc(float2 a, float2 b) {
    return make_float2(fmaf(a.x, b.x,  a.y * b.y),
                       fmaf(a.y, b.x, -a.x * b.y));
}

__device__ __forceinline__ float2 twf(float2 z, float c, float s) {
    return make_float2(fmaf(z.x, c,  z.y * s), fmaf(z.y, c, -z.x * s));
}
__device__ __forceinline__ float2 twi(float2 z, float c, float s) {
    return make_float2(fmaf(z.x, c, -z.y * s), fmaf(z.y, c,  z.x * s));
}

__device__ __forceinline__ void r4f(float2& A, float2& B, float2& C, float2& D) {
    float t0x = A.x + C.x, t0y = A.y + C.y, t1x = A.x - C.x, t1y = A.y - C.y;
    float t2x = B.x + D.x, t2y = B.y + D.y, t3x = B.x - D.x, t3y = B.y - D.y;
    A.x = t0x + t2x; A.y = t0y + t2y;  C.x = t0x - t2x; C.y = t0y - t2y;
    B.x = t1x + t3y; B.y = t1y - t3x;  D.x = t1x - t3y; D.y = t1y + t3x;
}
__device__ __forceinline__ void r4i(float2& A, float2& B, float2& C, float2& D) {
    float t0x = A.x + C.x, t0y = A.y + C.y, t1x = A.x - C.x, t1y = A.y - C.y;
    float t2x = B.x + D.x, t2y = B.y + D.y, t3x = B.x - D.x, t3y = B.y - D.y;
    A.x = t0x + t2x; A.y = t0y + t2y;  C.x = t0x - t2x; C.y = t0y - t2y;
    B.x = t1x - t3y; B.y = t1y + t3x;  D.x = t1x + t3y; D.y = t1y - t3x;
}

#define C16_1 0.9238795325112867f
#define S16_1 0.3826834323650898f
#define RSQ2  0.7071067811865476f

// 16-point DFT, natural input, base-4-digit-reversed register output.
__device__ __forceinline__ void dft16f(float2 a[16]) {
    r4f(a[0], a[4], a[8], a[12]); r4f(a[1], a[5], a[9], a[13]);
    r4f(a[2], a[6], a[10], a[14]); r4f(a[3], a[7], a[11], a[15]);
    a[5]  = twf(a[5],  C16_1,  S16_1);
    a[9]  = twf(a[9],  RSQ2,   RSQ2);
    a[13] = twf(a[13], S16_1,  C16_1);
    a[6]  = twf(a[6],  RSQ2,   RSQ2);
    a[10] = make_float2(a[10].y, -a[10].x);
    a[14] = twf(a[14], -RSQ2,   RSQ2);
    a[7]  = twf(a[7],  S16_1,  C16_1);
    a[11] = twf(a[11], -RSQ2,   RSQ2);
    a[15] = twf(a[15], -C16_1, -S16_1);
    r4f(a[0], a[1], a[2], a[3]);   r4f(a[4], a[5], a[6], a[7]);
    r4f(a[8], a[9], a[10], a[11]); r4f(a[12], a[13], a[14], a[15]);
}
__device__ __forceinline__ void dft16i(float2 a[16]) {
    r4i(a[0], a[4], a[8], a[12]); r4i(a[1], a[5], a[9], a[13]);
    r4i(a[2], a[6], a[10], a[14]); r4i(a[3], a[7], a[11], a[15]);
    a[5]  = twi(a[5],  C16_1,  S16_1);
    a[9]  = twi(a[9],  RSQ2,   RSQ2);
    a[13] = twi(a[13], S16_1,  C16_1);
    a[6]  = twi(a[6],  RSQ2,   RSQ2);
    a[10] = make_float2(-a[10].y, a[10].x);
    a[14] = twi(a[14], -RSQ2,   RSQ2);
    a[7]  = twi(a[7],  S16_1,  C16_1);
    a[11] = twi(a[11], -RSQ2,   RSQ2);
    a[15] = twi(a[15], -C16_1, -S16_1);
    r4i(a[0], a[1], a[2], a[3]);   r4i(a[4], a[5], a[6], a[7]);
    r4i(a[8], a[9], a[10], a[11]); r4i(a[12], a[13], a[14], a[15]);
}

// Apply w^r by bit decomposition (independent short chains).
__device__ __forceinline__ float2 twpow_f(float2 v, int r, float2 w1, float2 w2,
                                          float2 w4, float2 w8) {
    if (r & 1) v = cmul(v, w1);
    if (r & 2) v = cmul(v, w2);
    if (r & 4) v = cmul(v, w4);
    if (r & 8) v = cmul(v, w8);
    return v;
}
__device__ __forceinline__ float2 twpow_i(float2 v, int r, float2 w1, float2 w2,
                                          float2 w4, float2 w8) {
    if (r & 1) v = cmulc(v, w1);
    if (r & 2) v = cmulc(v, w2);
    if (r & 4) v = cmulc(v, w4);
    if (r & 8) v = cmulc(v, w8);
    return v;
}

// Forward radix-16 stage; REAL variant reads re only.
template<bool REAL>
__device__ __forceinline__ void bf16_fwd(float* __restrict__ re, float* __restrict__ im,
                                         int bp, int stride,
                                         float2 w1, float2 w2, float2 w4, float2 w8) {
    float2 a[16];
#pragma unroll
    for (int m = 0; m < 16; m++) {
        int A_ = adr(bp + stride * m);
        a[m] = make_float2(re[A_], REAL ? 0.f : im[A_]);
    }
    dft16f(a);
    { int A_ = adr(bp); re[A_] = a[0].x; im[A_] = a[0].y; }
#pragma unroll
    for (int r = 1; r < 16; r++) {
        int p = ((r & 3) << 2) | (r >> 2);
        float2 v = twpow_f(a[p], r, w1, w2, w4, w8);
        int A_ = adr(bp + stride * r);
        re[A_] = v.x; im[A_] = v.y;
    }
}

// Inverse radix-16 stage. ABS: store |X| into re only (im left stale).
template<bool ABS>
__device__ __forceinline__ void bf16_inv(float* __restrict__ re, float* __restrict__ im,
                                         int bp, int stride,
                                         float2 w1, float2 w2, float2 w4, float2 w8) {
    float2 a[16];
#pragma unroll
    for (int r = 0; r < 16; r++) {
        int A_ = adr(bp + stride * r);
        a[r] = make_float2(re[A_], im[A_]);
    }
#pragma unroll
    for (int r = 1; r < 16; r++)
        a[r] = twpow_i(a[r], r, w1, w2, w4, w8);
    dft16i(a);
#pragma unroll
    for (int m = 0; m < 16; m++) {
        int p = ((m & 3) << 2) | (m >> 2);
        int A_ = adr(bp + stride * m);
        if (ABS) {
            re[A_] = sqrtf(fmaf(a[p].x, a[p].x, a[p].y * a[p].y));
        } else {
            re[A_] = a[p].x; im[A_] = a[p].y;
        }
    }
}

// Final forward radix-4 stage: shared -> gmem (permuted order), no twiddles.
__device__ __forceinline__ void pass4_fwd(const float* __restrict__ re,
                                          const float* __restrict__ im,
                                          int t, float2* __restrict__ dst) {
#pragma unroll
    for (int h = 0; h < 4; h++) {
        int i0 = 4 * (t + 1024 * h);
        int A0 = adr(i0);
        float4 rr = *(const float4*)(re + A0);
        float4 ii = *(const float4*)(im + A0);
        float2 A = make_float2(rr.x, ii.x), B = make_float2(rr.y, ii.y);
        float2 C = make_float2(rr.z, ii.z), D = make_float2(rr.w, ii.w);
        r4f(A, B, C, D);
        float4* dp = (float4*)(dst + i0);
        dp[0] = make_float4(A.x, A.y, B.x, B.y);
        dp[1] = make_float4(C.x, C.y, D.x, D.y);
    }
}

// Entry inverse radix-4 stage: gmem * psi -> shared, no twiddles.
__device__ __forceinline__ void pass4_inv(float* __restrict__ re, float* __restrict__ im,
                                          int t, const float2* __restrict__ src,
                                          const float* __restrict__ psi) {
#pragma unroll
    for (int h = 0; h < 4; h++) {
        int i0 = 4 * (t + 1024 * h);
        const float4* sp = (const float4*)(src + i0);
        float4 v1 = sp[0], v2 = sp[1];
        float4 p4 = *(const float4*)(psi + i0);
        float2 A = make_float2(v1.x * p4.x, v1.y * p4.x);
        float2 B = make_float2(v1.z * p4.y, v1.w * p4.y);
        float2 C = make_float2(v2.x * p4.z, v2.y * p4.z);
        float2 D = make_float2(v2.z * p4.w, v2.w * p4.w);
        r4i(A, B, C, D);
        int A0 = adr(i0);
        *(float4*)(re + A0) = make_float4(A.x, B.x, C.x, D.x);
        *(float4*)(im + A0) = make_float4(A.y, B.y, C.y, D.y);
    }
}

// ----------------------- twiddle tables --------------------------------------
// Stage 1 (stride 1024, tb = t):        w1=g_tw[t],   w2=g_tw[2t],  w4, w8
// Stage 2 (stride 64,  tb = (t&63)<<4): w1=g_tw[16j], w2=g_tw[32j], ...
// Stage 3 (stride 4,   tb = (t&3)<<8):  w1=g_tw[256j], ...
struct Tabs {
    float2 *s1w1, *s1w2, *s1w4, *s1w8;
    float2 *s2w1, *s2w2, *s2w4, *s2w8;
    float2 *s3w1, *s3w2, *s3w4, *s3w8;
    float  *ph;
};

__device__ __forceinline__ Tabs layout(float* sm) {
    Tabs tb;
    float2* p = (float2*)(sm + 2 * NPAD);
    tb.s1w1 = p;        tb.s1w2 = p + 1024; tb.s1w4 = p + 2048; tb.s1w8 = p + 3072;
    p += 4096;
    tb.s2w1 = p;        tb.s2w2 = p + 64;   tb.s2w4 = p + 128;  tb.s2w8 = p + 192;
    p += 256;
    tb.s3w1 = p;        tb.s3w2 = p + 4;    tb.s3w4 = p + 8;    tb.s3w8 = p + 12;
    p += 16;
    tb.ph = (float*)p;
    return tb;
}

__device__ __forceinline__ void load_tabs(Tabs tb, int t) {
    if (t < 1024) {
        tb.s1w1[t] = g_tw[t];
        tb.s1w2[t] = g_tw[2 * t];
        tb.s1w4[t] = g_tw[4 * t];
        tb.s1w8[t] = g_tw[8 * t];
    }
    if (t < 64) {
        tb.s2w1[t] = g_tw[16 * t];
        tb.s2w2[t] = g_tw[32 * t];
        tb.s2w4[t] = g_tw[64 * t];
        tb.s2w8[t] = g_tw[128 * t];
    }
    if (t < 4) {
        tb.s3w1[t] = g_tw[256 * t];
        tb.s3w2[t] = g_tw[512 * t];
        tb.s3w4[t] = g_tw[1024 * t];
        tb.s3w8[t] = g_tw[2048 * t];
    }
    for (int i = t; i <= W_PHI; i += 1024) tb.ph[i] = g_phit[i];
}

// 3 inner forward passes (strides 1024, 64, 4). REAL_IN: first pass reads re only.
template<bool REAL_IN>
__device__ __forceinline__ void fwd3(float* re, float* im, Tabs tb, int t) {
    bf16_fwd<REAL_IN>(re, im, t, 1024,
                      tb.s1w1[t], tb.s1w2[t], tb.s1w4[t], tb.s1w8[t]);
    __syncthreads();
    { int j = t & 63;
      bf16_fwd<false>(re, im, ((t >> 6) << 10) + j, 64,
                      tb.s2w1[j], tb.s2w2[j], tb.s2w4[j], tb.s2w8[j]); }
    __syncthreads();
    { int j = t & 3;
      bf16_fwd<false>(re, im, ((t >> 2) << 6) + j, 4,
                      tb.s3w1[j], tb.s3w2[j], tb.s3w4[j], tb.s3w8[j]); }
    __syncthreads();
}

// 3 inner inverse passes (strides 4, 64, 1024); last optionally takes |.|
template<bool ABS>
__device__ __forceinline__ void inv3(float* re, float* im, Tabs tb, int t) {
    { int j = t & 3;
      bf16_inv<false>(re, im, ((t >> 2) << 6) + j, 4,
                      tb.s3w1[j], tb.s3w2[j], tb.s3w4[j], tb.s3w8[j]); }
    __syncthreads();
    { int j = t & 63;
      bf16_inv<false>(re, im, ((t >> 6) << 10) + j, 64,
                      tb.s2w1[j], tb.s2w2[j], tb.s2w4[j], tb.s2w8[j]); }
    __syncthreads();
    bf16_inv<ABS>(re, im, t, 1024,
                  tb.s1w1[t], tb.s1w2[t], tb.s1w4[t], tb.s1w8[t]);
    __syncthreads();
}

// Time-domain lowpass + downsample by 256 (reads padded re array).
__device__ __forceinline__ void lowpass64(const float* __restrict__ re,
                                          const float* __restrict__ ph,
                                          float* __restrict__ outp) {
    const int lane = threadIdx.x & 31;
    const int warp = threadIdx.x >> 5;
    for (int m = warp; m < M_OUT; m += 32) {
        const int t0 = m << 8;
        float acc = 0.f;
        for (int dd = lane; dd <= 2 * W_PHI; dd += 32) {
            const int d   = dd - W_PHI;
            const int ad  = d < 0 ? -d : d;
            const int idx = (t0 - d + T_N) & (T_N - 1);
            acc = fmaf(re[adr(idx)], ph[ad], acc);
        }
#pragma unroll
        for (int off = 16; off; off >>= 1)
            acc += __shfl_down_sync(0xffffffffu, acc, off);
        if (lane == 0) outp[m] = acc;
    }
}

// ----------------------- init kernels ---------------------------------------
__device__ __forceinline__ int posrm(int k) {
    return ((k & 15) << 10) | (((k >> 4) & 15) << 6) | (((k >> 8) & 15) << 2) | (k >> 12);
}

__global__ void k_init(const float* __restrict__ psi1, const float* __restrict__ psi2) {
    const float invN = 1.0f / (float)T_N;
    const int total = N1 * T_N;
    for (int i = blockIdx.x * blockDim.x + threadIdx.x; i < total;
         i += gridDim.x * blockDim.x) {
        const int k = i & (T_N - 1);
        const int j = i >> 14;
        const int pos = posrm(k);
        g_psi1p[(j << 14) + pos] = psi1[i] * invN;
        if (j < N2) g_psi2p[(j << 14) + pos] = psi2[i] * invN;
        if (j == 0) {
            float sn, cn;
            sincospif(-2.0f * (float)k / (float)T_N, &sn, &cn);
            g_tw[k] = make_float2(cn, sn);
        }
    }
}

__global__ void k_phit(const float* __restrict__ phi) {
    __shared__ float red[256];
    const int n = blockIdx.x;   // 0..W_PHI
    float acc = 0.f;
    for (int k = threadIdx.x; k < T_N; k += blockDim.x)
        acc = fmaf(phi[k], g_tw[(k * n) & (T_N - 1)].x, acc);
    red[threadIdx.x] = acc;
    __syncthreads();
    for (int off = 128; off; off >>= 1) {
        if (threadIdx.x < off) red[threadIdx.x] += red[threadIdx.x + off];
        __syncthreads();
    }
    if (threadIdx.x == 0) g_phit[n] = red[0] * (1.0f / (float)T_N);
}

// ----------------------- main kernels ---------------------------------------
__global__ void __launch_bounds__(1024, 1)
k_xfft(const float* __restrict__ x, float* __restrict__ out) {
    extern __shared__ float sm[];
    float* re = sm; float* im = sm + NPAD;
    Tabs tb = layout(sm);
    const int b = blockIdx.x, t = threadIdx.x;
    load_tabs(tb, t);
    const float* xb = x + b * T_N;
    for (int i = t; i < T_N; i += 1024) re[adr(i)] = xb[i];
    __syncthreads();
    lowpass64(re, tb.ph, out + b * M_OUT);              // S0
    __syncthreads();
    fwd3<true>(re, im, tb, t);
    pass4_fwd(re, im, t, g_xh + b * T_N);
}

__global__ void __launch_bounds__(1024, 1)
k_order1(float* __restrict__ out) {
    extern __shared__ float sm[];
    float* re = sm; float* im = sm + NPAD;
    Tabs tb = layout(sm);
    const int j1 = blockIdx.x, b = blockIdx.y, t = threadIdx.x;
    load_tabs(tb, t);
    pass4_inv(re, im, t, g_xh + b * T_N, g_psi1p + j1 * T_N);
    __syncthreads();
    inv3<true>(re, im, tb, t);                          // |ifft| -> re
    lowpass64(re, tb.ph, out + S1_BASE + (b * N1 + j1) * M_OUT);   // S1
    __syncthreads();
    fwd3<true>(re, im, tb, t);
    pass4_fwd(re, im, t, g_u1h + (size_t)(b * N1 + j1) * T_N);
}

__global__ void __launch_bounds__(1024, 1)
k_order2(const int* __restrict__ pj1, const int* __restrict__ pj2,
         float* __restrict__ out) {
    extern __shared__ float sm[];
    float* re = sm; float* im = sm + NPAD;
    Tabs tb = layout(sm);
    const int idx = blockIdx.x, t = threadIdx.x;
    const int b = idx / P_N;
    const int p = idx - b * P_N;
    const int j1 = pj1[p], j2 = pj2[p];
    load_tabs(tb, t);
    pass4_inv(re, im, t, g_u1h + (size_t)(b * N1 + j1) * T_N, g_psi2p + j2 * T_N);
    __syncthreads();
    inv3<true>(re, im, tb, t);
    lowpass64(re, tb.ph, out + S2_BASE + (b * P_N + p) * M_OUT);   // S2
}

// ----------------------- launch --------------------------------------------
extern "C" void kernel_launch(void* const* d_in, const int* in_sizes, int n_in,
                              void* d_out, int out_size) {
    (void)in_sizes; (void)n_in; (void)out_size;
    const float* x    = (const float*)d_in[0];
    const float* psi1 = (const float*)d_in[1];
    const float* psi2 = (const float*)d_in[2];
    const float* phi  = (const float*)d_in[3];
    const int*   pj1  = (const int*)d_in[4];
    const int*   pj2  = (const int*)d_in[5];
    float* out = (float*)d_out;

    cudaFuncSetAttribute(k_xfft,   cudaFuncAttributeMaxDynamicSharedMemorySize, SMEM_BYTES);
    cudaFuncSetAttribute(k_order1, cudaFuncAttributeMaxDynamicSharedMemorySize, SMEM_BYTES);
    cudaFuncSetAttribute(k_order2, cudaFuncAttributeMaxDynamicSharedMemorySize, SMEM_BYTES);

    k_init<<<256, 256>>>(psi1, psi2);
    k_phit<<<W_PHI + 1, 256>>>(phi);
    k_xfft<<<B_N, 1024, SMEM_BYTES>>>(x, out);
    dim3 g1(N1, B_N);
    k_order1<<<g1, 1024, SMEM_BYTES>>>(out);
    k_order2<<<B_N * P_N, 1024, SMEM_BYTES>>>(pj1, pj2, out);
}

// round 13
// speedup vs baseline: 1.8014x; 1.0429x over previous
#include <cuda_runtime.h>
#include <math.h>

// ---------------------------------------------------------------------------
// Wavelet scattering, T=16384, B=16, n1=64, n2=8, P=224, stride 256.
//
// R13 = R12 with 4x more decimation margin (calibrated on R12's measured
// aliasing error ~ (sigma/M)^2): subband order-2 only for j2 >= 4 with
// M = 2^(17-j2), decimation s' = 2^(j2-3); j2 in {1,2,3} use the full-size
// radix-16 path. All other code identical to the 619us-class front-end.
// ---------------------------------------------------------------------------

#define T_N    16384
#define B_N    16
#define N1     64
#define N2     8
#define P_N    224
#define M_OUT  64
#define W_PHI  512
#define NPAD   (T_N + 1024)           // padded float array length (i + 4*(i>>6))
#define TW_F2  (4 * (1024 + 64 + 4))  // 4368 float2 of twiddle tables
#define SMEM_BYTES ((2 * NPAD) * 4 + TW_F2 * 8 + (W_PHI + 4) * 4)
#define SMEM_BAND  84000

#define S1_BASE 1024
#define S2_BASE 66560

// ----------------------- device scratch ------------------------------------
static __device__ float2 g_xh[B_N * T_N];                     // permuted
static __device__ float2 g_u1h[(size_t)B_N * N1 * T_N];       // permuted
static __device__ float  g_psi1p[N1 * T_N];                   // permuted, /N
static __device__ float  g_psi2p[N2 * T_N];                   // permuted, /N
static __device__ float  g_psi2n[N2 * 8192];                  // natural, /N (k<8192)
static __device__ float2 g_tw[T_N];                           // e^{-2pi i k/N}
static __device__ float  g_phit[W_PHI + 1];

// ----------------------- helpers -------------------------------------------
__device__ __forceinline__ int adr(int i)  { return i + ((i >> 6) << 2); }
__device__ __forceinline__ int padb(int i) { return i + ((i >> 5) << 2); }

__device__ __forceinline__ float2 cmul(float2 a, float2 b) {
    return make_float2(fmaf(a.x, b.x, -a.y * b.y),
                       fmaf(a.x, b.y,  a.y * b.x));
}
// a * conj(b)
__device__ __forceinline__ float2 cmulc(float2 a, float2 b) {
    return make_float2(fmaf(a.x, b.x,  a.y * b.y),
                       fmaf(a.y, b.x, -a.x * b.y));
}

__device__ __forceinline__ float2 twf(float2 z, float c, float s) {
    return make_float2(fmaf(z.x, c,  z.y * s), fmaf(z.y, c, -z.x * s));
}
__device__ __forceinline__ float2 twi(float2 z, float c, float s) {
    return make_float2(fmaf(z.x, c, -z.y * s), fmaf(z.y, c,  z.x * s));
}

__device__ __forceinline__ void r4f(float2& A, float2& B, float2& C, float2& D) {
    float t0x = A.x + C.x, t0y = A.y + C.y, t1x = A.x - C.x, t1y = A.y - C.y;
    float t2x = B.x + D.x, t2y = B.y + D.y, t3x = B.x - D.x, t3y = B.y - D.y;
    A.x = t0x + t2x; A.y = t0y + t2y;  C.x = t0x - t2x; C.y = t0y - t2y;
    B.x = t1x + t3y; B.y = t1y - t3x;  D.x = t1x - t3y; D.y = t1y + t3x;
}
__device__ __forceinline__ void r4i(float2& A, float2& B, float2& C, float2& D) {
    float t0x = A.x + C.x, t0y = A.y + C.y, t1x = A.x - C.x, t1y = A.y - C.y;
    float t2x = B.x + D.x, t2y = B.y + D.y, t3x = B.x - D.x, t3y = B.y - D.y;
    A.x = t0x + t2x; A.y = t0y + t2y;  C.x = t0x - t2x; C.y = t0y - t2y;
    B.x = t1x - t3y; B.y = t1y + t3x;  D.x = t1x + t3y; D.y = t1y - t3x;
}

#define C16_1 0.9238795325112867f
#define S16_1 0.3826834323650898f
#define RSQ2  0.7071067811865476f

__device__ __forceinline__ void dft16f(float2 a[16]) {
    r4f(a[0], a[4], a[8], a[12]); r4f(a[1], a[5], a[9], a[13]);
    r4f(a[2], a[6], a[10], a[14]); r4f(a[3], a[7], a[11], a[15]);
    a[5]  = twf(a[5],  C16_1,  S16_1);
    a[9]  = twf(a[9],  RSQ2,   RSQ2);
    a[13] = twf(a[13], S16_1,  C16_1);
    a[6]  = twf(a[6],  RSQ2,   RSQ2);
    a[10] = make_float2(a[10].y, -a[10].x);
    a[14] = twf(a[14], -RSQ2,   RSQ2);
    a[7]  = twf(a[7],  S16_1,  C16_1);
    a[11] = twf(a[11], -RSQ2,   RSQ2);
    a[15] = twf(a[15], -C16_1, -S16_1);
    r4f(a[0], a[1], a[2], a[3]);   r4f(a[4], a[5], a[6], a[7]);
    r4f(a[8], a[9], a[10], a[11]); r4f(a[12], a[13], a[14], a[15]);
}
__device__ __forceinline__ void dft16i(float2 a[16]) {
    r4i(a[0], a[4], a[8], a[12]); r4i(a[1], a[5], a[9], a[13]);
    r4i(a[2], a[6], a[10], a[14]); r4i(a[3], a[7], a[11], a[15]);
    a[5]  = twi(a[5],  C16_1,  S16_1);
    a[9]  = twi(a[9],  RSQ2,   RSQ2);
    a[13] = twi(a[13], S16_1,  C16_1);
    a[6]  = twi(a[6],  RSQ2,   RSQ2);
    a[10] = make_float2(-a[10].y, a[10].x);
    a[14] = twi(a[14], -RSQ2,   RSQ2);
    a[7]  = twi(a[7],  S16_1,  C16_1);
    a[11] = twi(a[11], -RSQ2,   RSQ2);
    a[15] = twi(a[15], -C16_1, -S16_1);
    r4i(a[0], a[1], a[2], a[3]);   r4i(a[4], a[5], a[6], a[7]);
    r4i(a[8], a[9], a[10], a[11]); r4i(a[12], a[13], a[14], a[15]);
}

__device__ __forceinline__ float2 twpow_f(float2 v, int r, float2 w1, float2 w2,
                                          float2 w4, float2 w8) {
    if (r & 1) v = cmul(v, w1);
    if (r & 2) v = cmul(v, w2);
    if (r & 4) v = cmul(v, w4);
    if (r & 8) v = cmul(v, w8);
    return v;
}
__device__ __forceinline__ float2 twpow_i(float2 v, int r, float2 w1, float2 w2,
                                          float2 w4, float2 w8) {
    if (r & 1) v = cmulc(v, w1);
    if (r & 2) v = cmulc(v, w2);
    if (r & 4) v = cmulc(v, w4);
    if (r & 8) v = cmulc(v, w8);
    return v;
}

template<bool REAL>
__device__ __forceinline__ void bf16_fwd(float* __restrict__ re, float* __restrict__ im,
                                         int bp, int stride,
                                         float2 w1, float2 w2, float2 w4, float2 w8) {
    float2 a[16];
#pragma unroll
    for (int m = 0; m < 16; m++) {
        int A_ = adr(bp + stride * m);
        a[m] = make_float2(re[A_], REAL ? 0.f : im[A_]);
    }
    dft16f(a);
    { int A_ = adr(bp); re[A_] = a[0].x; im[A_] = a[0].y; }
#pragma unroll
    for (int r = 1; r < 16; r++) {
        int p = ((r & 3) << 2) | (r >> 2);
        float2 v = twpow_f(a[p], r, w1, w2, w4, w8);
        int A_ = adr(bp + stride * r);
        re[A_] = v.x; im[A_] = v.y;
    }
}

template<bool ABS>
__device__ __forceinline__ void bf16_inv(float* __restrict__ re, float* __restrict__ im,
                                         int bp, int stride,
                                         float2 w1, float2 w2, float2 w4, float2 w8) {
    float2 a[16];
#pragma unroll
    for (int r = 0; r < 16; r++) {
        int A_ = adr(bp + stride * r);
        a[r] = make_float2(re[A_], im[A_]);
    }
#pragma unroll
    for (int r = 1; r < 16; r++)
        a[r] = twpow_i(a[r], r, w1, w2, w4, w8);
    dft16i(a);
#pragma unroll
    for (int m = 0; m < 16; m++) {
        int p = ((m & 3) << 2) | (m >> 2);
        int A_ = adr(bp + stride * m);
        if (ABS) {
            re[A_] = sqrtf(fmaf(a[p].x, a[p].x, a[p].y * a[p].y));
        } else {
            re[A_] = a[p].x; im[A_] = a[p].y;
        }
    }
}

__device__ __forceinline__ void pass4_fwd(const float* __restrict__ re,
                                          const float* __restrict__ im,
                                          int t, float2* __restrict__ dst) {
#pragma unroll
    for (int h = 0; h < 4; h++) {
        int i0 = 4 * (t + 1024 * h);
        int A0 = adr(i0);
        float4 rr = *(const float4*)(re + A0);
        float4 ii = *(const float4*)(im + A0);
        float2 A = make_float2(rr.x, ii.x), B = make_float2(rr.y, ii.y);
        float2 C = make_float2(rr.z, ii.z), D = make_float2(rr.w, ii.w);
        r4f(A, B, C, D);
        float4* dp = (float4*)(dst + i0);
        dp[0] = make_float4(A.x, A.y, B.x, B.y);
        dp[1] = make_float4(C.x, C.y, D.x, D.y);
    }
}

__device__ __forceinline__ void pass4_inv(float* __restrict__ re, float* __restrict__ im,
                                          int t, const float2* __restrict__ src,
                                          const float* __restrict__ psi) {
#pragma unroll
    for (int h = 0; h < 4; h++) {
        int i0 = 4 * (t + 1024 * h);
        const float4* sp = (const float4*)(src + i0);
        float4 v1 = sp[0], v2 = sp[1];
        float4 p4 = *(const float4*)(psi + i0);
        float2 A = make_float2(v1.x * p4.x, v1.y * p4.x);
        float2 B = make_float2(v1.z * p4.y, v1.w * p4.y);
        float2 C = make_float2(v2.x * p4.z, v2.y * p4.z);
        float2 D = make_float2(v2.z * p4.w, v2.w * p4.w);
        r4i(A, B, C, D);
        int A0 = adr(i0);
        *(float4*)(re + A0) = make_float4(A.x, B.x, C.x, D.x);
        *(float4*)(im + A0) = make_float4(A.y, B.y, C.y, D.y);
    }
}

struct Tabs {
    float2 *s1w1, *s1w2, *s1w4, *s1w8;
    float2 *s2w1, *s2w2, *s2w4, *s2w8;
    float2 *s3w1, *s3w2, *s3w4, *s3w8;
    float  *ph;
};

__device__ __forceinline__ Tabs layout(float* sm) {
    Tabs tb;
    float2* p = (float2*)(sm + 2 * NPAD);
    tb.s1w1 = p;        tb.s1w2 = p + 1024; tb.s1w4 = p + 2048; tb.s1w8 = p + 3072;
    p += 4096;
    tb.s2w1 = p;        tb.s2w2 = p + 64;   tb.s2w4 = p + 128;  tb.s2w8 = p + 192;
    p += 256;
    tb.s3w1 = p;        tb.s3w2 = p + 4;    tb.s3w4 = p + 8;    tb.s3w8 = p + 12;
    p += 16;
    tb.ph = (float*)p;
    return tb;
}

__device__ __forceinline__ void load_tabs(Tabs tb, int t) {
    if (t < 1024) {
        tb.s1w1[t] = g_tw[t];
        tb.s1w2[t] = g_tw[2 * t];
        tb.s1w4[t] = g_tw[4 * t];
        tb.s1w8[t] = g_tw[8 * t];
    }
    if (t < 64) {
        tb.s2w1[t] = g_tw[16 * t];
        tb.s2w2[t] = g_tw[32 * t];
        tb.s2w4[t] = g_tw[64 * t];
        tb.s2w8[t] = g_tw[128 * t];
    }
    if (t < 4) {
        tb.s3w1[t] = g_tw[256 * t];
        tb.s3w2[t] = g_tw[512 * t];
        tb.s3w4[t] = g_tw[1024 * t];
        tb.s3w8[t] = g_tw[2048 * t];
    }
    for (int i = t; i <= W_PHI; i += 1024) tb.ph[i] = g_phit[i];
}

template<bool REAL_IN>
__device__ __forceinline__ void fwd3(float* re, float* im, Tabs tb, int t) {
    bf16_fwd<REAL_IN>(re, im, t, 1024,
                      tb.s1w1[t], tb.s1w2[t], tb.s1w4[t], tb.s1w8[t]);
    __syncthreads();
    { int j = t & 63;
      bf16_fwd<false>(re, im, ((t >> 6) << 10) + j, 64,
                      tb.s2w1[j], tb.s2w2[j], tb.s2w4[j], tb.s2w8[j]); }
    __syncthreads();
    { int j = t & 3;
      bf16_fwd<false>(re, im, ((t >> 2) << 6) + j, 4,
                      tb.s3w1[j], tb.s3w2[j], tb.s3w4[j], tb.s3w8[j]); }
    __syncthreads();
}

template<bool ABS>
__device__ __forceinline__ void inv3(float* re, float* im, Tabs tb, int t) {
    { int j = t & 3;
      bf16_inv<false>(re, im, ((t >> 2) << 6) + j, 4,
                      tb.s3w1[j], tb.s3w2[j], tb.s3w4[j], tb.s3w8[j]); }
    __syncthreads();
    { int j = t & 63;
      bf16_inv<false>(re, im, ((t >> 6) << 10) + j, 64,
                      tb.s2w1[j], tb.s2w2[j], tb.s2w4[j], tb.s2w8[j]); }
    __syncthreads();
    bf16_inv<ABS>(re, im, t, 1024,
                  tb.s1w1[t], tb.s1w2[t], tb.s1w4[t], tb.s1w8[t]);
    __syncthreads();
}

__device__ __forceinline__ void lowpass64(const float* __restrict__ re,
                                          const float* __restrict__ ph,
                                          float* __restrict__ outp) {
    const int lane = threadIdx.x & 31;
    const int warp = threadIdx.x >> 5;
    for (int m = warp; m < M_OUT; m += 32) {
        const int t0 = m << 8;
        float acc = 0.f;
        for (int dd = lane; dd <= 2 * W_PHI; dd += 32) {
            const int d   = dd - W_PHI;
            const int ad  = d < 0 ? -d : d;
            const int idx = (t0 - d + T_N) & (T_N - 1);
            acc = fmaf(re[adr(idx)], ph[ad], acc);
        }
#pragma unroll
        for (int off = 16; off; off >>= 1)
            acc += __shfl_down_sync(0xffffffffu, acc, off);
        if (lane == 0) outp[m] = acc;
    }
}

// ----------------------- init kernels ---------------------------------------
// natural bin k -> gmem position (matches fwd3+pass4_fwd output layout)
__device__ __forceinline__ int posrm(int k) {
    return ((k & 15) << 10) | (((k >> 4) & 15) << 6) | (((k >> 8) & 15) << 2) | (k >> 12);
}

__global__ void k_init(const float* __restrict__ psi1, const float* __restrict__ psi2) {
    const float invN = 1.0f / (float)T_N;
    const int total = N1 * T_N;
    for (int i = blockIdx.x * blockDim.x + threadIdx.x; i < total;
         i += gridDim.x * blockDim.x) {
        const int k = i & (T_N - 1);
        const int j = i >> 14;
        const int pos = posrm(k);
        g_psi1p[(j << 14) + pos] = psi1[i] * invN;
        if (j < N2) {
            g_psi2p[(j << 14) + pos] = psi2[i] * invN;
            if (k < 8192) g_psi2n[(j << 13) + k] = psi2[i] * invN;
        }
        if (j == 0) {
            float sn, cn;
            sincospif(-2.0f * (float)k / (float)T_N, &sn, &cn);
            g_tw[k] = make_float2(cn, sn);
        }
    }
}

__global__ void k_phit(const float* __restrict__ phi) {
    __shared__ float red[256];
    const int n = blockIdx.x;   // 0..W_PHI
    float acc = 0.f;
    for (int k = threadIdx.x; k < T_N; k += blockDim.x)
        acc = fmaf(phi[k], g_tw[(k * n) & (T_N - 1)].x, acc);
    red[threadIdx.x] = acc;
    __syncthreads();
    for (int off = 128; off; off >>= 1) {
        if (threadIdx.x < off) red[threadIdx.x] += red[threadIdx.x + off];
        __syncthreads();
    }
    if (threadIdx.x == 0) g_phit[n] = red[0] * (1.0f / (float)T_N);
}

// ----------------------- main kernels ---------------------------------------
__global__ void __launch_bounds__(1024, 1)
k_xfft(const float* __restrict__ x, float* __restrict__ out) {
    extern __shared__ float sm[];
    float* re = sm; float* im = sm + NPAD;
    Tabs tb = layout(sm);
    const int b = blockIdx.x, t = threadIdx.x;
    load_tabs(tb, t);
    const float* xb = x + b * T_N;
    for (int i = t; i < T_N; i += 1024) re[adr(i)] = xb[i];
    __syncthreads();
    lowpass64(re, tb.ph, out + b * M_OUT);              // S0
    __syncthreads();
    fwd3<true>(re, im, tb, t);
    pass4_fwd(re, im, t, g_xh + b * T_N);
}

__global__ void __launch_bounds__(1024, 1)
k_order1(float* __restrict__ out) {
    extern __shared__ float sm[];
    float* re = sm; float* im = sm + NPAD;
    Tabs tb = layout(sm);
    const int j1 = blockIdx.x, b = blockIdx.y, t = threadIdx.x;
    load_tabs(tb, t);
    pass4_inv(re, im, t, g_xh + b * T_N, g_psi1p + j1 * T_N);
    __syncthreads();
    inv3<true>(re, im, tb, t);                          // |ifft| -> re
    lowpass64(re, tb.ph, out + S1_BASE + (b * N1 + j1) * M_OUT);   // S1
    __syncthreads();
    fwd3<true>(re, im, tb, t);
    pass4_fwd(re, im, t, g_u1h + (size_t)(b * N1 + j1) * T_N);
}

// Full-size order-2 path: pairs with j2 <= 3.
__global__ void __launch_bounds__(1024, 1)
k_order2(const int* __restrict__ pj1, const int* __restrict__ pj2,
         float* __restrict__ out) {
    const int idx = blockIdx.x;
    const int b = idx / P_N;
    const int p = idx - b * P_N;
    const int j2 = pj2[p];
    if (j2 >= 4) return;
    extern __shared__ float sm[];
    float* re = sm; float* im = sm + NPAD;
    Tabs tb = layout(sm);
    const int t = threadIdx.x;
    const int j1 = pj1[p];
    load_tabs(tb, t);
    pass4_inv(re, im, t, g_u1h + (size_t)(b * N1 + j1) * T_N, g_psi2p + j2 * T_N);
    __syncthreads();
    inv3<true>(re, im, tb, t);
    lowpass64(re, tb.ph, out + S2_BASE + (b * P_N + p) * M_OUT);   // S2
}

// Subband order-2 path: pairs with j2 >= 4.  M = 2^(17-j2), s' = 2^(j2-3).
// Y[k] = U1h[k]*psi2[k] (k < M, natural order) -> unnormalized inverse DIF FFT
// (natural in -> bit-reversed out) -> |.| -> decimated phi-conv (x s').
__global__ void __launch_bounds__(512, 2)
k_order2_band(const int* __restrict__ pj1, const int* __restrict__ pj2,
              float* __restrict__ out) {
    const int idx = blockIdx.x, tid = threadIdx.x;
    const int b = idx / P_N;
    const int p = idx - b * P_N;
    const int j1 = pj1[p], j2 = pj2[p];
    if (j2 < 4) return;
    extern __shared__ float sm[];
    float* re  = sm;            // 9216 floats (padded M <= 8192)
    float* im  = sm + 9216;     // 9216
    float* twx = sm + 18432;    // 1024
    float* twy = sm + 19456;    // 1024
    float* ph  = sm + 20480;    // 513
    const int lgM = 17 - j2;                 // 13..10
    const int M   = 1 << lgM;
    const int lgs = j2 - 3;                  // s' = 2^lgs, 2..16
    // phi + twiddle tables
    for (int i = tid; i <= W_PHI; i += 512) ph[i] = g_phit[i];
    const int lgMs = lgM - (lgM & 1);        // radix-4 sub-size
    const int tstep = T_N >> lgMs;
    for (int r = tid; r < (1 << (lgMs - 2)); r += 512) {
        float2 w = g_tw[r * tstep]; twx[r] = w.x; twy[r] = w.y;
    }
    // load Y[k] = U1h[k] * psi2n[k], k < M (natural order)
    const float2* uh = g_u1h + (size_t)(b * N1 + j1) * T_N;
    const float*  p2 = g_psi2n + (j2 << 13);
    for (int k = tid; k < M; k += 512) {
        float2 u = uh[posrm(k)];
        float  w = p2[k];
        int a = padb(k);
        re[a] = u.x * w; im[a] = u.y * w;
    }
    __syncthreads();
    // optional radix-2 first stage (odd log2): top=sum, bottom=(diff)*conj(g_tw[j*s'])
    if (lgM & 1) {
        int H = M >> 1;
        for (int j = tid; j < H; j += 512) {
            int pa = padb(j), pb = padb(j + H);
            float ax = re[pa], ay = im[pa], bx = re[pb], by = im[pb];
            float2 w = g_tw[j << lgs];
            float dx = ax - bx, dy = ay - by;
            re[pa] = ax + bx; im[pa] = ay + by;
            re[pb] = fmaf(dx, w.x,  dy * w.y);
            im[pb] = fmaf(dy, w.x, -dx * w.y);
        }
        __syncthreads();
    }
    // radix-4 DIF inverse stages (bit-reversed output ordering)
    const int lgQ = lgMs - 2;
    for (int lgL = lgQ; lgL >= 0; lgL -= 2) {
        const int L = 1 << lgL;
        const int twsh = lgQ - lgL;
        for (int u = tid; u < (M >> 2); u += 512) {
            int v   = u & ((1 << lgQ) - 1);
            int sub = u >> lgQ;
            int j   = v & (L - 1);
            int blk = v >> lgL;
            int base = (sub << lgMs) + (blk << (lgL + 2)) + j;
            int a0 = padb(base), a1 = padb(base + L);
            int a2 = padb(base + 2 * L), a3 = padb(base + 3 * L);
            float x0r = re[a0], x0i = im[a0], x1r = re[a1], x1i = im[a1];
            float x2r = re[a2], x2i = im[a2], x3r = re[a3], x3i = im[a3];
            float w1x = twx[j << twsh], w1y = twy[j << twsh];       // g_tw (fwd) value
            float w2x = fmaf(w1x, w1x, -w1y * w1y), w2y = 2.f * w1x * w1y;
            float w3x = fmaf(w2x, w1x, -w2y * w1y);
            float w3y = fmaf(w2x, w1y,  w2y * w1x);
            float t0r = x0r + x2r, t0i = x0i + x2i, t1r = x0r - x2r, t1i = x0i - x2i;
            float t2r = x1r + x3r, t2i = x1i + x3i, t4r = x1r - x3r, t4i = x1i - x3i;
            re[a0] = t0r + t2r; im[a0] = t0i + t2i;
            float d1r = t0r - t2r, d1i = t0i - t2i;                  // * conj(w2)
            re[a1] = fmaf(d1r, w2x,  d1i * w2y);
            im[a1] = fmaf(d1i, w2x, -d1r * w2y);
            float c2r = t1r - t4i, c2i = t1i + t4r;                  // (t1 + i t4)*conj(w1)
            re[a2] = fmaf(c2r, w1x,  c2i * w1y);
            im[a2] = fmaf(c2i, w1x, -c2r * w1y);
            float c3r = t1r + t4i, c3i = t1i - t4r;                  // (t1 - i t4)*conj(w3)
            re[a3] = fmaf(c3r, w3x,  c3i * w3y);
            im[a3] = fmaf(c3i, w3x, -c3r * w3y);
        }
        __syncthreads();
    }
    // modulus (in place, bitrev order — order-agnostic)
    for (int i = tid; i < M; i += 512) {
        int a = padb(i);
        float xr = re[a], xi = im[a];
        re[a] = sqrtf(fmaf(xr, xr, xi * xi));
    }
    __syncthreads();
    // decimated phi-conv: S2[m] = s' * sum_e U2[(m*256/s' - e) mod M] * phi[|e|*s']
    const int lane = tid & 31, warp = tid >> 5;
    const int he = W_PHI >> lgs;
    float* outp = out + S2_BASE + (b * P_N + p) * M_OUT;
    const float fs = (float)(1 << lgs);
    for (int m = warp; m < M_OUT; m += 16) {
        int qc = m << (8 - lgs);
        float acc = 0.f;
        for (int ee = lane; ee <= 2 * he; ee += 32) {
            int e = ee - he;
            int q = (qc - e) & (M - 1);
            int pos = (int)(__brev((unsigned)q) >> (32 - lgM));
            int ae = e < 0 ? -e : e;
            acc = fmaf(re[padb(pos)], ph[ae << lgs], acc);
        }
#pragma unroll
        for (int off = 16; off; off >>= 1)
            acc += __shfl_down_sync(0xffffffffu, acc, off);
        if (lane == 0) outp[m] = acc * fs;
    }
}

// ----------------------- launch --------------------------------------------
extern "C" void kernel_launch(void* const* d_in, const int* in_sizes, int n_in,
                              void* d_out, int out_size) {
    (void)in_sizes; (void)n_in; (void)out_size;
    const float* x    = (const float*)d_in[0];
    const float* psi1 = (const float*)d_in[1];
    const float* psi2 = (const float*)d_in[2];
    const float* phi  = (const float*)d_in[3];
    const int*   pj1  = (const int*)d_in[4];
    const int*   pj2  = (const int*)d_in[5];
    float* out = (float*)d_out;

    cudaFuncSetAttribute(k_xfft,        cudaFuncAttributeMaxDynamicSharedMemorySize, SMEM_BYTES);
    cudaFuncSetAttribute(k_order1,      cudaFuncAttributeMaxDynamicSharedMemorySize, SMEM_BYTES);
    cudaFuncSetAttribute(k_order2,      cudaFuncAttributeMaxDynamicSharedMemorySize, SMEM_BYTES);
    cudaFuncSetAttribute(k_order2_band, cudaFuncAttributeMaxDynamicSharedMemorySize, SMEM_BAND);

    k_init<<<256, 256>>>(psi1, psi2);
    k_phit<<<W_PHI + 1, 256>>>(phi);
    k_xfft<<<B_N, 1024, SMEM_BYTES>>>(x, out);
    dim3 g1(N1, B_N);
    k_order1<<<g1, 1024, SMEM_BYTES>>>(out);
    k_order2<<<B_N * P_N, 1024, SMEM_BYTES>>>(pj1, pj2, out);
    k_order2_band<<<B_N * P_N, 512, SMEM_BAND>>>(pj1, pj2, out);
}

// round 14
// speedup vs baseline: 1.8747x; 1.0407x over previous
#include <cuda_runtime.h>
#include <math.h>

// ---------------------------------------------------------------------------
// Wavelet scattering, T=16384, B=16, n1=64, n2=8, P=224, stride 256.
//
// R14 = R13 + coalesced band input: k_order1's final pass also stores U1h
// bins < M_need(j1) in NATURAL order (g_u1hn); the j2>=4 subband kernel reads
// them coalesced instead of gathering uh[posrm(k)] (32 lines/warp-load).
// For j1>=24 the permuted U1h is never consumed -> its write is skipped.
// Numerics identical to R13 (rel_err 8.87e-5).
// ---------------------------------------------------------------------------

#define T_N    16384
#define B_N    16
#define N1     64
#define N2     8
#define P_N    224
#define M_OUT  64
#define W_PHI  512
#define NPAD   (T_N + 1024)           // padded float array length (i + 4*(i>>6))
#define TW_F2  (4 * (1024 + 64 + 4))  // 4368 float2 of twiddle tables
#define SMEM_BYTES ((2 * NPAD) * 4 + TW_F2 * 8 + (W_PHI + 4) * 4)
#define SMEM_BAND  84000

#define S1_BASE 1024
#define S2_BASE 66560

// ----------------------- device scratch ------------------------------------
static __device__ float2 g_xh[B_N * T_N];                     // permuted
static __device__ float2 g_u1h[(size_t)B_N * N1 * T_N];       // permuted (j1<24 used)
static __device__ float2 g_u1hn[(size_t)B_N * N1 * 8192];     // natural low bins
static __device__ float  g_psi1p[N1 * T_N];                   // permuted, /N
static __device__ float  g_psi2p[N2 * T_N];                   // permuted, /N
static __device__ float  g_psi2n[N2 * 8192];                  // natural, /N (k<8192)
static __device__ float2 g_tw[T_N];                           // e^{-2pi i k/N}
static __device__ float  g_phit[W_PHI + 1];

// ----------------------- helpers -------------------------------------------
__device__ __forceinline__ int adr(int i)  { return i + ((i >> 6) << 2); }
__device__ __forceinline__ int padb(int i) { return i + ((i >> 5) << 2); }

__device__ __forceinline__ float2 cmul(float2 a, float2 b) {
    return make_float2(fmaf(a.x, b.x, -a.y * b.y),
                       fmaf(a.x, b.y,  a.y * b.x));
}
// a * conj(b)
__device__ __forceinline__ float2 cmulc(float2 a, float2 b) {
    return make_float2(fmaf(a.x, b.x,  a.y * b.y),
                       fmaf(a.y, b.x, -a.x * b.y));
}

__device__ __forceinline__ float2 twf(float2 z, float c, float s) {
    return make_float2(fmaf(z.x, c,  z.y * s), fmaf(z.y, c, -z.x * s));
}
__device__ __forceinline__ float2 twi(float2 z, float c, float s) {
    return make_float2(fmaf(z.x, c, -z.y * s), fmaf(z.y, c,  z.x * s));
}

__device__ __forceinline__ void r4f(float2& A, float2& B, float2& C, float2& D) {
    float t0x = A.x + C.x, t0y = A.y + C.y, t1x = A.x - C.x, t1y = A.y - C.y;
    float t2x = B.x + D.x, t2y = B.y + D.y, t3x = B.x - D.x, t3y = B.y - D.y;
    A.x = t0x + t2x; A.y = t0y + t2y;  C.x = t0x - t2x; C.y = t0y - t2y;
    B.x = t1x + t3y; B.y = t1y - t3x;  D.x = t1x - t3y; D.y = t1y + t3x;
}
__device__ __forceinline__ void r4i(float2& A, float2& B, float2& C, float2& D) {
    float t0x = A.x + C.x, t0y = A.y + C.y, t1x = A.x - C.x, t1y = A.y - C.y;
    float t2x = B.x + D.x, t2y = B.y + D.y, t3x = B.x - D.x, t3y = B.y - D.y;
    A.x = t0x + t2x; A.y = t0y + t2y;  C.x = t0x - t2x; C.y = t0y - t2y;
    B.x = t1x - t3y; B.y = t1y + t3x;  D.x = t1x + t3y; D.y = t1y - t3x;
}

#define C16_1 0.9238795325112867f
#define S16_1 0.3826834323650898f
#define RSQ2  0.7071067811865476f

__device__ __forceinline__ void dft16f(float2 a[16]) {
    r4f(a[0], a[4], a[8], a[12]); r4f(a[1], a[5], a[9], a[13]);
    r4f(a[2], a[6], a[10], a[14]); r4f(a[3], a[7], a[11], a[15]);
    a[5]  = twf(a[5],  C16_1,  S16_1);
    a[9]  = twf(a[9],  RSQ2,   RSQ2);
    a[13] = twf(a[13], S16_1,  C16_1);
    a[6]  = twf(a[6],  RSQ2,   RSQ2);
    a[10] = make_float2(a[10].y, -a[10].x);
    a[14] = twf(a[14], -RSQ2,   RSQ2);
    a[7]  = twf(a[7],  S16_1,  C16_1);
    a[11] = twf(a[11], -RSQ2,   RSQ2);
    a[15] = twf(a[15], -C16_1, -S16_1);
    r4f(a[0], a[1], a[2], a[3]);   r4f(a[4], a[5], a[6], a[7]);
    r4f(a[8], a[9], a[10], a[11]); r4f(a[12], a[13], a[14], a[15]);
}
__device__ __forceinline__ void dft16i(float2 a[16]) {
    r4i(a[0], a[4], a[8], a[12]); r4i(a[1], a[5], a[9], a[13]);
    r4i(a[2], a[6], a[10], a[14]); r4i(a[3], a[7], a[11], a[15]);
    a[5]  = twi(a[5],  C16_1,  S16_1);
    a[9]  = twi(a[9],  RSQ2,   RSQ2);
    a[13] = twi(a[13], S16_1,  C16_1);
    a[6]  = twi(a[6],  RSQ2,   RSQ2);
    a[10] = make_float2(-a[10].y, a[10].x);
    a[14] = twi(a[14], -RSQ2,   RSQ2);
    a[7]  = twi(a[7],  S16_1,  C16_1);
    a[11] = twi(a[11], -RSQ2,   RSQ2);
    a[15] = twi(a[15], -C16_1, -S16_1);
    r4i(a[0], a[1], a[2], a[3]);   r4i(a[4], a[5], a[6], a[7]);
    r4i(a[8], a[9], a[10], a[11]); r4i(a[12], a[13], a[14], a[15]);
}

__device__ __forceinline__ float2 twpow_f(float2 v, int r, float2 w1, float2 w2,
                                          float2 w4, float2 w8) {
    if (r & 1) v = cmul(v, w1);
    if (r & 2) v = cmul(v, w2);
    if (r & 4) v = cmul(v, w4);
    if (r & 8) v = cmul(v, w8);
    return v;
}
__device__ __forceinline__ float2 twpow_i(float2 v, int r, float2 w1, float2 w2,
                                          float2 w4, float2 w8) {
    if (r & 1) v = cmulc(v, w1);
    if (r & 2) v = cmulc(v, w2);
    if (r & 4) v = cmulc(v, w4);
    if (r & 8) v = cmulc(v, w8);
    return v;
}

template<bool REAL>
__device__ __forceinline__ void bf16_fwd(float* __restrict__ re, float* __restrict__ im,
                                         int bp, int stride,
                                         float2 w1, float2 w2, float2 w4, float2 w8) {
    float2 a[16];
#pragma unroll
    for (int m = 0; m < 16; m++) {
        int A_ = adr(bp + stride * m);
        a[m] = make_float2(re[A_], REAL ? 0.f : im[A_]);
    }
    dft16f(a);
    { int A_ = adr(bp); re[A_] = a[0].x; im[A_] = a[0].y; }
#pragma unroll
    for (int r = 1; r < 16; r++) {
        int p = ((r & 3) << 2) | (r >> 2);
        float2 v = twpow_f(a[p], r, w1, w2, w4, w8);
        int A_ = adr(bp + stride * r);
        re[A_] = v.x; im[A_] = v.y;
    }
}

template<bool ABS>
__device__ __forceinline__ void bf16_inv(float* __restrict__ re, float* __restrict__ im,
                                         int bp, int stride,
                                         float2 w1, float2 w2, float2 w4, float2 w8) {
    float2 a[16];
#pragma unroll
    for (int r = 0; r < 16; r++) {
        int A_ = adr(bp + stride * r);
        a[r] = make_float2(re[A_], im[A_]);
    }
#pragma unroll
    for (int r = 1; r < 16; r++)
        a[r] = twpow_i(a[r], r, w1, w2, w4, w8);
    dft16i(a);
#pragma unroll
    for (int m = 0; m < 16; m++) {
        int p = ((m & 3) << 2) | (m >> 2);
        int A_ = adr(bp + stride * m);
        if (ABS) {
            re[A_] = sqrtf(fmaf(a[p].x, a[p].x, a[p].y * a[p].y));
        } else {
            re[A_] = a[p].x; im[A_] = a[p].y;
        }
    }
}

// Final forward radix-4 stage: shared -> gmem permuted (used by k_xfft).
__device__ __forceinline__ void pass4_fwd(const float* __restrict__ re,
                                          const float* __restrict__ im,
                                          int t, float2* __restrict__ dst) {
#pragma unroll
    for (int h = 0; h < 4; h++) {
        int i0 = 4 * (t + 1024 * h);
        int A0 = adr(i0);
        float4 rr = *(const float4*)(re + A0);
        float4 ii = *(const float4*)(im + A0);
        float2 A = make_float2(rr.x, ii.x), B = make_float2(rr.y, ii.y);
        float2 C = make_float2(rr.z, ii.z), D = make_float2(rr.w, ii.w);
        r4f(A, B, C, D);
        float4* dp = (float4*)(dst + i0);
        dp[0] = make_float4(A.x, A.y, B.x, B.y);
        dp[1] = make_float4(C.x, C.y, D.x, D.y);
    }
}

// k_order1 variant: optional permuted store + natural-order store of bins
// < M_need. Position p -> natural bin: (p&3)<<12 | ((p>>2)&15)<<8 |
// ((p>>6)&15)<<4 | (p>>10). For p = 4u+j only j=0 (A) and j=1 (B) can be
// < 8192 (bins b0 and b0+4096).
__device__ __forceinline__ void pass4_fwd_o1(const float* __restrict__ re,
                                             const float* __restrict__ im,
                                             int t, float2* __restrict__ dst,
                                             float2* __restrict__ nat,
                                             int M_need, bool write_perm) {
#pragma unroll
    for (int h = 0; h < 4; h++) {
        int u  = t + 1024 * h;
        int i0 = 4 * u;
        int A0 = adr(i0);
        float4 rr = *(const float4*)(re + A0);
        float4 ii = *(const float4*)(im + A0);
        float2 A = make_float2(rr.x, ii.x), B = make_float2(rr.y, ii.y);
        float2 C = make_float2(rr.z, ii.z), D = make_float2(rr.w, ii.w);
        r4f(A, B, C, D);
        if (write_perm) {
            float4* dp = (float4*)(dst + i0);
            dp[0] = make_float4(A.x, A.y, B.x, B.y);
            dp[1] = make_float4(C.x, C.y, D.x, D.y);
        }
        int b0 = ((u & 15) << 8) | (((u >> 4) & 15) << 4) | (u >> 8);
        if (b0 < M_need) nat[b0] = A;
        int b1 = b0 + 4096;
        if (b1 < M_need) nat[b1] = B;
    }
}

// Entry inverse radix-4 stage: gmem * psi -> shared, no twiddles.
__device__ __forceinline__ void pass4_inv(float* __restrict__ re, float* __restrict__ im,
                                          int t, const float2* __restrict__ src,
                                          const float* __restrict__ psi) {
#pragma unroll
    for (int h = 0; h < 4; h++) {
        int i0 = 4 * (t + 1024 * h);
        const float4* sp = (const float4*)(src + i0);
        float4 v1 = sp[0], v2 = sp[1];
        float4 p4 = *(const float4*)(psi + i0);
        float2 A = make_float2(v1.x * p4.x, v1.y * p4.x);
        float2 B = make_float2(v1.z * p4.y, v1.w * p4.y);
        float2 C = make_float2(v2.x * p4.z, v2.y * p4.z);
        float2 D = make_float2(v2.z * p4.w, v2.w * p4.w);
        r4i(A, B, C, D);
        int A0 = adr(i0);
        *(float4*)(re + A0) = make_float4(A.x, B.x, C.x, D.x);
        *(float4*)(im + A0) = make_float4(A.y, B.y, C.y, D.y);
    }
}

struct Tabs {
    float2 *s1w1, *s1w2, *s1w4, *s1w8;
    float2 *s2w1, *s2w2, *s2w4, *s2w8;
    float2 *s3w1, *s3w2, *s3w4, *s3w8;
    float  *ph;
};

__device__ __forceinline__ Tabs layout(float* sm) {
    Tabs tb;
    float2* p = (float2*)(sm + 2 * NPAD);
    tb.s1w1 = p;        tb.s1w2 = p + 1024; tb.s1w4 = p + 2048; tb.s1w8 = p + 3072;
    p += 4096;
    tb.s2w1 = p;        tb.s2w2 = p + 64;   tb.s2w4 = p + 128;  tb.s2w8 = p + 192;
    p += 256;
    tb.s3w1 = p;        tb.s3w2 = p + 4;    tb.s3w4 = p + 8;    tb.s3w8 = p + 12;
    p += 16;
    tb.ph = (float*)p;
    return tb;
}

__device__ __forceinline__ void load_tabs(Tabs tb, int t) {
    if (t < 1024) {
        tb.s1w1[t] = g_tw[t];
        tb.s1w2[t] = g_tw[2 * t];
        tb.s1w4[t] = g_tw[4 * t];
        tb.s1w8[t] = g_tw[8 * t];
    }
    if (t < 64) {
        tb.s2w1[t] = g_tw[16 * t];
        tb.s2w2[t] = g_tw[32 * t];
        tb.s2w4[t] = g_tw[64 * t];
        tb.s2w8[t] = g_tw[128 * t];
    }
    if (t < 4) {
        tb.s3w1[t] = g_tw[256 * t];
        tb.s3w2[t] = g_tw[512 * t];
        tb.s3w4[t] = g_tw[1024 * t];
        tb.s3w8[t] = g_tw[2048 * t];
    }
    for (int i = t; i <= W_PHI; i += 1024) tb.ph[i] = g_phit[i];
}

template<bool REAL_IN>
__device__ __forceinline__ void fwd3(float* re, float* im, Tabs tb, int t) {
    bf16_fwd<REAL_IN>(re, im, t, 1024,
                      tb.s1w1[t], tb.s1w2[t], tb.s1w4[t], tb.s1w8[t]);
    __syncthreads();
    { int j = t & 63;
      bf16_fwd<false>(re, im, ((t >> 6) << 10) + j, 64,
                      tb.s2w1[j], tb.s2w2[j], tb.s2w4[j], tb.s2w8[j]); }
    __syncthreads();
    { int j = t & 3;
      bf16_fwd<false>(re, im, ((t >> 2) << 6) + j, 4,
                      tb.s3w1[j], tb.s3w2[j], tb.s3w4[j], tb.s3w8[j]); }
    __syncthreads();
}

template<bool ABS>
__device__ __forceinline__ void inv3(float* re, float* im, Tabs tb, int t) {
    { int j = t & 3;
      bf16_inv<false>(re, im, ((t >> 2) << 6) + j, 4,
                      tb.s3w1[j], tb.s3w2[j], tb.s3w4[j], tb.s3w8[j]); }
    __syncthreads();
    { int j = t & 63;
      bf16_inv<false>(re, im, ((t >> 6) << 10) + j, 64,
                      tb.s2w1[j], tb.s2w2[j], tb.s2w4[j], tb.s2w8[j]); }
    __syncthreads();
    bf16_inv<ABS>(re, im, t, 1024,
                  tb.s1w1[t], tb.s1w2[t], tb.s1w4[t], tb.s1w8[t]);
    __syncthreads();
}

__device__ __forceinline__ void lowpass64(const float* __restrict__ re,
                                          const float* __restrict__ ph,
                                          float* __restrict__ outp) {
    const int lane = threadIdx.x & 31;
    const int warp = threadIdx.x >> 5;
    for (int m = warp; m < M_OUT; m += 32) {
        const int t0 = m << 8;
        float acc = 0.f;
        for (int dd = lane; dd <= 2 * W_PHI; dd += 32) {
            const int d   = dd - W_PHI;
            const int ad  = d < 0 ? -d : d;
            const int idx = (t0 - d + T_N) & (T_N - 1);
            acc = fmaf(re[adr(idx)], ph[ad], acc);
        }
#pragma unroll
        for (int off = 16; off; off >>= 1)
            acc += __shfl_down_sync(0xffffffffu, acc, off);
        if (lane == 0) outp[m] = acc;
    }
}

// ----------------------- init kernels ---------------------------------------
// natural bin k -> gmem position (matches fwd3+pass4_fwd output layout)
__device__ __forceinline__ int posrm(int k) {
    return ((k & 15) << 10) | (((k >> 4) & 15) << 6) | (((k >> 8) & 15) << 2) | (k >> 12);
}

__global__ void k_init(const float* __restrict__ psi1, const float* __restrict__ psi2) {
    const float invN = 1.0f / (float)T_N;
    const int total = N1 * T_N;
    for (int i = blockIdx.x * blockDim.x + threadIdx.x; i < total;
         i += gridDim.x * blockDim.x) {
        const int k = i & (T_N - 1);
        const int j = i >> 14;
        const int pos = posrm(k);
        g_psi1p[(j << 14) + pos] = psi1[i] * invN;
        if (j < N2) {
            g_psi2p[(j << 14) + pos] = psi2[i] * invN;
            if (k < 8192) g_psi2n[(j << 13) + k] = psi2[i] * invN;
        }
        if (j == 0) {
            float sn, cn;
            sincospif(-2.0f * (float)k / (float)T_N, &sn, &cn);
            g_tw[k] = make_float2(cn, sn);
        }
    }
}

__global__ void k_phit(const float* __restrict__ phi) {
    __shared__ float red[256];
    const int n = blockIdx.x;   // 0..W_PHI
    float acc = 0.f;
    for (int k = threadIdx.x; k < T_N; k += blockDim.x)
        acc = fmaf(phi[k], g_tw[(k * n) & (T_N - 1)].x, acc);
    red[threadIdx.x] = acc;
    __syncthreads();
    for (int off = 128; off; off >>= 1) {
        if (threadIdx.x < off) red[threadIdx.x] += red[threadIdx.x + off];
        __syncthreads();
    }
    if (threadIdx.x == 0) g_phit[n] = red[0] * (1.0f / (float)T_N);
}

// ----------------------- main kernels ---------------------------------------
__global__ void __launch_bounds__(1024, 1)
k_xfft(const float* __restrict__ x, float* __restrict__ out) {
    extern __shared__ float sm[];
    float* re = sm; float* im = sm + NPAD;
    Tabs tb = layout(sm);
    const int b = blockIdx.x, t = threadIdx.x;
    load_tabs(tb, t);
    const float* xb = x + b * T_N;
    for (int i = t; i < T_N; i += 1024) re[adr(i)] = xb[i];
    __syncthreads();
    lowpass64(re, tb.ph, out + b * M_OUT);              // S0
    __syncthreads();
    fwd3<true>(re, im, tb, t);
    pass4_fwd(re, im, t, g_xh + b * T_N);
}

__global__ void __launch_bounds__(1024, 1)
k_order1(float* __restrict__ out) {
    extern __shared__ float sm[];
    float* re = sm; float* im = sm + NPAD;
    Tabs tb = layout(sm);
    const int j1 = blockIdx.x, b = blockIdx.y, t = threadIdx.x;
    load_tabs(tb, t);
    pass4_inv(re, im, t, g_xh + b * T_N, g_psi1p + j1 * T_N);
    __syncthreads();
    inv3<true>(re, im, tb, t);                          // |ifft| -> re
    lowpass64(re, tb.ph, out + S1_BASE + (b * N1 + j1) * M_OUT);   // S1
    __syncthreads();
    fwd3<true>(re, im, tb, t);
    // natural low-bin copy for the band path; permuted copy only if consumed
    const int o = j1 >> 3;
    const int oc = o < 3 ? 3 : o;
    const int M_need = 1 << (16 - oc);                  // 8192 .. 512
    pass4_fwd_o1(re, im, t,
                 g_u1h + (size_t)(b * N1 + j1) * T_N,
                 g_u1hn + (size_t)(b * N1 + j1) * 8192,
                 M_need, j1 < 24);
}

// Full-size order-2 path: pairs with j2 <= 3 (all have j1 < 24).
__global__ void __launch_bounds__(1024, 1)
k_order2(const int* __restrict__ pj1, const int* __restrict__ pj2,
         float* __restrict__ out) {
    const int idx = blockIdx.x;
    const int b = idx / P_N;
    const int p = idx - b * P_N;
    const int j2 = pj2[p];
    if (j2 >= 4) return;
    extern __shared__ float sm[];
    float* re = sm; float* im = sm + NPAD;
    Tabs tb = layout(sm);
    const int t = threadIdx.x;
    const int j1 = pj1[p];
    load_tabs(tb, t);
    pass4_inv(re, im, t, g_u1h + (size_t)(b * N1 + j1) * T_N, g_psi2p + j2 * T_N);
    __syncthreads();
    inv3<true>(re, im, tb, t);
    lowpass64(re, tb.ph, out + S2_BASE + (b * P_N + p) * M_OUT);   // S2
}

// Subband order-2 path: pairs with j2 >= 4.  M = 2^(17-j2), s' = 2^(j2-3).
// Y[k] = U1hn[k]*psi2n[k] (k < M, natural, COALESCED) -> inverse DIF FFT
// (natural in -> bit-reversed out) -> |.| -> decimated phi-conv (x s').
__global__ void __launch_bounds__(512, 2)
k_order2_band(const int* __restrict__ pj1, const int* __restrict__ pj2,
              float* __restrict__ out) {
    const int idx = blockIdx.x, tid = threadIdx.x;
    const int b = idx / P_N;
    const int p = idx - b * P_N;
    const int j1 = pj1[p], j2 = pj2[p];
    if (j2 < 4) return;
    extern __shared__ float sm[];
    float* re  = sm;            // 9216 floats (padded M <= 8192)
    float* im  = sm + 9216;     // 9216
    float* twx = sm + 18432;    // 1024
    float* twy = sm + 19456;    // 1024
    float* ph  = sm + 20480;    // 513
    const int lgM = 17 - j2;                 // 13..10
    const int M   = 1 << lgM;
    const int lgs = j2 - 3;                  // s' = 2^lgs
    // phi + twiddle tables
    for (int i = tid; i <= W_PHI; i += 512) ph[i] = g_phit[i];
    const int lgMs = lgM - (lgM & 1);        // radix-4 sub-size
    const int tstep = T_N >> lgMs;
    for (int r = tid; r < (1 << (lgMs - 2)); r += 512) {
        float2 w = g_tw[r * tstep]; twx[r] = w.x; twy[r] = w.y;
    }
    // load Y[k] = U1hn[k] * psi2n[k], k < M (natural order, coalesced)
    const float2* uhn = g_u1hn + (size_t)(b * N1 + j1) * 8192;
    const float*  p2  = g_psi2n + (j2 << 13);
    for (int k = tid; k < M; k += 512) {
        float2 u = uhn[k];
        float  w = p2[k];
        int a = padb(k);
        re[a] = u.x * w; im[a] = u.y * w;
    }
    __syncthreads();
    // optional radix-2 first stage (odd log2): top=sum, bottom=(diff)*conj(g_tw[j*s'])
    if (lgM & 1) {
        int H = M >> 1;
        for (int j = tid; j < H; j += 512) {
            int pa = padb(j), pb = padb(j + H);
            float ax = re[pa], ay = im[pa], bx = re[pb], by = im[pb];
            float2 w = g_tw[j << lgs];
            float dx = ax - bx, dy = ay - by;
            re[pa] = ax + bx; im[pa] = ay + by;
            re[pb] = fmaf(dx, w.x,  dy * w.y);
            im[pb] = fmaf(dy, w.x, -dx * w.y);
        }
        __syncthreads();
    }
    // radix-4 DIF inverse stages (bit-reversed output ordering)
    const int lgQ = lgMs - 2;
    for (int lgL = lgQ; lgL >= 0; lgL -= 2) {
        const int L = 1 << lgL;
        const int twsh = lgQ - lgL;
        for (int u = tid; u < (M >> 2); u += 512) {
            int v   = u & ((1 << lgQ) - 1);
            int sub = u >> lgQ;
            int j   = v & (L - 1);
            int blk = v >> lgL;
            int base = (sub << lgMs) + (blk << (lgL + 2)) + j;
            int a0 = padb(base), a1 = padb(base + L);
            int a2 = padb(base + 2 * L), a3 = padb(base + 3 * L);
            float x0r = re[a0], x0i = im[a0], x1r = re[a1], x1i = im[a1];
            float x2r = re[a2], x2i = im[a2], x3r = re[a3], x3i = im[a3];
            float w1x = twx[j << twsh], w1y = twy[j << twsh];       // g_tw (fwd) value
            float w2x = fmaf(w1x, w1x, -w1y * w1y), w2y = 2.f * w1x * w1y;
            float w3x = fmaf(w2x, w1x, -w2y * w1y);
            float w3y = fmaf(w2x, w1y,  w2y * w1x);
            float t0r = x0r + x2r, t0i = x0i + x2i, t1r = x0r - x2r, t1i = x0i - x2i;
            float t2r = x1r + x3r, t2i = x1i + x3i, t4r = x1r - x3r, t4i = x1i - x3i;
            re[a0] = t0r + t2r; im[a0] = t0i + t2i;
            float d1r = t0r - t2r, d1i = t0i - t2i;                  // * conj(w2)
            re[a1] = fmaf(d1r, w2x,  d1i * w2y);
            im[a1] = fmaf(d1i, w2x, -d1r * w2y);
            float c2r = t1r - t4i, c2i = t1i + t4r;                  // (t1 + i t4)*conj(w1)
            re[a2] = fmaf(c2r, w1x,  c2i * w1y);
            im[a2] = fmaf(c2i, w1x, -c2r * w1y);
            float c3r = t1r + t4i, c3i = t1i - t4r;                  // (t1 - i t4)*conj(w3)
            re[a3] = fmaf(c3r, w3x,  c3i * w3y);
            im[a3] = fmaf(c3i, w3x, -c3r * w3y);
        }
        __syncthreads();
    }
    // modulus (in place, bitrev order — order-agnostic)
    for (int i = tid; i < M; i += 512) {
        int a = padb(i);
        float xr = re[a], xi = im[a];
        re[a] = sqrtf(fmaf(xr, xr, xi * xi));
    }
    __syncthreads();
    // decimated phi-conv: S2[m] = s' * sum_e U2[(m*256/s' - e) mod M] * phi[|e|*s']
    const int lane = tid & 31, warp = tid >> 5;
    const int he = W_PHI >> lgs;
    float* outp = out + S2_BASE + (b * P_N + p) * M_OUT;
    const float fs = (float)(1 << lgs);
    for (int m = warp; m < M_OUT; m += 16) {
        int qc = m << (8 - lgs);
        float acc = 0.f;
        for (int ee = lane; ee <= 2 * he; ee += 32) {
            int e = ee - he;
            int q = (qc - e) & (M - 1);
            int pos = (int)(__brev((unsigned)q) >> (32 - lgM));
            int ae = e < 0 ? -e : e;
            acc = fmaf(re[padb(pos)], ph[ae << lgs], acc);
        }
#pragma unroll
        for (int off = 16; off; off >>= 1)
            acc += __shfl_down_sync(0xffffffffu, acc, off);
        if (lane == 0) outp[m] = acc * fs;
    }
}

// ----------------------- launch --------------------------------------------
extern "C" void kernel_launch(void* const* d_in, const int* in_sizes, int n_in,
                              void* d_out, int out_size) {
    (void)in_sizes; (void)n_in; (void)out_size;
    const float* x    = (const float*)d_in[0];
    const float* psi1 = (const float*)d_in[1];
    const float* psi2 = (const float*)d_in[2];
    const float* phi  = (const float*)d_in[3];
    const int*   pj1  = (const int*)d_in[4];
    const int*   pj2  = (const int*)d_in[5];
    float* out = (float*)d_out;

    cudaFuncSetAttribute(k_xfft,        cudaFuncAttributeMaxDynamicSharedMemorySize, SMEM_BYTES);
    cudaFuncSetAttribute(k_order1,      cudaFuncAttributeMaxDynamicSharedMemorySize, SMEM_BYTES);
    cudaFuncSetAttribute(k_order2,      cudaFuncAttributeMaxDynamicSharedMemorySize, SMEM_BYTES);
    cudaFuncSetAttribute(k_order2_band, cudaFuncAttributeMaxDynamicSharedMemorySize, SMEM_BAND);

    k_init<<<256, 256>>>(psi1, psi2);
    k_phit<<<W_PHI + 1, 256>>>(phi);
    k_xfft<<<B_N, 1024, SMEM_BYTES>>>(x, out);
    dim3 g1(N1, B_N);
    k_order1<<<g1, 1024, SMEM_BYTES>>>(out);
    k_order2<<<B_N * P_N, 1024, SMEM_BYTES>>>(pj1, pj2, out);
    k_order2_band<<<B_N * P_N, 512, SMEM_BAND>>>(pj1, pj2, out);
}

// round 15
// speedup vs baseline: 2.0688x; 1.1036x over previous
#include <cuda_runtime.h>
#include <math.h>

// ---------------------------------------------------------------------------
// Wavelet scattering, T=16384, B=16, n1=64, n2=8, P=224, stride 256.
//
// R15 = R14 + (1) band conv de-bitreversed via a padded natural-order copy
// (fixes 32-way smem bank conflicts on every conv tap), (2) k_phit truncated
// to the 1024 nonzero phi bins (16x less work), (3) compact per-path pair
// lists so full/band kernels launch only the CTAs they run (j2-sorted).
// ---------------------------------------------------------------------------

#define T_N    16384
#define B_N    16
#define N1     64
#define N2     8
#define P_N    224
#define M_OUT  64
#define W_PHI  512
#define NPAD   (T_N + 1024)           // padded float array length (i + 4*(i>>6))
#define TW_F2  (4 * (1024 + 64 + 4))  // 4368 float2 of twiddle tables
#define SMEM_BYTES ((2 * NPAD) * 4 + TW_F2 * 8 + (W_PHI + 4) * 4)
#define SMEM_BAND  84000
#define FULL_P 48
#define BAND_P 176

#define S1_BASE 1024
#define S2_BASE 66560

// ----------------------- device scratch ------------------------------------
static __device__ float2 g_xh[B_N * T_N];                     // permuted
static __device__ float2 g_u1h[(size_t)B_N * N1 * T_N];       // permuted (j1<24 used)
static __device__ float2 g_u1hn[(size_t)B_N * N1 * 8192];     // natural low bins
static __device__ float  g_psi1p[N1 * T_N];                   // permuted, /N
static __device__ float  g_psi2p[N2 * T_N];                   // permuted, /N
static __device__ float  g_psi2n[N2 * 8192];                  // natural, /N (k<8192)
static __device__ float2 g_tw[T_N];                           // e^{-2pi i k/N}
static __device__ float  g_phit[W_PHI + 1];
static __device__ int    g_fullp[FULL_P];
static __device__ int    g_bandp[BAND_P];

// ----------------------- helpers -------------------------------------------
__device__ __forceinline__ int adr(int i)  { return i + ((i >> 6) << 2); }
__device__ __forceinline__ int padb(int i) { return i + ((i >> 5) << 2); }

__device__ __forceinline__ float2 cmul(float2 a, float2 b) {
    return make_float2(fmaf(a.x, b.x, -a.y * b.y),
                       fmaf(a.x, b.y,  a.y * b.x));
}
// a * conj(b)
__device__ __forceinline__ float2 cmulc(float2 a, float2 b) {
    return make_float2(fmaf(a.x, b.x,  a.y * b.y),
                       fmaf(a.y, b.x, -a.x * b.y));
}

__device__ __forceinline__ float2 twf(float2 z, float c, float s) {
    return make_float2(fmaf(z.x, c,  z.y * s), fmaf(z.y, c, -z.x * s));
}
__device__ __forceinline__ float2 twi(float2 z, float c, float s) {
    return make_float2(fmaf(z.x, c, -z.y * s), fmaf(z.y, c,  z.x * s));
}

__device__ __forceinline__ void r4f(float2& A, float2& B, float2& C, float2& D) {
    float t0x = A.x + C.x, t0y = A.y + C.y, t1x = A.x - C.x, t1y = A.y - C.y;
    float t2x = B.x + D.x, t2y = B.y + D.y, t3x = B.x - D.x, t3y = B.y - D.y;
    A.x = t0x + t2x; A.y = t0y + t2y;  C.x = t0x - t2x; C.y = t0y - t2y;
    B.x = t1x + t3y; B.y = t1y - t3x;  D.x = t1x - t3y; D.y = t1y + t3x;
}
__device__ __forceinline__ void r4i(float2& A, float2& B, float2& C, float2& D) {
    float t0x = A.x + C.x, t0y = A.y + C.y, t1x = A.x - C.x, t1y = A.y - C.y;
    float t2x = B.x + D.x, t2y = B.y + D.y, t3x = B.x - D.x, t3y = B.y - D.y;
    A.x = t0x + t2x; A.y = t0y + t2y;  C.x = t0x - t2x; C.y = t0y - t2y;
    B.x = t1x - t3y; B.y = t1y + t3x;  D.x = t1x + t3y; D.y = t1y - t3x;
}

#define C16_1 0.9238795325112867f
#define S16_1 0.3826834323650898f
#define RSQ2  0.7071067811865476f

__device__ __forceinline__ void dft16f(float2 a[16]) {
    r4f(a[0], a[4], a[8], a[12]); r4f(a[1], a[5], a[9], a[13]);
    r4f(a[2], a[6], a[10], a[14]); r4f(a[3], a[7], a[11], a[15]);
    a[5]  = twf(a[5],  C16_1,  S16_1);
    a[9]  = twf(a[9],  RSQ2,   RSQ2);
    a[13] = twf(a[13], S16_1,  C16_1);
    a[6]  = twf(a[6],  RSQ2,   RSQ2);
    a[10] = make_float2(a[10].y, -a[10].x);
    a[14] = twf(a[14], -RSQ2,   RSQ2);
    a[7]  = twf(a[7],  S16_1,  C16_1);
    a[11] = twf(a[11], -RSQ2,   RSQ2);
    a[15] = twf(a[15], -C16_1, -S16_1);
    r4f(a[0], a[1], a[2], a[3]);   r4f(a[4], a[5], a[6], a[7]);
    r4f(a[8], a[9], a[10], a[11]); r4f(a[12], a[13], a[14], a[15]);
}
__device__ __forceinline__ void dft16i(float2 a[16]) {
    r4i(a[0], a[4], a[8], a[12]); r4i(a[1], a[5], a[9], a[13]);
    r4i(a[2], a[6], a[10], a[14]); r4i(a[3], a[7], a[11], a[15]);
    a[5]  = twi(a[5],  C16_1,  S16_1);
    a[9]  = twi(a[9],  RSQ2,   RSQ2);
    a[13] = twi(a[13], S16_1,  C16_1);
    a[6]  = twi(a[6],  RSQ2,   RSQ2);
    a[10] = make_float2(-a[10].y, a[10].x);
    a[14] = twi(a[14], -RSQ2,   RSQ2);
    a[7]  = twi(a[7],  S16_1,  C16_1);
    a[11] = twi(a[11], -RSQ2,   RSQ2);
    a[15] = twi(a[15], -C16_1, -S16_1);
    r4i(a[0], a[1], a[2], a[3]);   r4i(a[4], a[5], a[6], a[7]);
    r4i(a[8], a[9], a[10], a[11]); r4i(a[12], a[13], a[14], a[15]);
}

__device__ __forceinline__ float2 twpow_f(float2 v, int r, float2 w1, float2 w2,
                                          float2 w4, float2 w8) {
    if (r & 1) v = cmul(v, w1);
    if (r & 2) v = cmul(v, w2);
    if (r & 4) v = cmul(v, w4);
    if (r & 8) v = cmul(v, w8);
    return v;
}
__device__ __forceinline__ float2 twpow_i(float2 v, int r, float2 w1, float2 w2,
                                          float2 w4, float2 w8) {
    if (r & 1) v = cmulc(v, w1);
    if (r & 2) v = cmulc(v, w2);
    if (r & 4) v = cmulc(v, w4);
    if (r & 8) v = cmulc(v, w8);
    return v;
}

template<bool REAL>
__device__ __forceinline__ void bf16_fwd(float* __restrict__ re, float* __restrict__ im,
                                         int bp, int stride,
                                         float2 w1, float2 w2, float2 w4, float2 w8) {
    float2 a[16];
#pragma unroll
    for (int m = 0; m < 16; m++) {
        int A_ = adr(bp + stride * m);
        a[m] = make_float2(re[A_], REAL ? 0.f : im[A_]);
    }
    dft16f(a);
    { int A_ = adr(bp); re[A_] = a[0].x; im[A_] = a[0].y; }
#pragma unroll
    for (int r = 1; r < 16; r++) {
        int p = ((r & 3) << 2) | (r >> 2);
        float2 v = twpow_f(a[p], r, w1, w2, w4, w8);
        int A_ = adr(bp + stride * r);
        re[A_] = v.x; im[A_] = v.y;
    }
}

template<bool ABS>
__device__ __forceinline__ void bf16_inv(float* __restrict__ re, float* __restrict__ im,
                                         int bp, int stride,
                                         float2 w1, float2 w2, float2 w4, float2 w8) {
    float2 a[16];
#pragma unroll
    for (int r = 0; r < 16; r++) {
        int A_ = adr(bp + stride * r);
        a[r] = make_float2(re[A_], im[A_]);
    }
#pragma unroll
    for (int r = 1; r < 16; r++)
        a[r] = twpow_i(a[r], r, w1, w2, w4, w8);
    dft16i(a);
#pragma unroll
    for (int m = 0; m < 16; m++) {
        int p = ((m & 3) << 2) | (m >> 2);
        int A_ = adr(bp + stride * m);
        if (ABS) {
            re[A_] = sqrtf(fmaf(a[p].x, a[p].x, a[p].y * a[p].y));
        } else {
            re[A_] = a[p].x; im[A_] = a[p].y;
        }
    }
}

// Final forward radix-4 stage: shared -> gmem permuted (used by k_xfft).
__device__ __forceinline__ void pass4_fwd(const float* __restrict__ re,
                                          const float* __restrict__ im,
                                          int t, float2* __restrict__ dst) {
#pragma unroll
    for (int h = 0; h < 4; h++) {
        int i0 = 4 * (t + 1024 * h);
        int A0 = adr(i0);
        float4 rr = *(const float4*)(re + A0);
        float4 ii = *(const float4*)(im + A0);
        float2 A = make_float2(rr.x, ii.x), B = make_float2(rr.y, ii.y);
        float2 C = make_float2(rr.z, ii.z), D = make_float2(rr.w, ii.w);
        r4f(A, B, C, D);
        float4* dp = (float4*)(dst + i0);
        dp[0] = make_float4(A.x, A.y, B.x, B.y);
        dp[1] = make_float4(C.x, C.y, D.x, D.y);
    }
}

// k_order1 variant: optional permuted store + natural-order store of bins
// < M_need (bins b0 and b0+4096 are the only outputs < 8192).
__device__ __forceinline__ void pass4_fwd_o1(const float* __restrict__ re,
                                             const float* __restrict__ im,
                                             int t, float2* __restrict__ dst,
                                             float2* __restrict__ nat,
                                             int M_need, bool write_perm) {
#pragma unroll
    for (int h = 0; h < 4; h++) {
        int u  = t + 1024 * h;
        int i0 = 4 * u;
        int A0 = adr(i0);
        float4 rr = *(const float4*)(re + A0);
        float4 ii = *(const float4*)(im + A0);
        float2 A = make_float2(rr.x, ii.x), B = make_float2(rr.y, ii.y);
        float2 C = make_float2(rr.z, ii.z), D = make_float2(rr.w, ii.w);
        r4f(A, B, C, D);
        if (write_perm) {
            float4* dp = (float4*)(dst + i0);
            dp[0] = make_float4(A.x, A.y, B.x, B.y);
            dp[1] = make_float4(C.x, C.y, D.x, D.y);
        }
        int b0 = ((u & 15) << 8) | (((u >> 4) & 15) << 4) | (u >> 8);
        if (b0 < M_need) nat[b0] = A;
        int b1 = b0 + 4096;
        if (b1 < M_need) nat[b1] = B;
    }
}

// Entry inverse radix-4 stage: gmem * psi -> shared, no twiddles.
__device__ __forceinline__ void pass4_inv(float* __restrict__ re, float* __restrict__ im,
                                          int t, const float2* __restrict__ src,
                                          const float* __restrict__ psi) {
#pragma unroll
    for (int h = 0; h < 4; h++) {
        int i0 = 4 * (t + 1024 * h);
        const float4* sp = (const float4*)(src + i0);
        float4 v1 = sp[0], v2 = sp[1];
        float4 p4 = *(const float4*)(psi + i0);
        float2 A = make_float2(v1.x * p4.x, v1.y * p4.x);
        float2 B = make_float2(v1.z * p4.y, v1.w * p4.y);
        float2 C = make_float2(v2.x * p4.z, v2.y * p4.z);
        float2 D = make_float2(v2.z * p4.w, v2.w * p4.w);
        r4i(A, B, C, D);
        int A0 = adr(i0);
        *(float4*)(re + A0) = make_float4(A.x, B.x, C.x, D.x);
        *(float4*)(im + A0) = make_float4(A.y, B.y, C.y, D.y);
    }
}

struct Tabs {
    float2 *s1w1, *s1w2, *s1w4, *s1w8;
    float2 *s2w1, *s2w2, *s2w4, *s2w8;
    float2 *s3w1, *s3w2, *s3w4, *s3w8;
    float  *ph;
};

__device__ __forceinline__ Tabs layout(float* sm) {
    Tabs tb;
    float2* p = (float2*)(sm + 2 * NPAD);
    tb.s1w1 = p;        tb.s1w2 = p + 1024; tb.s1w4 = p + 2048; tb.s1w8 = p + 3072;
    p += 4096;
    tb.s2w1 = p;        tb.s2w2 = p + 64;   tb.s2w4 = p + 128;  tb.s2w8 = p + 192;
    p += 256;
    tb.s3w1 = p;        tb.s3w2 = p + 4;    tb.s3w4 = p + 8;    tb.s3w8 = p + 12;
    p += 16;
    tb.ph = (float*)p;
    return tb;
}

__device__ __forceinline__ void load_tabs(Tabs tb, int t) {
    if (t < 1024) {
        tb.s1w1[t] = g_tw[t];
        tb.s1w2[t] = g_tw[2 * t];
        tb.s1w4[t] = g_tw[4 * t];
        tb.s1w8[t] = g_tw[8 * t];
    }
    if (t < 64) {
        tb.s2w1[t] = g_tw[16 * t];
        tb.s2w2[t] = g_tw[32 * t];
        tb.s2w4[t] = g_tw[64 * t];
        tb.s2w8[t] = g_tw[128 * t];
    }
    if (t < 4) {
        tb.s3w1[t] = g_tw[256 * t];
        tb.s3w2[t] = g_tw[512 * t];
        tb.s3w4[t] = g_tw[1024 * t];
        tb.s3w8[t] = g_tw[2048 * t];
    }
    for (int i = t; i <= W_PHI; i += 1024) tb.ph[i] = g_phit[i];
}

template<bool REAL_IN>
__device__ __forceinline__ void fwd3(float* re, float* im, Tabs tb, int t) {
    bf16_fwd<REAL_IN>(re, im, t, 1024,
                      tb.s1w1[t], tb.s1w2[t], tb.s1w4[t], tb.s1w8[t]);
    __syncthreads();
    { int j = t & 63;
      bf16_fwd<false>(re, im, ((t >> 6) << 10) + j, 64,
                      tb.s2w1[j], tb.s2w2[j], tb.s2w4[j], tb.s2w8[j]); }
    __syncthreads();
    { int j = t & 3;
      bf16_fwd<false>(re, im, ((t >> 2) << 6) + j, 4,
                      tb.s3w1[j], tb.s3w2[j], tb.s3w4[j], tb.s3w8[j]); }
    __syncthreads();
}

template<bool ABS>
__device__ __forceinline__ void inv3(float* re, float* im, Tabs tb, int t) {
    { int j = t & 3;
      bf16_inv<false>(re, im, ((t >> 2) << 6) + j, 4,
                      tb.s3w1[j], tb.s3w2[j], tb.s3w4[j], tb.s3w8[j]); }
    __syncthreads();
    { int j = t & 63;
      bf16_inv<false>(re, im, ((t >> 6) << 10) + j, 64,
                      tb.s2w1[j], tb.s2w2[j], tb.s2w4[j], tb.s2w8[j]); }
    __syncthreads();
    bf16_inv<ABS>(re, im, t, 1024,
                  tb.s1w1[t], tb.s1w2[t], tb.s1w4[t], tb.s1w8[t]);
    __syncthreads();
}

__device__ __forceinline__ void lowpass64(const float* __restrict__ re,
                                          const float* __restrict__ ph,
                                          float* __restrict__ outp) {
    const int lane = threadIdx.x & 31;
    const int warp = threadIdx.x >> 5;
    for (int m = warp; m < M_OUT; m += 32) {
        const int t0 = m << 8;
        float acc = 0.f;
        for (int dd = lane; dd <= 2 * W_PHI; dd += 32) {
            const int d   = dd - W_PHI;
            const int ad  = d < 0 ? -d : d;
            const int idx = (t0 - d + T_N) & (T_N - 1);
            acc = fmaf(re[adr(idx)], ph[ad], acc);
        }
#pragma unroll
        for (int off = 16; off; off >>= 1)
            acc += __shfl_down_sync(0xffffffffu, acc, off);
        if (lane == 0) outp[m] = acc;
    }
}

// ----------------------- init kernels ---------------------------------------
__device__ __forceinline__ int posrm(int k) {
    return ((k & 15) << 10) | (((k >> 4) & 15) << 6) | (((k >> 8) & 15) << 2) | (k >> 12);
}

__global__ void k_init(const float* __restrict__ psi1, const float* __restrict__ psi2) {
    const float invN = 1.0f / (float)T_N;
    const int total = N1 * T_N;
    for (int i = blockIdx.x * blockDim.x + threadIdx.x; i < total;
         i += gridDim.x * blockDim.x) {
        const int k = i & (T_N - 1);
        const int j = i >> 14;
        const int pos = posrm(k);
        g_psi1p[(j << 14) + pos] = psi1[i] * invN;
        if (j < N2) {
            g_psi2p[(j << 14) + pos] = psi2[i] * invN;
            if (k < 8192) g_psi2n[(j << 13) + k] = psi2[i] * invN;
        }
        if (j == 0) {
            float sn, cn;
            sincospif(-2.0f * (float)k / (float)T_N, &sn, &cn);
            g_tw[k] = make_float2(cn, sn);
        }
    }
}

// Compact per-path pair lists (deterministic; tiny).
__global__ void k_lists(const int* __restrict__ pj2) {
    if (blockIdx.x == 0 && threadIdx.x == 0) {
        int nf = 0, nb = 0;
        for (int i = 0; i < FULL_P; i++) g_fullp[i] = -1;
        for (int i = 0; i < BAND_P; i++) g_bandp[i] = -1;
        for (int p = 0; p < P_N; p++)
            if (pj2[p] < 4 && nf < FULL_P) g_fullp[nf++] = p;
        for (int j2v = 4; j2v <= 7; j2v++)          // big-M (j2=4) first
            for (int p = 0; p < P_N; p++)
                if (pj2[p] == j2v && nb < BAND_P) g_bandp[nb++] = p;
    }
}

// phi_t[n]: phi_hat is symmetric and < 1e-400 beyond bin 1024, so
// phi_t[n] = (1/T)(phi[0] + 2*sum_{k=1}^{1023} phi[k] cos(2 pi k n / T)).
__global__ void k_phit(const float* __restrict__ phi) {
    __shared__ float red[256];
    const int n = blockIdx.x;   // 0..W_PHI
    float acc = 0.f;
    for (int k = threadIdx.x; k < 1024; k += blockDim.x) {
        float coef = (k == 0) ? phi[0] : 2.f * phi[k];
        acc = fmaf(coef, g_tw[(k * n) & (T_N - 1)].x, acc);
    }
    red[threadIdx.x] = acc;
    __syncthreads();
    for (int off = 128; off; off >>= 1) {
        if (threadIdx.x < off) red[threadIdx.x] += red[threadIdx.x + off];
        __syncthreads();
    }
    if (threadIdx.x == 0) g_phit[n] = red[0] * (1.0f / (float)T_N);
}

// ----------------------- main kernels ---------------------------------------
__global__ void __launch_bounds__(1024, 1)
k_xfft(const float* __restrict__ x, float* __restrict__ out) {
    extern __shared__ float sm[];
    float* re = sm; float* im = sm + NPAD;
    Tabs tb = layout(sm);
    const int b = blockIdx.x, t = threadIdx.x;
    load_tabs(tb, t);
    const float* xb = x + b * T_N;
    for (int i = t; i < T_N; i += 1024) re[adr(i)] = xb[i];
    __syncthreads();
    lowpass64(re, tb.ph, out + b * M_OUT);              // S0
    __syncthreads();
    fwd3<true>(re, im, tb, t);
    pass4_fwd(re, im, t, g_xh + b * T_N);
}

__global__ void __launch_bounds__(1024, 1)
k_order1(float* __restrict__ out) {
    extern __shared__ float sm[];
    float* re = sm; float* im = sm + NPAD;
    Tabs tb = layout(sm);
    const int j1 = blockIdx.x, b = blockIdx.y, t = threadIdx.x;
    load_tabs(tb, t);
    pass4_inv(re, im, t, g_xh + b * T_N, g_psi1p + j1 * T_N);
    __syncthreads();
    inv3<true>(re, im, tb, t);                          // |ifft| -> re
    lowpass64(re, tb.ph, out + S1_BASE + (b * N1 + j1) * M_OUT);   // S1
    __syncthreads();
    fwd3<true>(re, im, tb, t);
    const int o = j1 >> 3;
    const int oc = o < 3 ? 3 : o;
    const int M_need = 1 << (16 - oc);                  // 8192 .. 512
    pass4_fwd_o1(re, im, t,
                 g_u1h + (size_t)(b * N1 + j1) * T_N,
                 g_u1hn + (size_t)(b * N1 + j1) * 8192,
                 M_need, j1 < 24);
}

// Full-size order-2 path: compact list of j2<=3 pairs.
__global__ void __launch_bounds__(1024, 1)
k_order2(const int* __restrict__ pj1, const int* __restrict__ pj2,
         float* __restrict__ out) {
    const int idx = blockIdx.x;
    const int b = idx / FULL_P;
    const int p = g_fullp[idx - b * FULL_P];
    if (p < 0) return;
    extern __shared__ float sm[];
    float* re = sm; float* im = sm + NPAD;
    Tabs tb = layout(sm);
    const int t = threadIdx.x;
    const int j1 = pj1[p], j2 = pj2[p];
    load_tabs(tb, t);
    pass4_inv(re, im, t, g_u1h + (size_t)(b * N1 + j1) * T_N, g_psi2p + j2 * T_N);
    __syncthreads();
    inv3<true>(re, im, tb, t);
    lowpass64(re, tb.ph, out + S2_BASE + (b * P_N + p) * M_OUT);   // S2
}

// Subband order-2 path (compact list, j2>=4).  M = 2^(17-j2), s' = 2^(j2-3).
__global__ void __launch_bounds__(512, 2)
k_order2_band(const int* __restrict__ pj1, const int* __restrict__ pj2,
              float* __restrict__ out) {
    const int idx = blockIdx.x, tid = threadIdx.x;
    const int b = idx / BAND_P;
    const int p = g_bandp[idx - b * BAND_P];
    if (p < 0) return;
    const int j1 = pj1[p], j2 = pj2[p];
    extern __shared__ float sm[];
    float* re  = sm;            // 9216 floats (padded M <= 8192)
    float* im  = sm + 9216;     // 9216 (reused as natural-order magnitudes)
    float* twx = sm + 18432;    // 1024
    float* twy = sm + 19456;    // 1024
    float* ph  = sm + 20480;    // 513
    const int lgM = 17 - j2;                 // 13..10
    const int M   = 1 << lgM;
    const int lgs = j2 - 3;                  // s' = 2^lgs
    for (int i = tid; i <= W_PHI; i += 512) ph[i] = g_phit[i];
    const int lgMs = lgM - (lgM & 1);        // radix-4 sub-size
    const int tstep = T_N >> lgMs;
    for (int r = tid; r < (1 << (lgMs - 2)); r += 512) {
        float2 w = g_tw[r * tstep]; twx[r] = w.x; twy[r] = w.y;
    }
    // load Y[k] = U1hn[k] * psi2n[k], k < M (natural order, coalesced)
    const float2* uhn = g_u1hn + (size_t)(b * N1 + j1) * 8192;
    const float*  p2  = g_psi2n + (j2 << 13);
    for (int k = tid; k < M; k += 512) {
        float2 u = uhn[k];
        float  w = p2[k];
        int a = padb(k);
        re[a] = u.x * w; im[a] = u.y * w;
    }
    __syncthreads();
    // optional radix-2 first stage (odd log2)
    if (lgM & 1) {
        int H = M >> 1;
        for (int j = tid; j < H; j += 512) {
            int pa = padb(j), pb = padb(j + H);
            float ax = re[pa], ay = im[pa], bx = re[pb], by = im[pb];
            float2 w = g_tw[j << lgs];
            float dx = ax - bx, dy = ay - by;
            re[pa] = ax + bx; im[pa] = ay + by;
            re[pb] = fmaf(dx, w.x,  dy * w.y);
            im[pb] = fmaf(dy, w.x, -dx * w.y);
        }
        __syncthreads();
    }
    // radix-4 DIF inverse stages (bit-reversed output ordering)
    const int lgQ = lgMs - 2;
    for (int lgL = lgQ; lgL >= 0; lgL -= 2) {
        const int L = 1 << lgL;
        const int twsh = lgQ - lgL;
        for (int u = tid; u < (M >> 2); u += 512) {
            int v   = u & ((1 << lgQ) - 1);
            int sub = u >> lgQ;
            int j   = v & (L - 1);
            int blk = v >> lgL;
            int base = (sub << lgMs) + (blk << (lgL + 2)) + j;
            int a0 = padb(base), a1 = padb(base + L);
            int a2 = padb(base + 2 * L), a3 = padb(base + 3 * L);
            float x0r = re[a0], x0i = im[a0], x1r = re[a1], x1i = im[a1];
            float x2r = re[a2], x2i = im[a2], x3r = re[a3], x3i = im[a3];
            float w1x = twx[j << twsh], w1y = twy[j << twsh];
            float w2x = fmaf(w1x, w1x, -w1y * w1y), w2y = 2.f * w1x * w1y;
            float w3x = fmaf(w2x, w1x, -w2y * w1y);
            float w3y = fmaf(w2x, w1y,  w2y * w1x);
            float t0r = x0r + x2r, t0i = x0i + x2i, t1r = x0r - x2r, t1i = x0i - x2i;
            float t2r = x1r + x3r, t2i = x1i + x3i, t4r = x1r - x3r, t4i = x1i - x3i;
            re[a0] = t0r + t2r; im[a0] = t0i + t2i;
            float d1r = t0r - t2r, d1i = t0i - t2i;                  // * conj(w2)
            re[a1] = fmaf(d1r, w2x,  d1i * w2y);
            im[a1] = fmaf(d1i, w2x, -d1r * w2y);
            float c2r = t1r - t4i, c2i = t1i + t4r;                  // (t1+i t4)*conj(w1)
            re[a2] = fmaf(c2r, w1x,  c2i * w1y);
            im[a2] = fmaf(c2i, w1x, -c2r * w1y);
            float c3r = t1r + t4i, c3i = t1i - t4r;                  // (t1-i t4)*conj(w3)
            re[a3] = fmaf(c3r, w3x,  c3i * w3y);
            im[a3] = fmaf(c3i, w3x, -c3r * w3y);
        }
        __syncthreads();
    }
    // modulus in place on re (bitrev order)
    for (int i = tid; i < M; i += 512) {
        int a = padb(i);
        float xr = re[a], xi = im[a];
        re[a] = sqrtf(fmaf(xr, xr, xi * xi));
    }
    __syncthreads();
    // de-bitrev into im with conflict-free padding padq(q) = q + (q >> (lgM-5))
    const int qsh = lgM - 5;
    for (int i = tid; i < M; i += 512) {
        int q = (int)(__brev((unsigned)i) >> (32 - lgM));
        im[q + (q >> qsh)] = re[padb(i)];
    }
    __syncthreads();
    // decimated phi-conv on natural-order magnitudes (conflict-free reads)
    const int lane = tid & 31, warp = tid >> 5;
    const int he = W_PHI >> lgs;
    float* outp = out + S2_BASE + (b * P_N + p) * M_OUT;
    const float fs = (float)(1 << lgs);
    for (int m = warp; m < M_OUT; m += 16) {
        int qc = m << (8 - lgs);
        float acc = 0.f;
        for (int ee = lane; ee <= 2 * he; ee += 32) {
            int e = ee - he;
            int q = (qc - e) & (M - 1);
            int ae = e < 0 ? -e : e;
            acc = fmaf(im[q + (q >> qsh)], ph[ae << lgs], acc);
        }
#pragma unroll
        for (int off = 16; off; off >>= 1)
            acc += __shfl_down_sync(0xffffffffu, acc, off);
        if (lane == 0) outp[m] = acc * fs;
    }
}

// ----------------------- launch --------------------------------------------
extern "C" void kernel_launch(void* const* d_in, const int* in_sizes, int n_in,
                              void* d_out, int out_size) {
    (void)in_sizes; (void)n_in; (void)out_size;
    const float* x    = (const float*)d_in[0];
    const float* psi1 = (const float*)d_in[1];
    const float* psi2 = (const float*)d_in[2];
    const float* phi  = (const float*)d_in[3];
    const int*   pj1  = (const int*)d_in[4];
    const int*   pj2  = (const int*)d_in[5];
    float* out = (float*)d_out;

    cudaFuncSetAttribute(k_xfft,        cudaFuncAttributeMaxDynamicSharedMemorySize, SMEM_BYTES);
    cudaFuncSetAttribute(k_order1,      cudaFuncAttributeMaxDynamicSharedMemorySize, SMEM_BYTES);
    cudaFuncSetAttribute(k_order2,      cudaFuncAttributeMaxDynamicSharedMemorySize, SMEM_BYTES);
    cudaFuncSetAttribute(k_order2_band, cudaFuncAttributeMaxDynamicSharedMemorySize, SMEM_BAND);

    k_init<<<256, 256>>>(psi1, psi2);
    k_lists<<<1, 32>>>(pj2);
    k_phit<<<W_PHI + 1, 256>>>(phi);
    k_xfft<<<B_N, 1024, SMEM_BYTES>>>(x, out);
    dim3 g1(N1, B_N);
    k_order1<<<g1, 1024, SMEM_BYTES>>>(out);
    k_order2<<<B_N * FULL_P, 1024, SMEM_BYTES>>>(pj1, pj2, out);
    k_order2_band<<<B_N * BAND_P, 512, SMEM_BAND>>>(pj1, pj2, out);
}

// round 16
// speedup vs baseline: 2.1608x; 1.0445x over previous
#include <cuda_runtime.h>
#include <math.h>

// ---------------------------------------------------------------------------
// Wavelet scattering, T=16384, B=16, n1=64, n2=8, P=224, stride 256.
//
// R16 = R15 + subband ORDER-1 for j1 >= 32: psi1 support fits in
// M1 = 2^(17-o) bins (o = j1>>3), so U1 is computed by an M1-point inverse
// FFT of xhn*psi1n, S1 by the decimated phi-conv, and U1h bins < M1/2 by a
// forward M1-FFT implemented as conj(inverse-machine(real input)) — reusing
// the exact proven band FFT twice. k_order1 now runs only j1 < 32.
// ---------------------------------------------------------------------------

#define T_N    16384
#define B_N    16
#define N1     64
#define N2     8
#define P_N    224
#define M_OUT  64
#define W_PHI  512
#define NPAD   (T_N + 1024)           // padded float array length (i + 4*(i>>6))
#define TW_F2  (4 * (1024 + 64 + 4))  // 4368 float2 of twiddle tables
#define SMEM_BYTES ((2 * NPAD) * 4 + TW_F2 * 8 + (W_PHI + 4) * 4)
#define SMEM_BAND  84000
#define FULL_P 48
#define BAND_P 176

#define S1_BASE 1024
#define S2_BASE 66560

// ----------------------- device scratch ------------------------------------
static __device__ float2 g_xh[B_N * T_N];                     // permuted
static __device__ float2 g_xhn[B_N * 8192];                   // natural low bins of xh
static __device__ float2 g_u1h[(size_t)B_N * N1 * T_N];       // permuted (j1<24 used)
static __device__ float2 g_u1hn[(size_t)B_N * N1 * 8192];     // natural low bins
static __device__ float  g_psi1p[N1 * T_N];                   // permuted, /N
static __device__ float  g_psi1n[32 * 8192];                  // natural, /N (j1>=32, k<8192)
static __device__ float  g_psi2p[N2 * T_N];                   // permuted, /N
static __device__ float  g_psi2n[N2 * 8192];                  // natural, /N (k<8192)
static __device__ float2 g_tw[T_N];                           // e^{-2pi i k/N}
static __device__ float  g_phit[W_PHI + 1];
static __device__ int    g_fullp[FULL_P];
static __device__ int    g_bandp[BAND_P];

// ----------------------- helpers -------------------------------------------
__device__ __forceinline__ int adr(int i)  { return i + ((i >> 6) << 2); }
__device__ __forceinline__ int padb(int i) { return i + ((i >> 5) << 2); }

__device__ __forceinline__ float2 cmul(float2 a, float2 b) {
    return make_float2(fmaf(a.x, b.x, -a.y * b.y),
                       fmaf(a.x, b.y,  a.y * b.x));
}
// a * conj(b)
__device__ __forceinline__ float2 cmulc(float2 a, float2 b) {
    return make_float2(fmaf(a.x, b.x,  a.y * b.y),
                       fmaf(a.y, b.x, -a.x * b.y));
}

__device__ __forceinline__ float2 twf(float2 z, float c, float s) {
    return make_float2(fmaf(z.x, c,  z.y * s), fmaf(z.y, c, -z.x * s));
}
__device__ __forceinline__ float2 twi(float2 z, float c, float s) {
    return make_float2(fmaf(z.x, c, -z.y * s), fmaf(z.y, c,  z.x * s));
}

__device__ __forceinline__ void r4f(float2& A, float2& B, float2& C, float2& D) {
    float t0x = A.x + C.x, t0y = A.y + C.y, t1x = A.x - C.x, t1y = A.y - C.y;
    float t2x = B.x + D.x, t2y = B.y + D.y, t3x = B.x - D.x, t3y = B.y - D.y;
    A.x = t0x + t2x; A.y = t0y + t2y;  C.x = t0x - t2x; C.y = t0y - t2y;
    B.x = t1x + t3y; B.y = t1y - t3x;  D.x = t1x - t3y; D.y = t1y + t3x;
}
__device__ __forceinline__ void r4i(float2& A, float2& B, float2& C, float2& D) {
    float t0x = A.x + C.x, t0y = A.y + C.y, t1x = A.x - C.x, t1y = A.y - C.y;
    float t2x = B.x + D.x, t2y = B.y + D.y, t3x = B.x - D.x, t3y = B.y - D.y;
    A.x = t0x + t2x; A.y = t0y + t2y;  C.x = t0x - t2x; C.y = t0y - t2y;
    B.x = t1x - t3y; B.y = t1y + t3x;  D.x = t1x + t3y; D.y = t1y - t3x;
}

#define C16_1 0.9238795325112867f
#define S16_1 0.3826834323650898f
#define RSQ2  0.7071067811865476f

__device__ __forceinline__ void dft16f(float2 a[16]) {
    r4f(a[0], a[4], a[8], a[12]); r4f(a[1], a[5], a[9], a[13]);
    r4f(a[2], a[6], a[10], a[14]); r4f(a[3], a[7], a[11], a[15]);
    a[5]  = twf(a[5],  C16_1,  S16_1);
    a[9]  = twf(a[9],  RSQ2,   RSQ2);
    a[13] = twf(a[13], S16_1,  C16_1);
    a[6]  = twf(a[6],  RSQ2,   RSQ2);
    a[10] = make_float2(a[10].y, -a[10].x);
    a[14] = twf(a[14], -RSQ2,   RSQ2);
    a[7]  = twf(a[7],  S16_1,  C16_1);
    a[11] = twf(a[11], -RSQ2,   RSQ2);
    a[15] = twf(a[15], -C16_1, -S16_1);
    r4f(a[0], a[1], a[2], a[3]);   r4f(a[4], a[5], a[6], a[7]);
    r4f(a[8], a[9], a[10], a[11]); r4f(a[12], a[13], a[14], a[15]);
}
__device__ __forceinline__ void dft16i(float2 a[16]) {
    r4i(a[0], a[4], a[8], a[12]); r4i(a[1], a[5], a[9], a[13]);
    r4i(a[2], a[6], a[10], a[14]); r4i(a[3], a[7], a[11], a[15]);
    a[5]  = twi(a[5],  C16_1,  S16_1);
    a[9]  = twi(a[9],  RSQ2,   RSQ2);
    a[13] = twi(a[13], S16_1,  C16_1);
    a[6]  = twi(a[6],  RSQ2,   RSQ2);
    a[10] = make_float2(-a[10].y, a[10].x);
    a[14] = twi(a[14], -RSQ2,   RSQ2);
    a[7]  = twi(a[7],  S16_1,  C16_1);
    a[11] = twi(a[11], -RSQ2,   RSQ2);
    a[15] = twi(a[15], -C16_1, -S16_1);
    r4i(a[0], a[1], a[2], a[3]);   r4i(a[4], a[5], a[6], a[7]);
    r4i(a[8], a[9], a[10], a[11]); r4i(a[12], a[13], a[14], a[15]);
}

__device__ __forceinline__ float2 twpow_f(float2 v, int r, float2 w1, float2 w2,
                                          float2 w4, float2 w8) {
    if (r & 1) v = cmul(v, w1);
    if (r & 2) v = cmul(v, w2);
    if (r & 4) v = cmul(v, w4);
    if (r & 8) v = cmul(v, w8);
    return v;
}
__device__ __forceinline__ float2 twpow_i(float2 v, int r, float2 w1, float2 w2,
                                          float2 w4, float2 w8) {
    if (r & 1) v = cmulc(v, w1);
    if (r & 2) v = cmulc(v, w2);
    if (r & 4) v = cmulc(v, w4);
    if (r & 8) v = cmulc(v, w8);
    return v;
}

template<bool REAL>
__device__ __forceinline__ void bf16_fwd(float* __restrict__ re, float* __restrict__ im,
                                         int bp, int stride,
                                         float2 w1, float2 w2, float2 w4, float2 w8) {
    float2 a[16];
#pragma unroll
    for (int m = 0; m < 16; m++) {
        int A_ = adr(bp + stride * m);
        a[m] = make_float2(re[A_], REAL ? 0.f : im[A_]);
    }
    dft16f(a);
    { int A_ = adr(bp); re[A_] = a[0].x; im[A_] = a[0].y; }
#pragma unroll
    for (int r = 1; r < 16; r++) {
        int p = ((r & 3) << 2) | (r >> 2);
        float2 v = twpow_f(a[p], r, w1, w2, w4, w8);
        int A_ = adr(bp + stride * r);
        re[A_] = v.x; im[A_] = v.y;
    }
}

template<bool ABS>
__device__ __forceinline__ void bf16_inv(float* __restrict__ re, float* __restrict__ im,
                                         int bp, int stride,
                                         float2 w1, float2 w2, float2 w4, float2 w8) {
    float2 a[16];
#pragma unroll
    for (int r = 0; r < 16; r++) {
        int A_ = adr(bp + stride * r);
        a[r] = make_float2(re[A_], im[A_]);
    }
#pragma unroll
    for (int r = 1; r < 16; r++)
        a[r] = twpow_i(a[r], r, w1, w2, w4, w8);
    dft16i(a);
#pragma unroll
    for (int m = 0; m < 16; m++) {
        int p = ((m & 3) << 2) | (m >> 2);
        int A_ = adr(bp + stride * m);
        if (ABS) {
            re[A_] = sqrtf(fmaf(a[p].x, a[p].x, a[p].y * a[p].y));
        } else {
            re[A_] = a[p].x; im[A_] = a[p].y;
        }
    }
}

// Final forward radix-4 stage: shared -> gmem permuted.
__device__ __forceinline__ void pass4_fwd(const float* __restrict__ re,
                                          const float* __restrict__ im,
                                          int t, float2* __restrict__ dst) {
#pragma unroll
    for (int h = 0; h < 4; h++) {
        int i0 = 4 * (t + 1024 * h);
        int A0 = adr(i0);
        float4 rr = *(const float4*)(re + A0);
        float4 ii = *(const float4*)(im + A0);
        float2 A = make_float2(rr.x, ii.x), B = make_float2(rr.y, ii.y);
        float2 C = make_float2(rr.z, ii.z), D = make_float2(rr.w, ii.w);
        r4f(A, B, C, D);
        float4* dp = (float4*)(dst + i0);
        dp[0] = make_float4(A.x, A.y, B.x, B.y);
        dp[1] = make_float4(C.x, C.y, D.x, D.y);
    }
}

// Permuted store + natural-order store of bins < M_need (bins b0 and
// b0+4096 are the only outputs < 8192).
__device__ __forceinline__ void pass4_fwd_o1(const float* __restrict__ re,
                                             const float* __restrict__ im,
                                             int t, float2* __restrict__ dst,
                                             float2* __restrict__ nat,
                                             int M_need, bool write_perm) {
#pragma unroll
    for (int h = 0; h < 4; h++) {
        int u  = t + 1024 * h;
        int i0 = 4 * u;
        int A0 = adr(i0);
        float4 rr = *(const float4*)(re + A0);
        float4 ii = *(const float4*)(im + A0);
        float2 A = make_float2(rr.x, ii.x), B = make_float2(rr.y, ii.y);
        float2 C = make_float2(rr.z, ii.z), D = make_float2(rr.w, ii.w);
        r4f(A, B, C, D);
        if (write_perm) {
            float4* dp = (float4*)(dst + i0);
            dp[0] = make_float4(A.x, A.y, B.x, B.y);
            dp[1] = make_float4(C.x, C.y, D.x, D.y);
        }
        int b0 = ((u & 15) << 8) | (((u >> 4) & 15) << 4) | (u >> 8);
        if (b0 < M_need) nat[b0] = A;
        int b1 = b0 + 4096;
        if (b1 < M_need) nat[b1] = B;
    }
}

// Entry inverse radix-4 stage: gmem * psi -> shared, no twiddles.
__device__ __forceinline__ void pass4_inv(float* __restrict__ re, float* __restrict__ im,
                                          int t, const float2* __restrict__ src,
                                          const float* __restrict__ psi) {
#pragma unroll
    for (int h = 0; h < 4; h++) {
        int i0 = 4 * (t + 1024 * h);
        const float4* sp = (const float4*)(src + i0);
        float4 v1 = sp[0], v2 = sp[1];
        float4 p4 = *(const float4*)(psi + i0);
        float2 A = make_float2(v1.x * p4.x, v1.y * p4.x);
        float2 B = make_float2(v1.z * p4.y, v1.w * p4.y);
        float2 C = make_float2(v2.x * p4.z, v2.y * p4.z);
        float2 D = make_float2(v2.z * p4.w, v2.w * p4.w);
        r4i(A, B, C, D);
        int A0 = adr(i0);
        *(float4*)(re + A0) = make_float4(A.x, B.x, C.x, D.x);
        *(float4*)(im + A0) = make_float4(A.y, B.y, C.y, D.y);
    }
}

struct Tabs {
    float2 *s1w1, *s1w2, *s1w4, *s1w8;
    float2 *s2w1, *s2w2, *s2w4, *s2w8;
    float2 *s3w1, *s3w2, *s3w4, *s3w8;
    float  *ph;
};

__device__ __forceinline__ Tabs layout(float* sm) {
    Tabs tb;
    float2* p = (float2*)(sm + 2 * NPAD);
    tb.s1w1 = p;        tb.s1w2 = p + 1024; tb.s1w4 = p + 2048; tb.s1w8 = p + 3072;
    p += 4096;
    tb.s2w1 = p;        tb.s2w2 = p + 64;   tb.s2w4 = p + 128;  tb.s2w8 = p + 192;
    p += 256;
    tb.s3w1 = p;        tb.s3w2 = p + 4;    tb.s3w4 = p + 8;    tb.s3w8 = p + 12;
    p += 16;
    tb.ph = (float*)p;
    return tb;
}

__device__ __forceinline__ void load_tabs(Tabs tb, int t) {
    if (t < 1024) {
        tb.s1w1[t] = g_tw[t];
        tb.s1w2[t] = g_tw[2 * t];
        tb.s1w4[t] = g_tw[4 * t];
        tb.s1w8[t] = g_tw[8 * t];
    }
    if (t < 64) {
        tb.s2w1[t] = g_tw[16 * t];
        tb.s2w2[t] = g_tw[32 * t];
        tb.s2w4[t] = g_tw[64 * t];
        tb.s2w8[t] = g_tw[128 * t];
    }
    if (t < 4) {
        tb.s3w1[t] = g_tw[256 * t];
        tb.s3w2[t] = g_tw[512 * t];
        tb.s3w4[t] = g_tw[1024 * t];
        tb.s3w8[t] = g_tw[2048 * t];
    }
    for (int i = t; i <= W_PHI; i += 1024) tb.ph[i] = g_phit[i];
}

template<bool REAL_IN>
__device__ __forceinline__ void fwd3(float* re, float* im, Tabs tb, int t) {
    bf16_fwd<REAL_IN>(re, im, t, 1024,
                      tb.s1w1[t], tb.s1w2[t], tb.s1w4[t], tb.s1w8[t]);
    __syncthreads();
    { int j = t & 63;
      bf16_fwd<false>(re, im, ((t >> 6) << 10) + j, 64,
                      tb.s2w1[j], tb.s2w2[j], tb.s2w4[j], tb.s2w8[j]); }
    __syncthreads();
    { int j = t & 3;
      bf16_fwd<false>(re, im, ((t >> 2) << 6) + j, 4,
                      tb.s3w1[j], tb.s3w2[j], tb.s3w4[j], tb.s3w8[j]); }
    __syncthreads();
}

template<bool ABS>
__device__ __forceinline__ void inv3(float* re, float* im, Tabs tb, int t) {
    { int j = t & 3;
      bf16_inv<false>(re, im, ((t >> 2) << 6) + j, 4,
                      tb.s3w1[j], tb.s3w2[j], tb.s3w4[j], tb.s3w8[j]); }
    __syncthreads();
    { int j = t & 63;
      bf16_inv<false>(re, im, ((t >> 6) << 10) + j, 64,
                      tb.s2w1[j], tb.s2w2[j], tb.s2w4[j], tb.s2w8[j]); }
    __syncthreads();
    bf16_inv<ABS>(re, im, t, 1024,
                  tb.s1w1[t], tb.s1w2[t], tb.s1w4[t], tb.s1w8[t]);
    __syncthreads();
}

__device__ __forceinline__ void lowpass64(const float* __restrict__ re,
                                          const float* __restrict__ ph,
                                          float* __restrict__ outp) {
    const int lane = threadIdx.x & 31;
    const int warp = threadIdx.x >> 5;
    for (int m = warp; m < M_OUT; m += 32) {
        const int t0 = m << 8;
        float acc = 0.f;
        for (int dd = lane; dd <= 2 * W_PHI; dd += 32) {
            const int d   = dd - W_PHI;
            const int ad  = d < 0 ? -d : d;
            const int idx = (t0 - d + T_N) & (T_N - 1);
            acc = fmaf(re[adr(idx)], ph[ad], acc);
        }
#pragma unroll
        for (int off = 16; off; off >>= 1)
            acc += __shfl_down_sync(0xffffffffu, acc, off);
        if (lane == 0) outp[m] = acc;
    }
}

// Generic M-point inverse FFT machine on padded SoA shared arrays.
// Natural input -> bit-reversed output. (Used as forward FFT via conjugation
// for real inputs.) 512 threads.
__device__ void band_inv_fft(float* __restrict__ re, float* __restrict__ im,
                             const float* __restrict__ twx,
                             const float* __restrict__ twy,
                             int lgM, int lgs, int tid) {
    const int M = 1 << lgM;
    if (lgM & 1) {
        int H = M >> 1;
        for (int j = tid; j < H; j += 512) {
            int pa = padb(j), pb = padb(j + H);
            float ax = re[pa], ay = im[pa], bx = re[pb], by = im[pb];
            float2 w = g_tw[j << lgs];
            float dx = ax - bx, dy = ay - by;
            re[pa] = ax + bx; im[pa] = ay + by;
            re[pb] = fmaf(dx, w.x,  dy * w.y);
            im[pb] = fmaf(dy, w.x, -dx * w.y);
        }
        __syncthreads();
    }
    const int lgMs = lgM - (lgM & 1);
    const int lgQ = lgMs - 2;
    for (int lgL = lgQ; lgL >= 0; lgL -= 2) {
        const int L = 1 << lgL;
        const int twsh = lgQ - lgL;
        for (int u = tid; u < (M >> 2); u += 512) {
            int v   = u & ((1 << lgQ) - 1);
            int sub = u >> lgQ;
            int j   = v & (L - 1);
            int blk = v >> lgL;
            int base = (sub << lgMs) + (blk << (lgL + 2)) + j;
            int a0 = padb(base), a1 = padb(base + L);
            int a2 = padb(base + 2 * L), a3 = padb(base + 3 * L);
            float x0r = re[a0], x0i = im[a0], x1r = re[a1], x1i = im[a1];
            float x2r = re[a2], x2i = im[a2], x3r = re[a3], x3i = im[a3];
            float w1x = twx[j << twsh], w1y = twy[j << twsh];
            float w2x = fmaf(w1x, w1x, -w1y * w1y), w2y = 2.f * w1x * w1y;
            float w3x = fmaf(w2x, w1x, -w2y * w1y);
            float w3y = fmaf(w2x, w1y,  w2y * w1x);
            float t0r = x0r + x2r, t0i = x0i + x2i, t1r = x0r - x2r, t1i = x0i - x2i;
            float t2r = x1r + x3r, t2i = x1i + x3i, t4r = x1r - x3r, t4i = x1i - x3i;
            re[a0] = t0r + t2r; im[a0] = t0i + t2i;
            float d1r = t0r - t2r, d1i = t0i - t2i;                  // * conj(w2)
            re[a1] = fmaf(d1r, w2x,  d1i * w2y);
            im[a1] = fmaf(d1i, w2x, -d1r * w2y);
            float c2r = t1r - t4i, c2i = t1i + t4r;                  // (t1+i t4)*conj(w1)
            re[a2] = fmaf(c2r, w1x,  c2i * w1y);
            im[a2] = fmaf(c2i, w1x, -c2r * w1y);
            float c3r = t1r + t4i, c3i = t1i - t4r;                  // (t1-i t4)*conj(w3)
            re[a3] = fmaf(c3r, w3x,  c3i * w3y);
            im[a3] = fmaf(c3i, w3x, -c3r * w3y);
        }
        __syncthreads();
    }
}

// Shared prologue for band kernels: phi + stage-twiddle tables.
__device__ __forceinline__ void band_tabs(float* twx, float* twy, float* ph,
                                          int lgM, int tid) {
    for (int i = tid; i <= W_PHI; i += 512) ph[i] = g_phit[i];
    const int lgMs = lgM - (lgM & 1);
    const int tstep = T_N >> lgMs;
    for (int r = tid; r < (1 << (lgMs - 2)); r += 512) {
        float2 w = g_tw[r * tstep]; twx[r] = w.x; twy[r] = w.y;
    }
}

// Decimated phi-conv over natural-order (qsh-padded) magnitudes.
__device__ __forceinline__ void band_conv(const float* __restrict__ nat,
                                          const float* __restrict__ ph,
                                          int lgM, int lgs, int qsh, int tid,
                                          float* __restrict__ outp) {
    const int M = 1 << lgM;
    const int lane = tid & 31, warp = tid >> 5;
    const int he = W_PHI >> lgs;
    const float fs = (float)(1 << lgs);
    for (int m = warp; m < M_OUT; m += 16) {
        int qc = m << (8 - lgs);
        float acc = 0.f;
        for (int ee = lane; ee <= 2 * he; ee += 32) {
            int e = ee - he;
            int q = (qc - e) & (M - 1);
            int ae = e < 0 ? -e : e;
            acc = fmaf(nat[q + (q >> qsh)], ph[ae << lgs], acc);
        }
#pragma unroll
        for (int off = 16; off; off >>= 1)
            acc += __shfl_down_sync(0xffffffffu, acc, off);
        if (lane == 0) outp[m] = acc * fs;
    }
}

// ----------------------- init kernels ---------------------------------------
__device__ __forceinline__ int posrm(int k) {
    return ((k & 15) << 10) | (((k >> 4) & 15) << 6) | (((k >> 8) & 15) << 2) | (k >> 12);
}

__global__ void k_init(const float* __restrict__ psi1, const float* __restrict__ psi2) {
    const float invN = 1.0f / (float)T_N;
    const int total = N1 * T_N;
    for (int i = blockIdx.x * blockDim.x + threadIdx.x; i < total;
         i += gridDim.x * blockDim.x) {
        const int k = i & (T_N - 1);
        const int j = i >> 14;
        const int pos = posrm(k);
        g_psi1p[(j << 14) + pos] = psi1[i] * invN;
        if (j >= 32 && k < 8192) g_psi1n[((j - 32) << 13) + k] = psi1[i] * invN;
        if (j < N2) {
            g_psi2p[(j << 14) + pos] = psi2[i] * invN;
            if (k < 8192) g_psi2n[(j << 13) + k] = psi2[i] * invN;
        }
        if (j == 0) {
            float sn, cn;
            sincospif(-2.0f * (float)k / (float)T_N, &sn, &cn);
            g_tw[k] = make_float2(cn, sn);
        }
    }
}

__global__ void k_lists(const int* __restrict__ pj2) {
    if (blockIdx.x == 0 && threadIdx.x == 0) {
        int nf = 0, nb = 0;
        for (int i = 0; i < FULL_P; i++) g_fullp[i] = -1;
        for (int i = 0; i < BAND_P; i++) g_bandp[i] = -1;
        for (int p = 0; p < P_N; p++)
            if (pj2[p] < 4 && nf < FULL_P) g_fullp[nf++] = p;
        for (int j2v = 4; j2v <= 7; j2v++)
            for (int p = 0; p < P_N; p++)
                if (pj2[p] == j2v && nb < BAND_P) g_bandp[nb++] = p;
    }
}

__global__ void k_phit(const float* __restrict__ phi) {
    __shared__ float red[256];
    const int n = blockIdx.x;   // 0..W_PHI
    float acc = 0.f;
    for (int k = threadIdx.x; k < 1024; k += blockDim.x) {
        float coef = (k == 0) ? phi[0] : 2.f * phi[k];
        acc = fmaf(coef, g_tw[(k * n) & (T_N - 1)].x, acc);
    }
    red[threadIdx.x] = acc;
    __syncthreads();
    for (int off = 128; off; off >>= 1) {
        if (threadIdx.x < off) red[threadIdx.x] += red[threadIdx.x + off];
        __syncthreads();
    }
    if (threadIdx.x == 0) g_phit[n] = red[0] * (1.0f / (float)T_N);
}

// ----------------------- main kernels ---------------------------------------
__global__ void __launch_bounds__(1024, 1)
k_xfft(const float* __restrict__ x, float* __restrict__ out) {
    extern __shared__ float sm[];
    float* re = sm; float* im = sm + NPAD;
    Tabs tb = layout(sm);
    const int b = blockIdx.x, t = threadIdx.x;
    load_tabs(tb, t);
    const float* xb = x + b * T_N;
    for (int i = t; i < T_N; i += 1024) re[adr(i)] = xb[i];
    __syncthreads();
    lowpass64(re, tb.ph, out + b * M_OUT);              // S0
    __syncthreads();
    fwd3<true>(re, im, tb, t);
    pass4_fwd_o1(re, im, t, g_xh + b * T_N, g_xhn + b * 8192, 8192, true);
}

// Full-size order-1: j1 < 32 only.
__global__ void __launch_bounds__(1024, 1)
k_order1(float* __restrict__ out) {
    extern __shared__ float sm[];
    float* re = sm; float* im = sm + NPAD;
    Tabs tb = layout(sm);
    const int j1 = blockIdx.x, b = blockIdx.y, t = threadIdx.x;
    load_tabs(tb, t);
    pass4_inv(re, im, t, g_xh + b * T_N, g_psi1p + j1 * T_N);
    __syncthreads();
    inv3<true>(re, im, tb, t);                          // |ifft| -> re
    lowpass64(re, tb.ph, out + S1_BASE + (b * N1 + j1) * M_OUT);   // S1
    __syncthreads();
    fwd3<true>(re, im, tb, t);
    pass4_fwd_o1(re, im, t,
                 g_u1h + (size_t)(b * N1 + j1) * T_N,
                 g_u1hn + (size_t)(b * N1 + j1) * 8192,
                 8192, j1 < 24);
}

// Subband order-1: j1 >= 32.  M = 2^(17-o), s = 2^(o-3), o = j1>>3.
__global__ void __launch_bounds__(512, 2)
k_order1_band(float* __restrict__ out) {
    const int j1 = 32 + blockIdx.x;
    const int b  = blockIdx.y;
    const int tid = threadIdx.x;
    extern __shared__ float sm[];
    float* re  = sm;            // 9216
    float* im  = sm + 9216;     // 9216
    float* twx = sm + 18432;    // 1024
    float* twy = sm + 19456;    // 1024
    float* ph  = sm + 20480;    // 513
    const int o   = j1 >> 3;                 // 4..7
    const int lgM = 17 - o;                  // 13..10
    const int M   = 1 << lgM;
    const int lgs = o - 3;                   // 1..4
    band_tabs(twx, twy, ph, lgM, tid);
    // Y[k] = xhn[k] * psi1n[k], k < M (natural, coalesced)
    const float2* xhn = g_xhn + b * 8192;
    const float*  p1  = g_psi1n + ((j1 - 32) << 13);
    for (int k = tid; k < M; k += 512) {
        float2 u = xhn[k];
        float  w = p1[k];
        int a = padb(k);
        re[a] = u.x * w; im[a] = u.y * w;
    }
    __syncthreads();
    band_inv_fft(re, im, twx, twy, lgM, lgs, tid);      // U1 decimated, bitrev
    // modulus (bitrev order)
    for (int i = tid; i < M; i += 512) {
        int a = padb(i);
        float xr = re[a], xi = im[a];
        re[a] = sqrtf(fmaf(xr, xr, xi * xi));
    }
    __syncthreads();
    // de-bitrev magnitudes into im (natural, qsh padding)
    const int qsh = lgM - 5;
    for (int i = tid; i < M; i += 512) {
        int q = (int)(__brev((unsigned)i) >> (32 - lgM));
        im[q + (q >> qsh)] = re[padb(i)];
    }
    __syncthreads();
    band_conv(im, ph, lgM, lgs, qsh, tid,
              out + S1_BASE + (b * N1 + j1) * M_OUT);   // S1
    __syncthreads();
    // repack natural mags as real input for the forward FFT
    for (int k = tid; k < M; k += 512) re[padb(k)] = im[k + (k >> qsh)];
    __syncthreads();
    for (int k = tid; k < M; k += 512) im[padb(k)] = 0.f;
    __syncthreads();
    // forward FFT of real input = conj(inverse machine)
    band_inv_fft(re, im, twx, twy, lgM, lgs, tid);
    // U1h[k] ~= s * conj(V[k]) for k < M/2 (all any consumer needs)
    const int Mh = M >> 1;
    const float fs = (float)(1 << lgs);
    float2* dst = g_u1hn + (size_t)(b * N1 + j1) * 8192;
    for (int i = tid; i < M; i += 512) {
        int q = (int)(__brev((unsigned)i) >> (32 - lgM));
        if (q < Mh) {
            int a = padb(i);
            dst[q] = make_float2(fs * re[a], -fs * im[a]);
        }
    }
}

// Full-size order-2 path: compact list of j2<=3 pairs (all have j1<24).
__global__ void __launch_bounds__(1024, 1)
k_order2(const int* __restrict__ pj1, const int* __restrict__ pj2,
         float* __restrict__ out) {
    const int idx = blockIdx.x;
    const int b = idx / FULL_P;
    const int p = g_fullp[idx - b * FULL_P];
    if (p < 0) return;
    extern __shared__ float sm[];
    float* re = sm; float* im = sm + NPAD;
    Tabs tb = layout(sm);
    const int t = threadIdx.x;
    const int j1 = pj1[p], j2 = pj2[p];
    load_tabs(tb, t);
    pass4_inv(re, im, t, g_u1h + (size_t)(b * N1 + j1) * T_N, g_psi2p + j2 * T_N);
    __syncthreads();
    inv3<true>(re, im, tb, t);
    lowpass64(re, tb.ph, out + S2_BASE + (b * P_N + p) * M_OUT);   // S2
}

// Subband order-2 path (compact list, j2>=4).  M = 2^(17-j2), s' = 2^(j2-3).
__global__ void __launch_bounds__(512, 2)
k_order2_band(const int* __restrict__ pj1, const int* __restrict__ pj2,
              float* __restrict__ out) {
    const int idx = blockIdx.x, tid = threadIdx.x;
    const int b = idx / BAND_P;
    const int p = g_bandp[idx - b * BAND_P];
    if (p < 0) return;
    const int j1 = pj1[p], j2 = pj2[p];
    extern __shared__ float sm[];
    float* re  = sm;
    float* im  = sm + 9216;
    float* twx = sm + 18432;
    float* twy = sm + 19456;
    float* ph  = sm + 20480;
    const int lgM = 17 - j2;                 // 13..10
    const int M   = 1 << lgM;
    const int lgs = j2 - 3;
    band_tabs(twx, twy, ph, lgM, tid);
    const float2* uhn = g_u1hn + (size_t)(b * N1 + j1) * 8192;
    const float*  p2  = g_psi2n + (j2 << 13);
    for (int k = tid; k < M; k += 512) {
        float2 u = uhn[k];
        float  w = p2[k];
        int a = padb(k);
        re[a] = u.x * w; im[a] = u.y * w;
    }
    __syncthreads();
    band_inv_fft(re, im, twx, twy, lgM, lgs, tid);
    for (int i = tid; i < M; i += 512) {
        int a = padb(i);
        float xr = re[a], xi = im[a];
        re[a] = sqrtf(fmaf(xr, xr, xi * xi));
    }
    __syncthreads();
    const int qsh = lgM - 5;
    for (int i = tid; i < M; i += 512) {
        int q = (int)(__brev((unsigned)i) >> (32 - lgM));
        im[q + (q >> qsh)] = re[padb(i)];
    }
    __syncthreads();
    band_conv(im, ph, lgM, lgs, qsh, tid,
              out + S2_BASE + (b * P_N + p) * M_OUT);   // S2
}

// ----------------------- launch --------------------------------------------
extern "C" void kernel_launch(void* const* d_in, const int* in_sizes, int n_in,
                              void* d_out, int out_size) {
    (void)in_sizes; (void)n_in; (void)out_size;
    const float* x    = (const float*)d_in[0];
    const float* psi1 = (const float*)d_in[1];
    const float* psi2 = (const float*)d_in[2];
    const float* phi  = (const float*)d_in[3];
    const int*   pj1  = (const int*)d_in[4];
    const int*   pj2  = (const int*)d_in[5];
    float* out = (float*)d_out;

    cudaFuncSetAttribute(k_xfft,        cudaFuncAttributeMaxDynamicSharedMemorySize, SMEM_BYTES);
    cudaFuncSetAttribute(k_order1,      cudaFuncAttributeMaxDynamicSharedMemorySize, SMEM_BYTES);
    cudaFuncSetAttribute(k_order1_band, cudaFuncAttributeMaxDynamicSharedMemorySize, SMEM_BAND);
    cudaFuncSetAttribute(k_order2,      cudaFuncAttributeMaxDynamicSharedMemorySize, SMEM_BYTES);
    cudaFuncSetAttribute(k_order2_band, cudaFuncAttributeMaxDynamicSharedMemorySize, SMEM_BAND);

    k_init<<<256, 256>>>(psi1, psi2);
    k_lists<<<1, 32>>>(pj2);
    k_phit<<<W_PHI + 1, 256>>>(phi);
    k_xfft<<<B_N, 1024, SMEM_BYTES>>>(x, out);
    dim3 g1(32, B_N);
    k_order1<<<g1, 1024, SMEM_BYTES>>>(out);
    k_order1_band<<<g1, 512, SMEM_BAND>>>(out);
    k_order2<<<B_N * FULL_P, 1024, SMEM_BYTES>>>(pj1, pj2, out);
    k_order2_band<<<B_N * BAND_P, 512, SMEM_BAND>>>(pj1, pj2, out);
}

// round 17
// speedup vs baseline: 2.5197x; 1.1661x over previous
#include <cuda_runtime.h>
#include <math.h>

// ---------------------------------------------------------------------------
// Wavelet scattering, T=16384, B=16, n1=64, n2=8, P=224, stride 256.
//
// R17: band sizes re-derived from the measured aliasing law (ratio>=45.7
// safe, 22.9 => ~5e-4/pair):
//  * order-1 band j1>=24, M1 = 2^(15-o) (4x smaller than R16), full order-1
//    only j1<24; j1>=56 skip the U1h forward (no consumers); permuted U1h
//    written only for j1<16.
//  * order-2: j2=3 moves to the band path at M=8192 (ratio 22.9); full path
//    only j2<=2. Band input capped at avail(j1)=2^(14-o) with zero-fill.
// ---------------------------------------------------------------------------

#define T_N    16384
#define B_N    16
#define N1     64
#define N2     8
#define P_N    224
#define M_OUT  64
#define W_PHI  512
#define NPAD   (T_N + 1024)
#define TW_F2  (4 * (1024 + 64 + 4))
#define SMEM_BYTES ((2 * NPAD) * 4 + TW_F2 * 8 + (W_PHI + 4) * 4)
#define SMEM_BAND  84000
#define FULL_P 24
#define BAND_P 200

#define S1_BASE 1024
#define S2_BASE 66560

// ----------------------- device scratch ------------------------------------
static __device__ float2 g_xh[B_N * T_N];                     // permuted
static __device__ float2 g_xhn[B_N * 8192];                   // natural low bins of xh
static __device__ float2 g_u1h[(size_t)B_N * N1 * T_N];       // permuted (j1<16 used)
static __device__ float2 g_u1hn[(size_t)B_N * N1 * 8192];     // natural low bins
static __device__ float  g_psi1p[N1 * T_N];                   // permuted, /N
static __device__ float  g_psi1n[40 * 8192];                  // natural, /N (j1>=24)
static __device__ float  g_psi2p[N2 * T_N];                   // permuted, /N
static __device__ float  g_psi2n[N2 * 8192];                  // natural, /N (k<8192)
static __device__ float2 g_tw[T_N];                           // e^{-2pi i k/N}
static __device__ float  g_phit[W_PHI + 1];
static __device__ int    g_fullp[FULL_P];
static __device__ int    g_bandp[BAND_P];

// ----------------------- helpers -------------------------------------------
__device__ __forceinline__ int adr(int i)  { return i + ((i >> 6) << 2); }
__device__ __forceinline__ int padb(int i) { return i + ((i >> 5) << 2); }

__device__ __forceinline__ float2 cmul(float2 a, float2 b) {
    return make_float2(fmaf(a.x, b.x, -a.y * b.y),
                       fmaf(a.x, b.y,  a.y * b.x));
}
__device__ __forceinline__ float2 cmulc(float2 a, float2 b) {
    return make_float2(fmaf(a.x, b.x,  a.y * b.y),
                       fmaf(a.y, b.x, -a.x * b.y));
}

__device__ __forceinline__ float2 twf(float2 z, float c, float s) {
    return make_float2(fmaf(z.x, c,  z.y * s), fmaf(z.y, c, -z.x * s));
}
__device__ __forceinline__ float2 twi(float2 z, float c, float s) {
    return make_float2(fmaf(z.x, c, -z.y * s), fmaf(z.y, c,  z.x * s));
}

__device__ __forceinline__ void r4f(float2& A, float2& B, float2& C, float2& D) {
    float t0x = A.x + C.x, t0y = A.y + C.y, t1x = A.x - C.x, t1y = A.y - C.y;
    float t2x = B.x + D.x, t2y = B.y + D.y, t3x = B.x - D.x, t3y = B.y - D.y;
    A.x = t0x + t2x; A.y = t0y + t2y;  C.x = t0x - t2x; C.y = t0y - t2y;
    B.x = t1x + t3y; B.y = t1y - t3x;  D.x = t1x - t3y; D.y = t1y + t3x;
}
__device__ __forceinline__ void r4i(float2& A, float2& B, float2& C, float2& D) {
    float t0x = A.x + C.x, t0y = A.y + C.y, t1x = A.x - C.x, t1y = A.y - C.y;
    float t2x = B.x + D.x, t2y = B.y + D.y, t3x = B.x - D.x, t3y = B.y - D.y;
    A.x = t0x + t2x; A.y = t0y + t2y;  C.x = t0x - t2x; C.y = t0y - t2y;
    B.x = t1x - t3y; B.y = t1y + t3x;  D.x = t1x + t3y; D.y = t1y - t3x;
}

#define C16_1 0.9238795325112867f
#define S16_1 0.3826834323650898f
#define RSQ2  0.7071067811865476f

__device__ __forceinline__ void dft16f(float2 a[16]) {
    r4f(a[0], a[4], a[8], a[12]); r4f(a[1], a[5], a[9], a[13]);
    r4f(a[2], a[6], a[10], a[14]); r4f(a[3], a[7], a[11], a[15]);
    a[5]  = twf(a[5],  C16_1,  S16_1);
    a[9]  = twf(a[9],  RSQ2,   RSQ2);
    a[13] = twf(a[13], S16_1,  C16_1);
    a[6]  = twf(a[6],  RSQ2,   RSQ2);
    a[10] = make_float2(a[10].y, -a[10].x);
    a[14] = twf(a[14], -RSQ2,   RSQ2);
    a[7]  = twf(a[7],  S16_1,  C16_1);
    a[11] = twf(a[11], -RSQ2,   RSQ2);
    a[15] = twf(a[15], -C16_1, -S16_1);
    r4f(a[0], a[1], a[2], a[3]);   r4f(a[4], a[5], a[6], a[7]);
    r4f(a[8], a[9], a[10], a[11]); r4f(a[12], a[13], a[14], a[15]);
}
__device__ __forceinline__ void dft16i(float2 a[16]) {
    r4i(a[0], a[4], a[8], a[12]); r4i(a[1], a[5], a[9], a[13]);
    r4i(a[2], a[6], a[10], a[14]); r4i(a[3], a[7], a[11], a[15]);
    a[5]  = twi(a[5],  C16_1,  S16_1);
    a[9]  = twi(a[9],  RSQ2,   RSQ2);
    a[13] = twi(a[13], S16_1,  C16_1);
    a[6]  = twi(a[6],  RSQ2,   RSQ2);
    a[10] = make_float2(-a[10].y, a[10].x);
    a[14] = twi(a[14], -RSQ2,   RSQ2);
    a[7]  = twi(a[7],  S16_1,  C16_1);
    a[11] = twi(a[11], -RSQ2,   RSQ2);
    a[15] = twi(a[15], -C16_1, -S16_1);
    r4i(a[0], a[1], a[2], a[3]);   r4i(a[4], a[5], a[6], a[7]);
    r4i(a[8], a[9], a[10], a[11]); r4i(a[12], a[13], a[14], a[15]);
}

__device__ __forceinline__ float2 twpow_f(float2 v, int r, float2 w1, float2 w2,
                                          float2 w4, float2 w8) {
    if (r & 1) v = cmul(v, w1);
    if (r & 2) v = cmul(v, w2);
    if (r & 4) v = cmul(v, w4);
    if (r & 8) v = cmul(v, w8);
    return v;
}
__device__ __forceinline__ float2 twpow_i(float2 v, int r, float2 w1, float2 w2,
                                          float2 w4, float2 w8) {
    if (r & 1) v = cmulc(v, w1);
    if (r & 2) v = cmulc(v, w2);
    if (r & 4) v = cmulc(v, w4);
    if (r & 8) v = cmulc(v, w8);
    return v;
}

template<bool REAL>
__device__ __forceinline__ void bf16_fwd(float* __restrict__ re, float* __restrict__ im,
                                         int bp, int stride,
                                         float2 w1, float2 w2, float2 w4, float2 w8) {
    float2 a[16];
#pragma unroll
    for (int m = 0; m < 16; m++) {
        int A_ = adr(bp + stride * m);
        a[m] = make_float2(re[A_], REAL ? 0.f : im[A_]);
    }
    dft16f(a);
    { int A_ = adr(bp); re[A_] = a[0].x; im[A_] = a[0].y; }
#pragma unroll
    for (int r = 1; r < 16; r++) {
        int p = ((r & 3) << 2) | (r >> 2);
        float2 v = twpow_f(a[p], r, w1, w2, w4, w8);
        int A_ = adr(bp + stride * r);
        re[A_] = v.x; im[A_] = v.y;
    }
}

template<bool ABS>
__device__ __forceinline__ void bf16_inv(float* __restrict__ re, float* __restrict__ im,
                                         int bp, int stride,
                                         float2 w1, float2 w2, float2 w4, float2 w8) {
    float2 a[16];
#pragma unroll
    for (int r = 0; r < 16; r++) {
        int A_ = adr(bp + stride * r);
        a[r] = make_float2(re[A_], im[A_]);
    }
#pragma unroll
    for (int r = 1; r < 16; r++)
        a[r] = twpow_i(a[r], r, w1, w2, w4, w8);
    dft16i(a);
#pragma unroll
    for (int m = 0; m < 16; m++) {
        int p = ((m & 3) << 2) | (m >> 2);
        int A_ = adr(bp + stride * m);
        if (ABS) {
            re[A_] = sqrtf(fmaf(a[p].x, a[p].x, a[p].y * a[p].y));
        } else {
            re[A_] = a[p].x; im[A_] = a[p].y;
        }
    }
}

// Permuted store + natural-order store of bins < M_need.
__device__ __forceinline__ void pass4_fwd_o1(const float* __restrict__ re,
                                             const float* __restrict__ im,
                                             int t, float2* __restrict__ dst,
                                             float2* __restrict__ nat,
                                             int M_need, bool write_perm) {
#pragma unroll
    for (int h = 0; h < 4; h++) {
        int u  = t + 1024 * h;
        int i0 = 4 * u;
        int A0 = adr(i0);
        float4 rr = *(const float4*)(re + A0);
        float4 ii = *(const float4*)(im + A0);
        float2 A = make_float2(rr.x, ii.x), B = make_float2(rr.y, ii.y);
        float2 C = make_float2(rr.z, ii.z), D = make_float2(rr.w, ii.w);
        r4f(A, B, C, D);
        if (write_perm) {
            float4* dp = (float4*)(dst + i0);
            dp[0] = make_float4(A.x, A.y, B.x, B.y);
            dp[1] = make_float4(C.x, C.y, D.x, D.y);
        }
        int b0 = ((u & 15) << 8) | (((u >> 4) & 15) << 4) | (u >> 8);
        if (b0 < M_need) nat[b0] = A;
        int b1 = b0 + 4096;
        if (b1 < M_need) nat[b1] = B;
    }
}

// Entry inverse radix-4 stage: gmem * psi -> shared, no twiddles.
__device__ __forceinline__ void pass4_inv(float* __restrict__ re, float* __restrict__ im,
                                          int t, const float2* __restrict__ src,
                                          const float* __restrict__ psi) {
#pragma unroll
    for (int h = 0; h < 4; h++) {
        int i0 = 4 * (t + 1024 * h);
        const float4* sp = (const float4*)(src + i0);
        float4 v1 = sp[0], v2 = sp[1];
        float4 p4 = *(const float4*)(psi + i0);
        float2 A = make_float2(v1.x * p4.x, v1.y * p4.x);
        float2 B = make_float2(v1.z * p4.y, v1.w * p4.y);
        float2 C = make_float2(v2.x * p4.z, v2.y * p4.z);
        float2 D = make_float2(v2.z * p4.w, v2.w * p4.w);
        r4i(A, B, C, D);
        int A0 = adr(i0);
        *(float4*)(re + A0) = make_float4(A.x, B.x, C.x, D.x);
        *(float4*)(im + A0) = make_float4(A.y, B.y, C.y, D.y);
    }
}

struct Tabs {
    float2 *s1w1, *s1w2, *s1w4, *s1w8;
    float2 *s2w1, *s2w2, *s2w4, *s2w8;
    float2 *s3w1, *s3w2, *s3w4, *s3w8;
    float  *ph;
};

__device__ __forceinline__ Tabs layout(float* sm) {
    Tabs tb;
    float2* p = (float2*)(sm + 2 * NPAD);
    tb.s1w1 = p;        tb.s1w2 = p + 1024; tb.s1w4 = p + 2048; tb.s1w8 = p + 3072;
    p += 4096;
    tb.s2w1 = p;        tb.s2w2 = p + 64;   tb.s2w4 = p + 128;  tb.s2w8 = p + 192;
    p += 256;
    tb.s3w1 = p;        tb.s3w2 = p + 4;    tb.s3w4 = p + 8;    tb.s3w8 = p + 12;
    p += 16;
    tb.ph = (float*)p;
    return tb;
}

__device__ __forceinline__ void load_tabs(Tabs tb, int t) {
    if (t < 1024) {
        tb.s1w1[t] = g_tw[t];
        tb.s1w2[t] = g_tw[2 * t];
        tb.s1w4[t] = g_tw[4 * t];
        tb.s1w8[t] = g_tw[8 * t];
    }
    if (t < 64) {
        tb.s2w1[t] = g_tw[16 * t];
        tb.s2w2[t] = g_tw[32 * t];
        tb.s2w4[t] = g_tw[64 * t];
        tb.s2w8[t] = g_tw[128 * t];
    }
    if (t < 4) {
        tb.s3w1[t] = g_tw[256 * t];
        tb.s3w2[t] = g_tw[512 * t];
        tb.s3w4[t] = g_tw[1024 * t];
        tb.s3w8[t] = g_tw[2048 * t];
    }
    for (int i = t; i <= W_PHI; i += 1024) tb.ph[i] = g_phit[i];
}

template<bool REAL_IN>
__device__ __forceinline__ void fwd3(float* re, float* im, Tabs tb, int t) {
    bf16_fwd<REAL_IN>(re, im, t, 1024,
                      tb.s1w1[t], tb.s1w2[t], tb.s1w4[t], tb.s1w8[t]);
    __syncthreads();
    { int j = t & 63;
      bf16_fwd<false>(re, im, ((t >> 6) << 10) + j, 64,
                      tb.s2w1[j], tb.s2w2[j], tb.s2w4[j], tb.s2w8[j]); }
    __syncthreads();
    { int j = t & 3;
      bf16_fwd<false>(re, im, ((t >> 2) << 6) + j, 4,
                      tb.s3w1[j], tb.s3w2[j], tb.s3w4[j], tb.s3w8[j]); }
    __syncthreads();
}

template<bool ABS>
__device__ __forceinline__ void inv3(float* re, float* im, Tabs tb, int t) {
    { int j = t & 3;
      bf16_inv<false>(re, im, ((t >> 2) << 6) + j, 4,
                      tb.s3w1[j], tb.s3w2[j], tb.s3w4[j], tb.s3w8[j]); }
    __syncthreads();
    { int j = t & 63;
      bf16_inv<false>(re, im, ((t >> 6) << 10) + j, 64,
                      tb.s2w1[j], tb.s2w2[j], tb.s2w4[j], tb.s2w8[j]); }
    __syncthreads();
    bf16_inv<ABS>(re, im, t, 1024,
                  tb.s1w1[t], tb.s1w2[t], tb.s1w4[t], tb.s1w8[t]);
    __syncthreads();
}

__device__ __forceinline__ void lowpass64(const float* __restrict__ re,
                                          const float* __restrict__ ph,
                                          float* __restrict__ outp) {
    const int lane = threadIdx.x & 31;
    const int warp = threadIdx.x >> 5;
    for (int m = warp; m < M_OUT; m += 32) {
        const int t0 = m << 8;
        float acc = 0.f;
        for (int dd = lane; dd <= 2 * W_PHI; dd += 32) {
            const int d   = dd - W_PHI;
            const int ad  = d < 0 ? -d : d;
            const int idx = (t0 - d + T_N) & (T_N - 1);
            acc = fmaf(re[adr(idx)], ph[ad], acc);
        }
#pragma unroll
        for (int off = 16; off; off >>= 1)
            acc += __shfl_down_sync(0xffffffffu, acc, off);
        if (lane == 0) outp[m] = acc;
    }
}

// Generic M-point inverse FFT machine (natural in -> bit-reversed out).
__device__ void band_inv_fft(float* __restrict__ re, float* __restrict__ im,
                             const float* __restrict__ twx,
                             const float* __restrict__ twy,
                             int lgM, int lgs, int tid) {
    const int M = 1 << lgM;
    if (lgM & 1) {
        int H = M >> 1;
        for (int j = tid; j < H; j += 512) {
            int pa = padb(j), pb = padb(j + H);
            float ax = re[pa], ay = im[pa], bx = re[pb], by = im[pb];
            float2 w = g_tw[j << lgs];
            float dx = ax - bx, dy = ay - by;
            re[pa] = ax + bx; im[pa] = ay + by;
            re[pb] = fmaf(dx, w.x,  dy * w.y);
            im[pb] = fmaf(dy, w.x, -dx * w.y);
        }
        __syncthreads();
    }
    const int lgMs = lgM - (lgM & 1);
    const int lgQ = lgMs - 2;
    for (int lgL = lgQ; lgL >= 0; lgL -= 2) {
        const int L = 1 << lgL;
        const int twsh = lgQ - lgL;
        for (int u = tid; u < (M >> 2); u += 512) {
            int v   = u & ((1 << lgQ) - 1);
            int sub = u >> lgQ;
            int j   = v & (L - 1);
            int blk = v >> lgL;
            int base = (sub << lgMs) + (blk << (lgL + 2)) + j;
            int a0 = padb(base), a1 = padb(base + L);
            int a2 = padb(base + 2 * L), a3 = padb(base + 3 * L);
            float x0r = re[a0], x0i = im[a0], x1r = re[a1], x1i = im[a1];
            float x2r = re[a2], x2i = im[a2], x3r = re[a3], x3i = im[a3];
            float w1x = twx[j << twsh], w1y = twy[j << twsh];
            float w2x = fmaf(w1x, w1x, -w1y * w1y), w2y = 2.f * w1x * w1y;
            float w3x = fmaf(w2x, w1x, -w2y * w1y);
            float w3y = fmaf(w2x, w1y,  w2y * w1x);
            float t0r = x0r + x2r, t0i = x0i + x2i, t1r = x0r - x2r, t1i = x0i - x2i;
            float t2r = x1r + x3r, t2i = x1i + x3i, t4r = x1r - x3r, t4i = x1i - x3i;
            re[a0] = t0r + t2r; im[a0] = t0i + t2i;
            float d1r = t0r - t2r, d1i = t0i - t2i;                  // * conj(w2)
            re[a1] = fmaf(d1r, w2x,  d1i * w2y);
            im[a1] = fmaf(d1i, w2x, -d1r * w2y);
            float c2r = t1r - t4i, c2i = t1i + t4r;                  // (t1+i t4)*conj(w1)
            re[a2] = fmaf(c2r, w1x,  c2i * w1y);
            im[a2] = fmaf(c2i, w1x, -c2r * w1y);
            float c3r = t1r + t4i, c3i = t1i - t4r;                  // (t1-i t4)*conj(w3)
            re[a3] = fmaf(c3r, w3x,  c3i * w3y);
            im[a3] = fmaf(c3i, w3x, -c3r * w3y);
        }
        __syncthreads();
    }
}

__device__ __forceinline__ void band_tabs(float* twx, float* twy, float* ph,
                                          int lgM, int tid) {
    for (int i = tid; i <= W_PHI; i += 512) ph[i] = g_phit[i];
    const int lgMs = lgM - (lgM & 1);
    const int tstep = T_N >> lgMs;
    for (int r = tid; r < (1 << (lgMs - 2)); r += 512) {
        float2 w = g_tw[r * tstep]; twx[r] = w.x; twy[r] = w.y;
    }
}

__device__ __forceinline__ void band_conv(const float* __restrict__ nat,
                                          const float* __restrict__ ph,
                                          int lgM, int lgs, int qsh, int tid,
                                          float* __restrict__ outp) {
    const int M = 1 << lgM;
    const int lane = tid & 31, warp = tid >> 5;
    const int he = W_PHI >> lgs;
    const float fs = (float)(1 << lgs);
    for (int m = warp; m < M_OUT; m += 16) {
        int qc = m << (8 - lgs);
        float acc = 0.f;
        for (int ee = lane; ee <= 2 * he; ee += 32) {
            int e = ee - he;
            int q = (qc - e) & (M - 1);
            int ae = e < 0 ? -e : e;
            acc = fmaf(nat[q + (q >> qsh)], ph[ae << lgs], acc);
        }
#pragma unroll
        for (int off = 16; off; off >>= 1)
            acc += __shfl_down_sync(0xffffffffu, acc, off);
        if (lane == 0) outp[m] = acc * fs;
    }
}

// ----------------------- init kernels ---------------------------------------
__device__ __forceinline__ int posrm(int k) {
    return ((k & 15) << 10) | (((k >> 4) & 15) << 6) | (((k >> 8) & 15) << 2) | (k >> 12);
}

__global__ void k_init(const float* __restrict__ psi1, const float* __restrict__ psi2) {
    const float invN = 1.0f / (float)T_N;
    const int total = N1 * T_N;
    for (int i = blockIdx.x * blockDim.x + threadIdx.x; i < total;
         i += gridDim.x * blockDim.x) {
        const int k = i & (T_N - 1);
        const int j = i >> 14;
        const int pos = posrm(k);
        g_psi1p[(j << 14) + pos] = psi1[i] * invN;
        if (j >= 24 && k < 8192) g_psi1n[((j - 24) << 13) + k] = psi1[i] * invN;
        if (j < N2) {
            g_psi2p[(j << 14) + pos] = psi2[i] * invN;
            if (k < 8192) g_psi2n[(j << 13) + k] = psi2[i] * invN;
        }
        if (j == 0) {
            float sn, cn;
            sincospif(-2.0f * (float)k / (float)T_N, &sn, &cn);
            g_tw[k] = make_float2(cn, sn);
        }
    }
}

__global__ void k_lists(const int* __restrict__ pj2) {
    if (blockIdx.x == 0 && threadIdx.x == 0) {
        int nf = 0, nb = 0;
        for (int i = 0; i < FULL_P; i++) g_fullp[i] = -1;
        for (int i = 0; i < BAND_P; i++) g_bandp[i] = -1;
        for (int p = 0; p < P_N; p++)
            if (pj2[p] < 3 && nf < FULL_P) g_fullp[nf++] = p;
        for (int j2v = 3; j2v <= 7; j2v++)          // big-M first
            for (int p = 0; p < P_N; p++)
                if (pj2[p] == j2v && nb < BAND_P) g_bandp[nb++] = p;
    }
}

__global__ void k_phit(const float* __restrict__ phi) {
    __shared__ float red[256];
    const int n = blockIdx.x;   // 0..W_PHI
    float acc = 0.f;
    for (int k = threadIdx.x; k < 1024; k += blockDim.x) {
        float coef = (k == 0) ? phi[0] : 2.f * phi[k];
        acc = fmaf(coef, g_tw[(k * n) & (T_N - 1)].x, acc);
    }
    red[threadIdx.x] = acc;
    __syncthreads();
    for (int off = 128; off; off >>= 1) {
        if (threadIdx.x < off) red[threadIdx.x] += red[threadIdx.x + off];
        __syncthreads();
    }
    if (threadIdx.x == 0) g_phit[n] = red[0] * (1.0f / (float)T_N);
}

// ----------------------- main kernels ---------------------------------------
__global__ void __launch_bounds__(1024, 1)
k_xfft(const float* __restrict__ x, float* __restrict__ out) {
    extern __shared__ float sm[];
    float* re = sm; float* im = sm + NPAD;
    Tabs tb = layout(sm);
    const int b = blockIdx.x, t = threadIdx.x;
    load_tabs(tb, t);
    const float* xb = x + b * T_N;
    for (int i = t; i < T_N; i += 1024) re[adr(i)] = xb[i];
    __syncthreads();
    lowpass64(re, tb.ph, out + b * M_OUT);              // S0
    __syncthreads();
    fwd3<true>(re, im, tb, t);
    pass4_fwd_o1(re, im, t, g_xh + b * T_N, g_xhn + b * 8192, 8192, true);
}

// Full-size order-1: j1 < 24 only; permuted write only j1 < 16.
__global__ void __launch_bounds__(1024, 1)
k_order1(float* __restrict__ out) {
    extern __shared__ float sm[];
    float* re = sm; float* im = sm + NPAD;
    Tabs tb = layout(sm);
    const int j1 = blockIdx.x, b = blockIdx.y, t = threadIdx.x;
    load_tabs(tb, t);
    pass4_inv(re, im, t, g_xh + b * T_N, g_psi1p + j1 * T_N);
    __syncthreads();
    inv3<true>(re, im, tb, t);                          // |ifft| -> re
    lowpass64(re, tb.ph, out + S1_BASE + (b * N1 + j1) * M_OUT);   // S1
    __syncthreads();
    fwd3<true>(re, im, tb, t);
    pass4_fwd_o1(re, im, t,
                 g_u1h + (size_t)(b * N1 + j1) * T_N,
                 g_u1hn + (size_t)(b * N1 + j1) * 8192,
                 8192, j1 < 16);
}

// Subband order-1: j1 >= 24.  M = 2^(15-o), s = 2^(o-1), o = j1>>3.
__global__ void __launch_bounds__(512, 2)
k_order1_band(float* __restrict__ out) {
    const int j1 = 24 + blockIdx.x;
    const int b  = blockIdx.y;
    const int tid = threadIdx.x;
    extern __shared__ float sm[];
    float* re  = sm;            // 9216
    float* im  = sm + 9216;     // 9216
    float* twx = sm + 18432;    // 1024
    float* twy = sm + 19456;    // 1024
    float* ph  = sm + 20480;    // 513
    const int o   = j1 >> 3;                 // 3..7
    const int lgM = 15 - o;                  // 12..8
    const int M   = 1 << lgM;
    const int lgs = o - 1;                   // 2..6
    band_tabs(twx, twy, ph, lgM, tid);
    const float2* xhn = g_xhn + b * 8192;
    const float*  p1  = g_psi1n + ((j1 - 24) << 13);
    for (int k = tid; k < M; k += 512) {
        float2 u = xhn[k];
        float  w = p1[k];
        int a = padb(k);
        re[a] = u.x * w; im[a] = u.y * w;
    }
    __syncthreads();
    band_inv_fft(re, im, twx, twy, lgM, lgs, tid);      // U1 decimated, bitrev
    for (int i = tid; i < M; i += 512) {
        int a = padb(i);
        float xr = re[a], xi = im[a];
        re[a] = sqrtf(fmaf(xr, xr, xi * xi));
    }
    __syncthreads();
    const int qsh = lgM - 5;
    for (int i = tid; i < M; i += 512) {
        int q = (int)(__brev((unsigned)i) >> (32 - lgM));
        im[q + (q >> qsh)] = re[padb(i)];
    }
    __syncthreads();
    band_conv(im, ph, lgM, lgs, qsh, tid,
              out + S1_BASE + (b * N1 + j1) * M_OUT);   // S1
    if (j1 >= 56) return;                                // no order-2 consumers
    __syncthreads();
    // repack natural mags as real input for the forward FFT
    for (int k = tid; k < M; k += 512) re[padb(k)] = im[k + (k >> qsh)];
    __syncthreads();
    for (int k = tid; k < M; k += 512) im[padb(k)] = 0.f;
    __syncthreads();
    band_inv_fft(re, im, twx, twy, lgM, lgs, tid);       // fwd = conj(inv)
    const int Mh = M >> 1;
    const float fs = (float)(1 << lgs);
    float2* dst = g_u1hn + (size_t)(b * N1 + j1) * 8192;
    for (int i = tid; i < M; i += 512) {
        int q = (int)(__brev((unsigned)i) >> (32 - lgM));
        if (q < Mh) {
            int a = padb(i);
            dst[q] = make_float2(fs * re[a], -fs * im[a]);
        }
    }
}

// Full-size order-2: compact list of j2<=2 pairs (all have j1<16).
__global__ void __launch_bounds__(1024, 1)
k_order2(const int* __restrict__ pj1, const int* __restrict__ pj2,
         float* __restrict__ out) {
    const int idx = blockIdx.x;
    const int b = idx / FULL_P;
    const int p = g_fullp[idx - b * FULL_P];
    if (p < 0) return;
    extern __shared__ float sm[];
    float* re = sm; float* im = sm + NPAD;
    Tabs tb = layout(sm);
    const int t = threadIdx.x;
    const int j1 = pj1[p], j2 = pj2[p];
    load_tabs(tb, t);
    pass4_inv(re, im, t, g_u1h + (size_t)(b * N1 + j1) * T_N, g_psi2p + j2 * T_N);
    __syncthreads();
    inv3<true>(re, im, tb, t);
    lowpass64(re, tb.ph, out + S2_BASE + (b * P_N + p) * M_OUT);   // S2
}

// Subband order-2 (compact list, j2>=3).  lgM = min(13, 17-j2), s' = 2^(14-lgM).
__global__ void __launch_bounds__(512, 2)
k_order2_band(const int* __restrict__ pj1, const int* __restrict__ pj2,
              float* __restrict__ out) {
    const int idx = blockIdx.x, tid = threadIdx.x;
    const int b = idx / BAND_P;
    const int p = g_bandp[idx - b * BAND_P];
    if (p < 0) return;
    const int j1 = pj1[p], j2 = pj2[p];
    extern __shared__ float sm[];
    float* re  = sm;
    float* im  = sm + 9216;
    float* twx = sm + 18432;
    float* twy = sm + 19456;
    float* ph  = sm + 20480;
    int lgM = 17 - j2; if (lgM > 13) lgM = 13;           // 13..10
    const int M   = 1 << lgM;
    const int lgs = 14 - lgM;                            // 1..4
    band_tabs(twx, twy, ph, lgM, tid);
    // input bins available from the producer of u1hn
    const int o1 = j1 >> 3;
    int avail = (j1 >= 24) ? (1 << (14 - o1)) : 8192;
    int cap = avail < M ? avail : M;
    const float2* uhn = g_u1hn + (size_t)(b * N1 + j1) * 8192;
    const float*  p2  = g_psi2n + (j2 << 13);
    for (int k = tid; k < cap; k += 512) {
        float2 u = uhn[k];
        float  w = p2[k];
        int a = padb(k);
        re[a] = u.x * w; im[a] = u.y * w;
    }
    for (int k = cap + tid; k < M; k += 512) {
        int a = padb(k);
        re[a] = 0.f; im[a] = 0.f;
    }
    __syncthreads();
    band_inv_fft(re, im, twx, twy, lgM, lgs, tid);
    for (int i = tid; i < M; i += 512) {
        int a = padb(i);
        float xr = re[a], xi = im[a];
        re[a] = sqrtf(fmaf(xr, xr, xi * xi));
    }
    __syncthreads();
    const int qsh = lgM - 5;
    for (int i = tid; i < M; i += 512) {
        int q = (int)(__brev((unsigned)i) >> (32 - lgM));
        im[q + (q >> qsh)] = re[padb(i)];
    }
    __syncthreads();
    band_conv(im, ph, lgM, lgs, qsh, tid,
              out + S2_BASE + (b * P_N + p) * M_OUT);   // S2
}

// ----------------------- launch --------------------------------------------
extern "C" void kernel_launch(void* const* d_in, const int* in_sizes, int n_in,
                              void* d_out, int out_size) {
    (void)in_sizes; (void)n_in; (void)out_size;
    const float* x    = (const float*)d_in[0];
    const float* psi1 = (const float*)d_in[1];
    const float* psi2 = (const float*)d_in[2];
    const float* phi  = (const float*)d_in[3];
    const int*   pj1  = (const int*)d_in[4];
    const int*   pj2  = (const int*)d_in[5];
    float* out = (float*)d_out;

    cudaFuncSetAttribute(k_xfft,        cudaFuncAttributeMaxDynamicSharedMemorySize, SMEM_BYTES);
    cudaFuncSetAttribute(k_order1,      cudaFuncAttributeMaxDynamicSharedMemorySize, SMEM_BYTES);
    cudaFuncSetAttribute(k_order1_band, cudaFuncAttributeMaxDynamicSharedMemorySize, SMEM_BAND);
    cudaFuncSetAttribute(k_order2,      cudaFuncAttributeMaxDynamicSharedMemorySize, SMEM_BYTES);
    cudaFuncSetAttribute(k_order2_band, cudaFuncAttributeMaxDynamicSharedMemorySize, SMEM_BAND);

    k_init<<<256, 256>>>(psi1, psi2);
    k_lists<<<1, 32>>>(pj2);
    k_phit<<<W_PHI + 1, 256>>>(phi);
    k_xfft<<<B_N, 1024, SMEM_BYTES>>>(x, out);
    dim3 g1(24, B_N);
    k_order1<<<g1, 1024, SMEM_BYTES>>>(out);
    dim3 g1b(40, B_N);
    k_order1_band<<<g1b, 512, SMEM_BAND>>>(out);
    k_order2<<<B_N * FULL_P, 1024, SMEM_BYTES>>>(pj1, pj2, out);
    k_order2_band<<<B_N * BAND_P, 512, SMEM_BAND>>>(pj1, pj2, out);
}